// round 1
// baseline (speedup 1.0000x reference)
#include <cuda_runtime.h>
#include <math.h>

// Problem constants (fixed by setup_inputs)
#define BATCH 4
#define TLEN  1024
#define KD    64
#define HNUM  8
#define R32   32
#define NSEQ  32      // BATCH*HNUM
#define MROWS 4096    // BATCH*TLEN

// ---------------- scratch (static device globals; no allocation) --------------
__device__ float g_x3[BATCH * R32 * TLEN];          // 512 KB
__device__ float g_xin[BATCH * TLEN * KD];           // 1 MB
__device__ float g_A[MROWS * 320];                   // 5 MB  (gathered A for QK gemm)
__device__ float g_WB[320 * 1024];                   // 1.25 MB (transposed wq|wk)
__device__ float g_WB2[64 * 1024];                   // 256 KB (transposed wv|wl)
__device__ float g_q[NSEQ * TLEN * KD];              // 8 MB
__device__ float g_k[NSEQ * TLEN * KD];
__device__ float g_v[NSEQ * TLEN * KD];
__device__ float g_l[NSEQ * TLEN * KD];
__device__ float g_og[NSEQ * TLEN * KD];
__device__ float g_ol[NSEQ * TLEN * KD];
__device__ float g_gated[MROWS * 1024];              // 16 MB
__device__ float g_y[MROWS * KD];                    // 1 MB

__device__ __forceinline__ float sigmoidf_(float x) { return 1.f / (1.f + expf(-x)); }
__device__ __forceinline__ float siluf_(float x)    { return x / (1.f + expf(-x)); }

// ---------------- kernel 1: x3 = bn(1x1 conv) --------------------------------
__global__ __launch_bounds__(256) void x3_kernel(
    const float* __restrict__ x, const float* __restrict__ sq_w,
    const float* __restrict__ bn_g, const float* __restrict__ bn_b)
{
    int idx = blockIdx.x * 256 + threadIdx.x;      // over BATCH*R32*TLEN
    if (idx >= BATCH * R32 * TLEN) return;
    int pos = idx & 1023;
    int r   = (idx >> 10) & 31;
    int bi  = idx >> 15;
    const float* xr = x + ((size_t)bi * TLEN + pos) * KD;
    const float* wr = sq_w + r * KD;
    float s = 0.f;
#pragma unroll
    for (int c = 0; c < KD; ++c) s += xr[c] * wr[c];
    // bn_g * x / sqrt(1+1e-5) + bn_b
    g_x3[idx] = s * bn_g[r] * 0.9999950000374997f + bn_b[r];
}

// ---------------- kernel 2: action gate + pos_emb -> xin ---------------------
__global__ __launch_bounds__(256) void xin_kernel(
    const float* __restrict__ x, const float* __restrict__ dw_w,
    const float* __restrict__ ex_w, const float* __restrict__ pos_emb)
{
    int bi = blockIdx.x;
    int t0 = blockIdx.y * 128;
    __shared__ float xp3[R32][128];
    int tid = threadIdx.x;
    for (int i = tid; i < R32 * 128; i += 256) {
        int r = i >> 7, j = i & 127;
        int pos = t0 + j;
        const float* x3r = g_x3 + bi * (R32 * TLEN) + r * TLEN;
        float v;
        if (pos == TLEN - 1) {
            v = x3r[TLEN - 1];
        } else {
            float d0 = dw_w[r * 3 + 0], d1 = dw_w[r * 3 + 1], d2 = dw_w[r * 3 + 2];
            float a = x3r[pos] * d0 + x3r[pos + 1] * d1 +
                      ((pos + 2 < TLEN) ? x3r[pos + 2] * d2 : 0.f);
            v = a - x3r[pos];
        }
        xp3[r][j] = v;
    }
    __syncthreads();
    for (int i = tid; i < 128 * KD; i += 256) {
        int j = i >> 6, c = i & 63;
        int pos = t0 + j;
        float gsum = 0.f;
#pragma unroll
        for (int r = 0; r < R32; ++r) gsum += xp3[r][j] * ex_w[c * R32 + r];
        float sig = sigmoidf_(gsum);
        size_t off = ((size_t)bi * TLEN + pos) * KD + c;
        g_xin[off] = x[off] * sig + pos_emb[pos * KD + c];
    }
}

// ---------------- prep kernels for GEMMs --------------------------------------
__global__ __launch_bounds__(256) void prep_wqk_kernel(
    const float* __restrict__ wq, const float* __restrict__ wk)
{
    int idx = blockIdx.x * 256 + threadIdx.x;     // 320*1024
    if (idx >= 320 * 1024) return;
    int n = idx & 1023, kcol = idx >> 10;
    g_WB[idx] = (n < 512) ? wq[n * 320 + kcol] : wk[(n - 512) * 320 + kcol];
}

__global__ __launch_bounds__(256) void prep_wvl_kernel(
    const float* __restrict__ wv, const float* __restrict__ wl)
{
    int idx = blockIdx.x * 256 + threadIdx.x;     // 64*1024
    if (idx >= 64 * 1024) return;
    int n = idx & 1023, c = idx >> 10;
    g_WB2[idx] = (n < 512) ? wv[n * 64 + c] : wl[(n - 512) * 64 + c];
}

__global__ __launch_bounds__(256) void prep_A_kernel()
{
    int idx = blockIdx.x * 256 + threadIdx.x;     // 4096*320
    if (idx >= MROWS * 320) return;
    int m = idx / 320, kcol = idx - m * 320;
    int c = kcol / 5, mm = kcol - c * 5;
    int bi = m >> 10, ti = m & 1023;
    int tsrc = ti + 2 * mm - 8;                   // left pad of 8, dilation 2
    float v = 0.f;
    if (tsrc >= 0) v = g_xin[((size_t)bi * TLEN + tsrc) * KD + c];
    g_A[idx] = v;
}

// ---------------- gate/concat build for uni GEMM -------------------------------
__global__ __launch_bounds__(256) void gate_kernel()
{
    int idx = blockIdx.x * 256 + threadIdx.x;     // 4096*1024
    if (idx >= MROWS * 1024) return;
    int row = idx >> 10, col = idx & 1023;
    int bi = row >> 10, ti2 = row & 1023;
    int ch = col >> 6, ki = col & 63;
    int h2 = ch & 7;
    size_t src = (((size_t)(bi * 8 + h2)) * TLEN + ti2) * KD + ki;
    float o = g_og[src], lv = g_ol[src];
    float gt = sigmoidf_(o);
    g_gated[idx] = (ch < 8) ? (1.f - gt) * lv : gt * o;
}

// ---------------- generic fp32 GEMM (M=4096) with fused epilogues --------------
// MODE 0: QK conv  (A=g_A K=320, B=g_WB  N=1024) -> silu(+bias)/scale, permuted store to g_q/g_k
// MODE 1: VL conv  (A=g_xin K=64, B=g_WB2 N=1024) -> silu, permuted store to g_v/g_l
// MODE 2: uni proj (A=g_gated K=1024, B=uni_w N=64) -> silu(+bias)+xin residual -> g_y
template <int MODE>
__global__ __launch_bounds__(256) void gemm_kernel(
    const float* __restrict__ Bext,
    const float* __restrict__ bias0, const float* __restrict__ bias1)
{
    const int Kdim = (MODE == 0) ? 320 : (MODE == 1) ? 64 : 1024;
    const int N    = (MODE == 2) ? 64 : 1024;
    const float* __restrict__ A  = (MODE == 0) ? g_A : (MODE == 1) ? g_xin : g_gated;
    const float* __restrict__ Bm = (MODE == 2) ? Bext : (MODE == 0) ? g_WB : g_WB2;

    __shared__ float As[16][64];
    __shared__ float Bs[16][64];
    int tid = threadIdx.x;
    int m0 = blockIdx.x * 64;
    int n0 = blockIdx.y * 64;
    int ty = tid >> 4, tx = tid & 15;
    float acc[4][4];
#pragma unroll
    for (int i = 0; i < 4; ++i)
#pragma unroll
        for (int j = 0; j < 4; ++j) acc[i][j] = 0.f;

    int arow = tid >> 2;
    int akq  = (tid & 3) << 2;
    int brow = tid >> 4;
    int bcol = (tid & 15) << 2;

    for (int k0 = 0; k0 < Kdim; k0 += 16) {
        float4 av = *(const float4*)&A[(size_t)(m0 + arow) * Kdim + k0 + akq];
        float4 bv = *(const float4*)&Bm[(size_t)(k0 + brow) * N + n0 + bcol];
        As[akq + 0][arow] = av.x;
        As[akq + 1][arow] = av.y;
        As[akq + 2][arow] = av.z;
        As[akq + 3][arow] = av.w;
        *(float4*)&Bs[brow][bcol] = bv;
        __syncthreads();
#pragma unroll
        for (int kk = 0; kk < 16; ++kk) {
            float4 a = *(const float4*)&As[kk][ty << 2];
            float4 b = *(const float4*)&Bs[kk][tx << 2];
            acc[0][0] += a.x * b.x; acc[0][1] += a.x * b.y; acc[0][2] += a.x * b.z; acc[0][3] += a.x * b.w;
            acc[1][0] += a.y * b.x; acc[1][1] += a.y * b.y; acc[1][2] += a.y * b.z; acc[1][3] += a.y * b.w;
            acc[2][0] += a.z * b.x; acc[2][1] += a.z * b.y; acc[2][2] += a.z * b.z; acc[2][3] += a.z * b.w;
            acc[3][0] += a.w * b.x; acc[3][1] += a.w * b.y; acc[3][2] += a.w * b.z; acc[3][3] += a.w * b.w;
        }
        __syncthreads();
    }

#pragma unroll
    for (int i = 0; i < 4; ++i) {
        int m = m0 + (ty << 2) + i;
#pragma unroll
        for (int j = 0; j < 4; ++j) {
            int n = n0 + (tx << 2) + j;
            float v = acc[i][j];
            if (MODE == 0) {
                float bias = (n < 512) ? bias0[n] : bias1[n - 512];
                float val = v + bias;
                float s = siluf_(val) * 0.35355339059327373f;   // / 64^0.25
                int o = n & 511, ki = o >> 3, h = o & 7;
                int bi = m >> 10, ti = m & 1023;
                int g = bi * 8 + (ti >> 7);
                int tj = ((ti & 127) << 3) | h;
                float* dst = (n < 512) ? g_q : g_k;
                dst[((size_t)g * TLEN + tj) * KD + ki] = s;
            } else if (MODE == 1) {
                float s = siluf_(v);
                int o = n & 511, ki = o >> 3, h = o & 7;
                int bi = m >> 10, ti = m & 1023;
                int g = bi * 8 + (ti >> 7);
                int tj = ((ti & 127) << 3) | h;
                float* dst = (n < 512) ? g_v : g_l;
                dst[((size_t)g * TLEN + tj) * KD + ki] = s;
            } else {
                float val = v + bias0[n];
                float s = siluf_(val);
                g_y[(size_t)m * KD + n] = s + g_xin[(size_t)m * KD + n];
            }
        }
    }
}

// ---------------- flash-style global causal attention --------------------------
__global__ __launch_bounds__(128) void flash_kernel()
{
    int g  = blockIdx.x;
    int q0 = blockIdx.y * 128;
    int tid = threadIdx.x;
    int qidx = q0 + tid;

    __shared__ float Ksm[64 * 64];
    __shared__ float Vsm[64 * 64];

    const float* qrow = g_q + ((size_t)g * TLEN + qidx) * KD;
    float q[64];
#pragma unroll
    for (int d = 0; d < 64; d += 4) {
        float4 t = *(const float4*)&qrow[d];
        q[d] = t.x; q[d + 1] = t.y; q[d + 2] = t.z; q[d + 3] = t.w;
    }
    float m = -1e30f, l = 0.f;
    float acc[64];
#pragma unroll
    for (int d = 0; d < 64; ++d) acc[d] = 0.f;

    int ktiles = (q0 + 128) / 64;    // key tiles of 64 covering 0..q0+127
    for (int kt = 0; kt < ktiles; ++kt) {
        int k0 = kt * 64;
        const float* Kg = g_k + (size_t)g * (TLEN * KD) + (size_t)k0 * KD;
        const float* Vg = g_v + (size_t)g * (TLEN * KD) + (size_t)k0 * KD;
        __syncthreads();
#pragma unroll
        for (int i = 0; i < 8; ++i) {
            int idx = tid + i * 128;                 // 1024 float4
            ((float4*)Ksm)[idx] = ((const float4*)Kg)[idx];
            ((float4*)Vsm)[idx] = ((const float4*)Vg)[idx];
        }
        __syncthreads();

        for (int j0 = 0; j0 < 64; j0 += 8) {
            if (k0 + j0 > qidx) break;
            float s[8];
            float tmax = m;
#pragma unroll
            for (int jj = 0; jj < 8; ++jj) {
                const float4* kr = (const float4*)&Ksm[(j0 + jj) * 64];
                float sum = 0.f;
#pragma unroll
                for (int d4 = 0; d4 < 16; ++d4) {
                    float4 kv = kr[d4];
                    sum += q[4 * d4 + 0] * kv.x;
                    sum += q[4 * d4 + 1] * kv.y;
                    sum += q[4 * d4 + 2] * kv.z;
                    sum += q[4 * d4 + 3] * kv.w;
                }
                int kidx = k0 + j0 + jj;
                s[jj] = (kidx <= qidx) ? sum : -1e30f;
                tmax = fmaxf(tmax, s[jj]);
            }
            float corr = expf(m - tmax);
            l *= corr;
#pragma unroll
            for (int d = 0; d < 64; ++d) acc[d] *= corr;
#pragma unroll
            for (int jj = 0; jj < 8; ++jj) {
                float p = expf(s[jj] - tmax);
                l += p;
                const float4* vr = (const float4*)&Vsm[(j0 + jj) * 64];
#pragma unroll
                for (int d4 = 0; d4 < 16; ++d4) {
                    float4 vv = vr[d4];
                    acc[4 * d4 + 0] += p * vv.x;
                    acc[4 * d4 + 1] += p * vv.y;
                    acc[4 * d4 + 2] += p * vv.z;
                    acc[4 * d4 + 3] += p * vv.w;
                }
            }
            m = tmax;
        }
    }
    float inv = 1.f / l;
    float* orow = g_og + ((size_t)g * TLEN + qidx) * KD;
#pragma unroll
    for (int d = 0; d < 64; d += 4) {
        float4 t;
        t.x = acc[d] * inv; t.y = acc[d + 1] * inv;
        t.z = acc[d + 2] * inv; t.w = acc[d + 3] * inv;
        *(float4*)&orow[d] = t;
    }
}

// ---------------- local windowed causal attention ------------------------------
__global__ __launch_bounds__(256) void local_attn_kernel()
{
    int g = blockIdx.x;
    int tjbase = blockIdx.y * 64;
    int lane = threadIdx.x & 31;
    int w = threadIdx.x >> 5;
    const float* Lg = g_l + (size_t)g * (TLEN * KD);
    float* Og = g_ol + (size_t)g * (TLEN * KD);
    for (int qi = 0; qi < 8; ++qi) {
        int tj = tjbase + w * 8 + qi;
        float a0 = Lg[tj * 64 + lane];
        float a1 = Lg[tj * 64 + lane + 32];
        float s[6];
        float mx = -1e30f;
#pragma unroll
        for (int wv = 0; wv < 6; ++wv) {
            int tp = tj - 5 + wv;
            float sc = -1e30f;
            if (tp >= 0) {
                float p = a0 * Lg[tp * 64 + lane] + a1 * Lg[tp * 64 + lane + 32];
#pragma unroll
                for (int o = 16; o; o >>= 1) p += __shfl_xor_sync(0xffffffffu, p, o);
                sc = p * 0.125f;   // / sqrt(64)
            }
            s[wv] = sc;
            mx = fmaxf(mx, sc);
        }
        float den = 0.f, o0 = 0.f, o1 = 0.f;
#pragma unroll
        for (int wv = 0; wv < 6; ++wv) {
            int tp = tj - 5 + wv;
            if (tp >= 0) {
                float pp = expf(s[wv] - mx);
                den += pp;
                o0 += pp * Lg[tp * 64 + lane];
                o1 += pp * Lg[tp * 64 + lane + 32];
            }
        }
        float inv = 1.f / den;
        Og[tj * 64 + lane] = o0 * inv;
        Og[tj * 64 + lane + 32] = o1 * inv;
    }
}

// ---------------- LN1 -> FF -> LN2 --------------------------------------------
__global__ __launch_bounds__(256) void ffln_kernel(
    const float* __restrict__ ln1g, const float* __restrict__ ln1b,
    const float* __restrict__ ln2g, const float* __restrict__ ln2b,
    const float* __restrict__ w1, const float* __restrict__ b1,
    const float* __restrict__ w2, const float* __restrict__ b2,
    float* __restrict__ out)
{
    const int R = 16;
    __shared__ float yl[R][64];
    __shared__ float hs[R][256];
    __shared__ float fs[R][64];
    int r0 = blockIdx.x * R;
    int tid = threadIdx.x;
    int lane = tid & 31, w = tid >> 5;

    // LN1 (8 warps x 2 rows)
    for (int rr = 0; rr < 2; ++rr) {
        int r = w * 2 + rr;
        const float* row = g_y + (size_t)(r0 + r) * 64;
        float v0 = row[lane], v1 = row[lane + 32];
        float sm = v0 + v1;
#pragma unroll
        for (int o = 16; o; o >>= 1) sm += __shfl_xor_sync(0xffffffffu, sm, o);
        float mean = sm * (1.f / 64.f);
        float d0 = v0 - mean, d1 = v1 - mean;
        float vs = d0 * d0 + d1 * d1;
#pragma unroll
        for (int o = 16; o; o >>= 1) vs += __shfl_xor_sync(0xffffffffu, vs, o);
        float inv = rsqrtf(vs * (1.f / 64.f) + 1e-5f);
        yl[r][lane]      = d0 * inv * ln1g[lane] + ln1b[lane];
        yl[r][lane + 32] = d1 * inv * ln1g[lane + 32] + ln1b[lane + 32];
    }
    __syncthreads();

    // FF1 + relu: thread tid owns hidden col j=tid for all 16 rows
    {
        float acc[R];
#pragma unroll
        for (int r = 0; r < R; ++r) acc[r] = b1[tid];
        for (int c = 0; c < 64; ++c) {
            float wv = w1[c * 256 + tid];
#pragma unroll
            for (int r = 0; r < R; ++r) acc[r] += yl[r][c] * wv;
        }
#pragma unroll
        for (int r = 0; r < R; ++r) hs[r][tid] = fmaxf(acc[r], 0.f);
    }
    __syncthreads();

    // FF2 + residual: thread (j2 = tid&63, rg = tid>>6) -> 4 rows each
    {
        int j2 = tid & 63, rg = tid >> 6;
#pragma unroll
        for (int rr = 0; rr < 4; ++rr) {
            int r = rg * 4 + rr;
            float a = b2[j2];
            for (int c = 0; c < 256; ++c) a += hs[r][c] * w2[c * 64 + j2];
            fs[r][j2] = a + yl[r][j2];
        }
    }
    __syncthreads();

    // LN2 + write out
    for (int rr = 0; rr < 2; ++rr) {
        int r = w * 2 + rr;
        float v0 = fs[r][lane], v1 = fs[r][lane + 32];
        float sm = v0 + v1;
#pragma unroll
        for (int o = 16; o; o >>= 1) sm += __shfl_xor_sync(0xffffffffu, sm, o);
        float mean = sm * (1.f / 64.f);
        float d0 = v0 - mean, d1 = v1 - mean;
        float vs = d0 * d0 + d1 * d1;
#pragma unroll
        for (int o = 16; o; o >>= 1) vs += __shfl_xor_sync(0xffffffffu, vs, o);
        float inv = rsqrtf(vs * (1.f / 64.f) + 1e-5f);
        float* orow = out + (size_t)(r0 + r) * 64;
        orow[lane]      = d0 * inv * ln2g[lane] + ln2b[lane];
        orow[lane + 32] = d1 * inv * ln2g[lane + 32] + ln2b[lane + 32];
    }
}

// ---------------- launch ---------------------------------------------------------
extern "C" void kernel_launch(void* const* d_in, const int* in_sizes, int n_in,
                              void* d_out, int out_size)
{
    (void)in_sizes; (void)n_in; (void)out_size;
    const float* x       = (const float*)d_in[0];
    const float* sq_w    = (const float*)d_in[1];
    const float* bn_g    = (const float*)d_in[2];
    const float* bn_b    = (const float*)d_in[3];
    const float* dw_w    = (const float*)d_in[4];
    const float* ex_w    = (const float*)d_in[5];
    const float* pos_emb = (const float*)d_in[6];
    const float* wq      = (const float*)d_in[7];
    const float* bq      = (const float*)d_in[8];
    const float* wk      = (const float*)d_in[9];
    const float* bk      = (const float*)d_in[10];
    const float* wv      = (const float*)d_in[11];
    const float* wl      = (const float*)d_in[12];
    const float* uni_w   = (const float*)d_in[13];
    const float* uni_b   = (const float*)d_in[14];
    const float* ln1_g   = (const float*)d_in[15];
    const float* ln1_b   = (const float*)d_in[16];
    const float* ln2_g   = (const float*)d_in[17];
    const float* ln2_b   = (const float*)d_in[18];
    const float* ff_w1   = (const float*)d_in[19];
    const float* ff_b1   = (const float*)d_in[20];
    const float* ff_w2   = (const float*)d_in[21];
    const float* ff_b2   = (const float*)d_in[22];
    float* out = (float*)d_out;

    x3_kernel<<<512, 256>>>(x, sq_w, bn_g, bn_b);
    xin_kernel<<<dim3(4, 8), 256>>>(x, dw_w, ex_w, pos_emb);

    prep_wqk_kernel<<<1280, 256>>>(wq, wk);
    prep_wvl_kernel<<<256, 256>>>(wv, wl);
    prep_A_kernel<<<5120, 256>>>();

    gemm_kernel<0><<<dim3(64, 16), 256>>>(nullptr, bq, bk);     // QK conv
    gemm_kernel<1><<<dim3(64, 16), 256>>>(nullptr, nullptr, nullptr); // VL conv

    flash_kernel<<<dim3(32, 8), 128>>>();
    local_attn_kernel<<<dim3(32, 16), 256>>>();

    gate_kernel<<<16384, 256>>>();
    gemm_kernel<2><<<dim3(64, 1), 256>>>(uni_w, uni_b, nullptr); // uni projection

    ffln_kernel<<<256, 256>>>(ln1_g, ln1_b, ln2_g, ln2_b,
                              ff_w1, ff_b1, ff_w2, ff_b2, out);
}

// round 2
// speedup vs baseline: 1.6356x; 1.6356x over previous
#include <cuda_runtime.h>
#include <math.h>
#include <stdint.h>

// Problem constants (fixed by setup_inputs)
#define BATCH 4
#define TLEN  1024
#define KD    64
#define HNUM  8
#define R32   32
#define NSEQ  32      // BATCH*HNUM
#define MROWS 4096    // BATCH*TLEN

// ---------------- scratch (static device globals; no allocation) --------------
__device__ float g_x3[BATCH * R32 * TLEN];
__device__ float g_xin[BATCH * TLEN * KD];
__device__ float g_A[MROWS * 320];
__device__ float g_WB[320 * 1024];
__device__ float g_WB2[64 * 1024];
__device__ float g_q[NSEQ * TLEN * KD];
__device__ float g_k[NSEQ * TLEN * KD];
__device__ float g_v[NSEQ * TLEN * KD];
__device__ float g_l[NSEQ * TLEN * KD];
__device__ float g_og[NSEQ * TLEN * KD];
__device__ float g_ol[NSEQ * TLEN * KD];
__device__ float g_gated[MROWS * 1024];
__device__ float g_y[MROWS * KD];

__device__ __forceinline__ float sigmoidf_(float x) { return 1.f / (1.f + expf(-x)); }
__device__ __forceinline__ float siluf_(float x)    { return x / (1.f + expf(-x)); }

// ---------------- tf32 mma helpers ---------------------------------------------
__device__ __forceinline__ uint32_t f2tf(float x) {
    uint32_t u;
    asm("cvt.rna.tf32.f32 %0, %1;" : "=r"(u) : "f"(x));
    return u;
}
__device__ __forceinline__ void mma8(float* c,
                                     uint32_t a0, uint32_t a1, uint32_t a2, uint32_t a3,
                                     uint32_t b0, uint32_t b1) {
    asm volatile(
        "mma.sync.aligned.m16n8k8.row.col.f32.tf32.tf32.f32 "
        "{%0,%1,%2,%3}, {%4,%5,%6,%7}, {%8,%9}, {%0,%1,%2,%3};"
        : "+f"(c[0]), "+f"(c[1]), "+f"(c[2]), "+f"(c[3])
        : "r"(a0), "r"(a1), "r"(a2), "r"(a3), "r"(b0), "r"(b1));
}

// ---------------- kernel 1: x3 = bn(1x1 conv) --------------------------------
__global__ __launch_bounds__(256) void x3_kernel(
    const float* __restrict__ x, const float* __restrict__ sq_w,
    const float* __restrict__ bn_g, const float* __restrict__ bn_b)
{
    int idx = blockIdx.x * 256 + threadIdx.x;
    if (idx >= BATCH * R32 * TLEN) return;
    int pos = idx & 1023;
    int r   = (idx >> 10) & 31;
    int bi  = idx >> 15;
    const float* xr = x + ((size_t)bi * TLEN + pos) * KD;
    const float* wr = sq_w + r * KD;
    float s = 0.f;
#pragma unroll
    for (int c = 0; c < KD; ++c) s += xr[c] * wr[c];
    g_x3[idx] = s * bn_g[r] * 0.9999950000374997f + bn_b[r];
}

// ---------------- kernel 2: action gate + pos_emb -> xin ---------------------
__global__ __launch_bounds__(256) void xin_kernel(
    const float* __restrict__ x, const float* __restrict__ dw_w,
    const float* __restrict__ ex_w, const float* __restrict__ pos_emb)
{
    int bi = blockIdx.x;
    int t0 = blockIdx.y * 128;
    __shared__ float xp3[R32][128];
    int tid = threadIdx.x;
    for (int i = tid; i < R32 * 128; i += 256) {
        int r = i >> 7, j = i & 127;
        int pos = t0 + j;
        const float* x3r = g_x3 + bi * (R32 * TLEN) + r * TLEN;
        float v;
        if (pos == TLEN - 1) {
            v = x3r[TLEN - 1];
        } else {
            float d0 = dw_w[r * 3 + 0], d1 = dw_w[r * 3 + 1], d2 = dw_w[r * 3 + 2];
            float a = x3r[pos] * d0 + x3r[pos + 1] * d1 +
                      ((pos + 2 < TLEN) ? x3r[pos + 2] * d2 : 0.f);
            v = a - x3r[pos];
        }
        xp3[r][j] = v;
    }
    __syncthreads();
    for (int i = tid; i < 128 * KD; i += 256) {
        int j = i >> 6, c = i & 63;
        int pos = t0 + j;
        float gsum = 0.f;
#pragma unroll
        for (int r = 0; r < R32; ++r) gsum += xp3[r][j] * ex_w[c * R32 + r];
        float sig = sigmoidf_(gsum);
        size_t off = ((size_t)bi * TLEN + pos) * KD + c;
        g_xin[off] = x[off] * sig + pos_emb[pos * KD + c];
    }
}

// ---------------- prep kernels for GEMMs --------------------------------------
__global__ __launch_bounds__(256) void prep_wqk_kernel(
    const float* __restrict__ wq, const float* __restrict__ wk)
{
    int idx = blockIdx.x * 256 + threadIdx.x;
    if (idx >= 320 * 1024) return;
    int n = idx & 1023, kcol = idx >> 10;
    g_WB[idx] = (n < 512) ? wq[n * 320 + kcol] : wk[(n - 512) * 320 + kcol];
}

__global__ __launch_bounds__(256) void prep_wvl_kernel(
    const float* __restrict__ wv, const float* __restrict__ wl)
{
    int idx = blockIdx.x * 256 + threadIdx.x;
    if (idx >= 64 * 1024) return;
    int n = idx & 1023, c = idx >> 10;
    g_WB2[idx] = (n < 512) ? wv[n * 64 + c] : wl[(n - 512) * 64 + c];
}

__global__ __launch_bounds__(256) void prep_A_kernel()
{
    int idx = blockIdx.x * 256 + threadIdx.x;
    if (idx >= MROWS * 320) return;
    int m = idx / 320, kcol = idx - m * 320;
    int c = kcol / 5, mm = kcol - c * 5;
    int bi = m >> 10, ti = m & 1023;
    int tsrc = ti + 2 * mm - 8;
    float v = 0.f;
    if (tsrc >= 0) v = g_xin[((size_t)bi * TLEN + tsrc) * KD + c];
    g_A[idx] = v;
}

// ---------------- gate/concat build for uni GEMM -------------------------------
__global__ __launch_bounds__(256) void gate_kernel()
{
    int idx = blockIdx.x * 256 + threadIdx.x;
    if (idx >= MROWS * 1024) return;
    int row = idx >> 10, col = idx & 1023;
    int bi = row >> 10, ti2 = row & 1023;
    int ch = col >> 6, ki = col & 63;
    int h2 = ch & 7;
    size_t src = (((size_t)(bi * 8 + h2)) * TLEN + ti2) * KD + ki;
    float o = g_og[src], lv = g_ol[src];
    float gt = sigmoidf_(o);
    g_gated[idx] = (ch < 8) ? (1.f - gt) * lv : gt * o;
}

// ---------------- tf32 MMA GEMM with fused epilogues ---------------------------
// MODE 0: QK conv  (A=g_A K=320, B=g_WB  N=1024) -> silu(+bias)/scale, permuted store
// MODE 1: VL conv  (A=g_xin K=64, B=g_WB2 N=1024) -> silu, permuted store
// MODE 2: uni proj (A=g_gated K=1024, B=uni_w N=64) -> silu(+bias)+xin residual
template <int MODE>
__device__ __forceinline__ void gemm_epilogue(int m, int n, float v,
                                              const float* bias0, const float* bias1)
{
    if (MODE == 0) {
        float bias = (n < 512) ? bias0[n] : bias1[n - 512];
        float s = siluf_(v + bias) * 0.35355339059327373f;   // / 64^0.25
        int o = n & 511, ki = o >> 3, h = o & 7;
        int bi = m >> 10, ti = m & 1023;
        int g = bi * 8 + (ti >> 7);
        int tj = ((ti & 127) << 3) | h;
        float* dst = (n < 512) ? g_q : g_k;
        dst[((size_t)g * TLEN + tj) * KD + ki] = s;
    } else if (MODE == 1) {
        float s = siluf_(v);
        int o = n & 511, ki = o >> 3, h = o & 7;
        int bi = m >> 10, ti = m & 1023;
        int g = bi * 8 + (ti >> 7);
        int tj = ((ti & 127) << 3) | h;
        float* dst = (n < 512) ? g_v : g_l;
        dst[((size_t)g * TLEN + tj) * KD + ki] = s;
    } else {
        float s = siluf_(v + bias0[n]);
        g_y[(size_t)m * KD + n] = s + g_xin[(size_t)m * KD + n];
    }
}

template <int MODE>
__global__ __launch_bounds__(256) void gemm_mma_kernel(
    const float* __restrict__ Bext,
    const float* __restrict__ bias0, const float* __restrict__ bias1)
{
    const int Kdim = (MODE == 0) ? 320 : (MODE == 1) ? 64 : 1024;
    const int N    = (MODE == 2) ? 64 : 1024;
    const float* __restrict__ A  = (MODE == 0) ? g_A : (MODE == 1) ? g_xin : g_gated;
    const float* __restrict__ Bm = (MODE == 2) ? Bext : (MODE == 0) ? g_WB : g_WB2;

    __shared__ uint32_t As[128][36];   // tf32, padded
    __shared__ uint32_t Bs[32][68];    // tf32, padded

    int tid  = threadIdx.x;
    int lane = tid & 31, wid = tid >> 5;
    int wm = wid & 3;          // 0..3 -> 32 rows each
    int wn = wid >> 2;         // 0..1 -> 32 cols each
    int m0 = blockIdx.x * 128;
    int n0 = blockIdx.y * 64;
    int gi = lane >> 2, ci = lane & 3;

    float acc[2][4][4];
#pragma unroll
    for (int a = 0; a < 2; ++a)
#pragma unroll
        for (int b = 0; b < 4; ++b)
#pragma unroll
            for (int c = 0; c < 4; ++c) acc[a][b][c] = 0.f;

    for (int k0 = 0; k0 < Kdim; k0 += 32) {
        // load A tile 128x32
#pragma unroll
        for (int i = 0; i < 4; ++i) {
            int f4 = tid + i * 256;          // 0..1023
            int row = f4 >> 3, c4 = (f4 & 7) << 2;
            float4 av = *(const float4*)&A[(size_t)(m0 + row) * Kdim + k0 + c4];
            uint4 u; u.x = f2tf(av.x); u.y = f2tf(av.y); u.z = f2tf(av.z); u.w = f2tf(av.w);
            *(uint4*)&As[row][c4] = u;
        }
        // load B tile 32x64
#pragma unroll
        for (int i = 0; i < 2; ++i) {
            int f4 = tid + i * 256;          // 0..511
            int row = f4 >> 4, c4 = (f4 & 15) << 2;
            float4 bv = *(const float4*)&Bm[(size_t)(k0 + row) * N + n0 + c4];
            uint4 u; u.x = f2tf(bv.x); u.y = f2tf(bv.y); u.z = f2tf(bv.z); u.w = f2tf(bv.w);
            *(uint4*)&Bs[row][c4] = u;
        }
        __syncthreads();

#pragma unroll
        for (int kk = 0; kk < 4; ++kk) {
            int k = kk * 8;
            uint32_t af[2][4];
#pragma unroll
            for (int mi = 0; mi < 2; ++mi) {
                int r = wm * 32 + mi * 16 + gi;
                af[mi][0] = As[r][k + ci];
                af[mi][1] = As[r + 8][k + ci];
                af[mi][2] = As[r][k + ci + 4];
                af[mi][3] = As[r + 8][k + ci + 4];
            }
            uint32_t bf[4][2];
#pragma unroll
            for (int ni = 0; ni < 4; ++ni) {
                int n = wn * 32 + ni * 8 + gi;
                bf[ni][0] = Bs[k + ci][n];
                bf[ni][1] = Bs[k + ci + 4][n];
            }
#pragma unroll
            for (int mi = 0; mi < 2; ++mi)
#pragma unroll
                for (int ni = 0; ni < 4; ++ni)
                    mma8(acc[mi][ni], af[mi][0], af[mi][1], af[mi][2], af[mi][3],
                         bf[ni][0], bf[ni][1]);
        }
        __syncthreads();
    }

#pragma unroll
    for (int mi = 0; mi < 2; ++mi)
#pragma unroll
        for (int ni = 0; ni < 4; ++ni)
#pragma unroll
            for (int j = 0; j < 4; ++j) {
                int m = m0 + wm * 32 + mi * 16 + gi + ((j >= 2) ? 8 : 0);
                int n = n0 + wn * 32 + ni * 8 + 2 * ci + (j & 1);
                gemm_epilogue<MODE>(m, n, acc[mi][ni][j], bias0, bias1);
            }
}

// ---------------- flash attention with tf32 mma ---------------------------------
__global__ __launch_bounds__(128) void flash_mma_kernel()
{
    int g  = blockIdx.x;
    int qt = blockIdx.y;
    int q0 = qt * 64;
    int tid = threadIdx.x;
    int lane = tid & 31, wid = tid >> 5;
    int gi = lane >> 2, ci = lane & 3;

    __shared__ uint32_t Ks[64][68];   // tf32 K tile [key][d]
    __shared__ uint32_t Vs[64][68];   // tf32 V tile [key][d]

    // Q fragments (m16 rows = wid*16..+15, full d=64 in 8 k-steps)
    int r0 = q0 + wid * 16 + gi;      // within sequence
    uint32_t qf[8][4];
    const float* Qg = g_q + (size_t)g * (TLEN * KD);
#pragma unroll
    for (int kk = 0; kk < 8; ++kk) {
        int c = kk * 8 + ci;
        qf[kk][0] = f2tf(Qg[(size_t)r0 * KD + c]);
        qf[kk][1] = f2tf(Qg[(size_t)(r0 + 8) * KD + c]);
        qf[kk][2] = f2tf(Qg[(size_t)r0 * KD + c + 4]);
        qf[kk][3] = f2tf(Qg[(size_t)(r0 + 8) * KD + c + 4]);
    }

    float o[8][4];
#pragma unroll
    for (int a = 0; a < 8; ++a)
#pragma unroll
        for (int b = 0; b < 4; ++b) o[a][b] = 0.f;
    float m0 = -1e30f, m1 = -1e30f, l0 = 0.f, l1 = 0.f;

    int src_lo = (lane & ~3) | (ci >> 1);
    int src_hi = src_lo + 2;
    bool odd = ci & 1;

    int nkt = qt + 1;
    for (int kt = 0; kt < nkt; ++kt) {
        int k0 = kt * 64;
        __syncthreads();
        // load K,V tiles (64x64) as tf32
        const float* Kg = g_k + ((size_t)g * TLEN + k0) * KD;
        const float* Vg = g_v + ((size_t)g * TLEN + k0) * KD;
#pragma unroll
        for (int i = 0; i < 8; ++i) {
            int f4 = tid + i * 128;        // 0..1023
            int row = f4 >> 4, c4 = (f4 & 15) << 2;
            float4 kv = *(const float4*)&Kg[(size_t)row * KD + c4];
            float4 vv = *(const float4*)&Vg[(size_t)row * KD + c4];
            uint4 ku; ku.x = f2tf(kv.x); ku.y = f2tf(kv.y); ku.z = f2tf(kv.z); ku.w = f2tf(kv.w);
            uint4 vu; vu.x = f2tf(vv.x); vu.y = f2tf(vv.y); vu.z = f2tf(vv.z); vu.w = f2tf(vv.w);
            *(uint4*)&Ks[row][c4] = ku;
            *(uint4*)&Vs[row][c4] = vu;
        }
        __syncthreads();

        // S = Q K^T  (16 x 64 per warp)
        float s[8][4];
#pragma unroll
        for (int ni = 0; ni < 8; ++ni) {
            s[ni][0] = s[ni][1] = s[ni][2] = s[ni][3] = 0.f;
            int key = ni * 8 + gi;
#pragma unroll
            for (int kk = 0; kk < 8; ++kk) {
                uint32_t b0 = Ks[key][kk * 8 + ci];
                uint32_t b1 = Ks[key][kk * 8 + ci + 4];
                mma8(s[ni], qf[kk][0], qf[kk][1], qf[kk][2], qf[kk][3], b0, b1);
            }
        }

        // causal mask (diagonal tile only)
        if (kt == qt) {
#pragma unroll
            for (int ni = 0; ni < 8; ++ni) {
#pragma unroll
                for (int j = 0; j < 4; ++j) {
                    int col = k0 + ni * 8 + 2 * ci + (j & 1);
                    int row = r0 + ((j >= 2) ? 8 : 0);
                    if (col > row) s[ni][j] = -1e30f;
                }
            }
        }

        // row max
        float mx0 = -1e30f, mx1 = -1e30f;
#pragma unroll
        for (int ni = 0; ni < 8; ++ni) {
            mx0 = fmaxf(mx0, fmaxf(s[ni][0], s[ni][1]));
            mx1 = fmaxf(mx1, fmaxf(s[ni][2], s[ni][3]));
        }
        mx0 = fmaxf(mx0, __shfl_xor_sync(0xffffffffu, mx0, 1));
        mx0 = fmaxf(mx0, __shfl_xor_sync(0xffffffffu, mx0, 2));
        mx1 = fmaxf(mx1, __shfl_xor_sync(0xffffffffu, mx1, 1));
        mx1 = fmaxf(mx1, __shfl_xor_sync(0xffffffffu, mx1, 2));
        float m0n = fmaxf(m0, mx0), m1n = fmaxf(m1, mx1);
        float corr0 = __expf(m0 - m0n), corr1 = __expf(m1 - m1n);

        float sum0 = 0.f, sum1 = 0.f;
#pragma unroll
        for (int ni = 0; ni < 8; ++ni) {
            s[ni][0] = __expf(s[ni][0] - m0n);
            s[ni][1] = __expf(s[ni][1] - m0n);
            s[ni][2] = __expf(s[ni][2] - m1n);
            s[ni][3] = __expf(s[ni][3] - m1n);
            sum0 += s[ni][0] + s[ni][1];
            sum1 += s[ni][2] + s[ni][3];
        }
        sum0 += __shfl_xor_sync(0xffffffffu, sum0, 1);
        sum0 += __shfl_xor_sync(0xffffffffu, sum0, 2);
        sum1 += __shfl_xor_sync(0xffffffffu, sum1, 1);
        sum1 += __shfl_xor_sync(0xffffffffu, sum1, 2);
        l0 = l0 * corr0 + sum0;
        l1 = l1 * corr1 + sum1;
        m0 = m0n; m1 = m1n;

        // rescale O
#pragma unroll
        for (int nd = 0; nd < 8; ++nd) {
            o[nd][0] *= corr0; o[nd][1] *= corr0;
            o[nd][2] *= corr1; o[nd][3] *= corr1;
        }

        // P @ V : A-fragments via register shuffle from C layout
#pragma unroll
        for (int kg = 0; kg < 8; ++kg) {
            float v00 = __shfl_sync(0xffffffffu, s[kg][0], src_lo);
            float v01 = __shfl_sync(0xffffffffu, s[kg][1], src_lo);
            float v10 = __shfl_sync(0xffffffffu, s[kg][2], src_lo);
            float v11 = __shfl_sync(0xffffffffu, s[kg][3], src_lo);
            float w00 = __shfl_sync(0xffffffffu, s[kg][0], src_hi);
            float w01 = __shfl_sync(0xffffffffu, s[kg][1], src_hi);
            float w10 = __shfl_sync(0xffffffffu, s[kg][2], src_hi);
            float w11 = __shfl_sync(0xffffffffu, s[kg][3], src_hi);
            uint32_t a0 = f2tf(odd ? v01 : v00);
            uint32_t a1 = f2tf(odd ? v11 : v10);
            uint32_t a2 = f2tf(odd ? w01 : w00);
            uint32_t a3 = f2tf(odd ? w11 : w10);
            int key = kg * 8 + ci;
#pragma unroll
            for (int nd = 0; nd < 8; ++nd) {
                uint32_t b0 = Vs[key][nd * 8 + gi];
                uint32_t b1 = Vs[key + 4][nd * 8 + gi];
                mma8(o[nd], a0, a1, a2, a3, b0, b1);
            }
        }
    }

    float inv0 = 1.f / l0, inv1 = 1.f / l1;
    float* Og = g_og + (size_t)g * (TLEN * KD);
#pragma unroll
    for (int nd = 0; nd < 8; ++nd) {
        int c = nd * 8 + 2 * ci;
        float2 t0; t0.x = o[nd][0] * inv0; t0.y = o[nd][1] * inv0;
        float2 t1; t1.x = o[nd][2] * inv1; t1.y = o[nd][3] * inv1;
        *(float2*)&Og[(size_t)r0 * KD + c] = t0;
        *(float2*)&Og[(size_t)(r0 + 8) * KD + c] = t1;
    }
}

// ---------------- local windowed causal attention ------------------------------
__global__ __launch_bounds__(256) void local_attn_kernel()
{
    int g = blockIdx.x;
    int tjbase = blockIdx.y * 64;
    int lane = threadIdx.x & 31;
    int w = threadIdx.x >> 5;
    const float* Lg = g_l + (size_t)g * (TLEN * KD);
    float* Og = g_ol + (size_t)g * (TLEN * KD);
    for (int qi = 0; qi < 8; ++qi) {
        int tj = tjbase + w * 8 + qi;
        float a0 = Lg[tj * 64 + lane];
        float a1 = Lg[tj * 64 + lane + 32];
        float s[6];
        float mx = -1e30f;
#pragma unroll
        for (int wv = 0; wv < 6; ++wv) {
            int tp = tj - 5 + wv;
            float sc = -1e30f;
            if (tp >= 0) {
                float p = a0 * Lg[tp * 64 + lane] + a1 * Lg[tp * 64 + lane + 32];
#pragma unroll
                for (int o = 16; o; o >>= 1) p += __shfl_xor_sync(0xffffffffu, p, o);
                sc = p * 0.125f;
            }
            s[wv] = sc;
            mx = fmaxf(mx, sc);
        }
        float den = 0.f, o0 = 0.f, o1 = 0.f;
#pragma unroll
        for (int wv = 0; wv < 6; ++wv) {
            int tp = tj - 5 + wv;
            if (tp >= 0) {
                float pp = expf(s[wv] - mx);
                den += pp;
                o0 += pp * Lg[tp * 64 + lane];
                o1 += pp * Lg[tp * 64 + lane + 32];
            }
        }
        float inv = 1.f / den;
        Og[tj * 64 + lane] = o0 * inv;
        Og[tj * 64 + lane + 32] = o1 * inv;
    }
}

// ---------------- LN1 -> FF -> LN2 --------------------------------------------
__global__ __launch_bounds__(256) void ffln_kernel(
    const float* __restrict__ ln1g, const float* __restrict__ ln1b,
    const float* __restrict__ ln2g, const float* __restrict__ ln2b,
    const float* __restrict__ w1, const float* __restrict__ b1,
    const float* __restrict__ w2, const float* __restrict__ b2,
    float* __restrict__ out)
{
    const int R = 16;
    __shared__ float yl[R][64];
    __shared__ float hs[R][256];
    __shared__ float fs[R][64];
    int r0 = blockIdx.x * R;
    int tid = threadIdx.x;
    int lane = tid & 31, w = tid >> 5;

    for (int rr = 0; rr < 2; ++rr) {
        int r = w * 2 + rr;
        const float* row = g_y + (size_t)(r0 + r) * 64;
        float v0 = row[lane], v1 = row[lane + 32];
        float sm = v0 + v1;
#pragma unroll
        for (int o = 16; o; o >>= 1) sm += __shfl_xor_sync(0xffffffffu, sm, o);
        float mean = sm * (1.f / 64.f);
        float d0 = v0 - mean, d1 = v1 - mean;
        float vs = d0 * d0 + d1 * d1;
#pragma unroll
        for (int o = 16; o; o >>= 1) vs += __shfl_xor_sync(0xffffffffu, vs, o);
        float inv = rsqrtf(vs * (1.f / 64.f) + 1e-5f);
        yl[r][lane]      = d0 * inv * ln1g[lane] + ln1b[lane];
        yl[r][lane + 32] = d1 * inv * ln1g[lane + 32] + ln1b[lane + 32];
    }
    __syncthreads();

    {
        float acc[R];
#pragma unroll
        for (int r = 0; r < R; ++r) acc[r] = b1[tid];
        for (int c = 0; c < 64; ++c) {
            float wv = w1[c * 256 + tid];
#pragma unroll
            for (int r = 0; r < R; ++r) acc[r] += yl[r][c] * wv;
        }
#pragma unroll
        for (int r = 0; r < R; ++r) hs[r][tid] = fmaxf(acc[r], 0.f);
    }
    __syncthreads();

    {
        int j2 = tid & 63, rg = tid >> 6;
#pragma unroll
        for (int rr = 0; rr < 4; ++rr) {
            int r = rg * 4 + rr;
            float a = b2[j2];
            for (int c = 0; c < 256; ++c) a += hs[r][c] * w2[c * 64 + j2];
            fs[r][j2] = a + yl[r][j2];
        }
    }
    __syncthreads();

    for (int rr = 0; rr < 2; ++rr) {
        int r = w * 2 + rr;
        float v0 = fs[r][lane], v1 = fs[r][lane + 32];
        float sm = v0 + v1;
#pragma unroll
        for (int o = 16; o; o >>= 1) sm += __shfl_xor_sync(0xffffffffu, sm, o);
        float mean = sm * (1.f / 64.f);
        float d0 = v0 - mean, d1 = v1 - mean;
        float vs = d0 * d0 + d1 * d1;
#pragma unroll
        for (int o = 16; o; o >>= 1) vs += __shfl_xor_sync(0xffffffffu, vs, o);
        float inv = rsqrtf(vs * (1.f / 64.f) + 1e-5f);
        float* orow = out + (size_t)(r0 + r) * 64;
        orow[lane]      = d0 * inv * ln2g[lane] + ln2b[lane];
        orow[lane + 32] = d1 * inv * ln2g[lane + 32] + ln2b[lane + 32];
    }
}

// ---------------- launch ---------------------------------------------------------
extern "C" void kernel_launch(void* const* d_in, const int* in_sizes, int n_in,
                              void* d_out, int out_size)
{
    (void)in_sizes; (void)n_in; (void)out_size;
    const float* x       = (const float*)d_in[0];
    const float* sq_w    = (const float*)d_in[1];
    const float* bn_g    = (const float*)d_in[2];
    const float* bn_b    = (const float*)d_in[3];
    const float* dw_w    = (const float*)d_in[4];
    const float* ex_w    = (const float*)d_in[5];
    const float* pos_emb = (const float*)d_in[6];
    const float* wq      = (const float*)d_in[7];
    const float* bq      = (const float*)d_in[8];
    const float* wk      = (const float*)d_in[9];
    const float* bk      = (const float*)d_in[10];
    const float* wv      = (const float*)d_in[11];
    const float* wl      = (const float*)d_in[12];
    const float* uni_w   = (const float*)d_in[13];
    const float* uni_b   = (const float*)d_in[14];
    const float* ln1_g   = (const float*)d_in[15];
    const float* ln1_b   = (const float*)d_in[16];
    const float* ln2_g   = (const float*)d_in[17];
    const float* ln2_b   = (const float*)d_in[18];
    const float* ff_w1   = (const float*)d_in[19];
    const float* ff_b1   = (const float*)d_in[20];
    const float* ff_w2   = (const float*)d_in[21];
    const float* ff_b2   = (const float*)d_in[22];
    float* out = (float*)d_out;

    x3_kernel<<<512, 256>>>(x, sq_w, bn_g, bn_b);
    xin_kernel<<<dim3(4, 8), 256>>>(x, dw_w, ex_w, pos_emb);

    prep_wqk_kernel<<<1280, 256>>>(wq, wk);
    prep_wvl_kernel<<<256, 256>>>(wv, wl);
    prep_A_kernel<<<5120, 256>>>();

    gemm_mma_kernel<0><<<dim3(32, 16), 256>>>(nullptr, bq, bk);
    gemm_mma_kernel<1><<<dim3(32, 16), 256>>>(nullptr, nullptr, nullptr);

    flash_mma_kernel<<<dim3(32, 16), 128>>>();
    local_attn_kernel<<<dim3(32, 16), 256>>>();

    gate_kernel<<<16384, 256>>>();
    gemm_mma_kernel<2><<<dim3(32, 1), 256>>>(uni_w, uni_b, nullptr);

    ffln_kernel<<<256, 256>>>(ln1_g, ln1_b, ln2_g, ln2_b,
                              ff_w1, ff_b1, ff_w2, ff_b2, out);
}

// round 3
// speedup vs baseline: 1.9534x; 1.1943x over previous
#include <cuda_runtime.h>
#include <math.h>
#include <stdint.h>

// Problem constants (fixed by setup_inputs)
#define BATCH 4
#define TLEN  1024
#define KD    64
#define HNUM  8
#define R32   32
#define NSEQ  32      // BATCH*HNUM
#define MROWS 4096    // BATCH*TLEN

// ---------------- scratch (static device globals; no allocation) --------------
__device__ float g_x3[BATCH * R32 * TLEN];
__device__ float g_xin[BATCH * TLEN * KD];          // tf32-exact
__device__ float g_WB[320 * 1024];                  // tap-major reordered wq|wk, tf32-exact
__device__ float g_WB2[64 * 1024];                  // wv|wl transposed, tf32-exact
__device__ float g_WU[1024 * 64];                   // uni_w, tf32-exact
__device__ float g_q[NSEQ * TLEN * KD];             // tf32-exact
__device__ float g_k[NSEQ * TLEN * KD];
__device__ float g_v[NSEQ * TLEN * KD];
__device__ float g_l[NSEQ * TLEN * KD];
__device__ float g_og[NSEQ * TLEN * KD];
__device__ float g_ol[NSEQ * TLEN * KD];
__device__ float g_part[4 * MROWS * KD];            // uni GEMM K-split partials

__device__ __forceinline__ float sigmoid_exact(float x) { return 1.f / (1.f + expf(-x)); }
__device__ __forceinline__ float sigmoid_fast(float x) {
    float t;
    asm("tanh.approx.f32 %0, %1;" : "=f"(t) : "f"(0.5f * x));
    return 0.5f * t + 0.5f;
}
__device__ __forceinline__ float silu_fast(float x) { return x * sigmoid_fast(x); }

// round f32 -> nearest tf32 (result is a valid f32 with low mantissa zeroed)
__device__ __forceinline__ float tf32r(float x) {
    uint32_t u;
    asm("cvt.rna.tf32.f32 %0, %1;" : "=r"(u) : "f"(x));
    return __uint_as_float(u);
}

__device__ __forceinline__ void mma8(float* c,
                                     uint32_t a0, uint32_t a1, uint32_t a2, uint32_t a3,
                                     uint32_t b0, uint32_t b1) {
    asm volatile(
        "mma.sync.aligned.m16n8k8.row.col.f32.tf32.tf32.f32 "
        "{%0,%1,%2,%3}, {%4,%5,%6,%7}, {%8,%9}, {%0,%1,%2,%3};"
        : "+f"(c[0]), "+f"(c[1]), "+f"(c[2]), "+f"(c[3])
        : "r"(a0), "r"(a1), "r"(a2), "r"(a3), "r"(b0), "r"(b1));
}

__device__ __forceinline__ void cp16(uint32_t dst, const void* src) {
    asm volatile("cp.async.ca.shared.global [%0], [%1], 16;" :: "r"(dst), "l"(src) : "memory");
}
__device__ __forceinline__ void cp16p(uint32_t dst, const void* src, int sz) {
    asm volatile("cp.async.ca.shared.global [%0], [%1], 16, %2;" :: "r"(dst), "l"(src), "r"(sz) : "memory");
}
#define CPCOMMIT() asm volatile("cp.async.commit_group;" ::: "memory")
#define CPWAIT0()  asm volatile("cp.async.wait_group 0;" ::: "memory")
#define CPWAIT1()  asm volatile("cp.async.wait_group 1;" ::: "memory")

// ---------------- kernel 1: x3 = bn(1x1 conv) --------------------------------
__global__ __launch_bounds__(256) void x3_kernel(
    const float* __restrict__ x, const float* __restrict__ sq_w,
    const float* __restrict__ bn_g, const float* __restrict__ bn_b)
{
    int idx = blockIdx.x * 256 + threadIdx.x;
    if (idx >= BATCH * R32 * TLEN) return;
    int pos = idx & 1023;
    int r   = (idx >> 10) & 31;
    int bi  = idx >> 15;
    const float* xr = x + ((size_t)bi * TLEN + pos) * KD;
    const float* wr = sq_w + r * KD;
    float s = 0.f;
#pragma unroll
    for (int c = 0; c < KD; ++c) s += xr[c] * wr[c];
    g_x3[idx] = s * bn_g[r] * 0.9999950000374997f + bn_b[r];
}

// ---------------- kernel 2: action gate + pos_emb -> xin (tf32-exact) ---------
__global__ __launch_bounds__(256) void xin_kernel(
    const float* __restrict__ x, const float* __restrict__ dw_w,
    const float* __restrict__ ex_w, const float* __restrict__ pos_emb)
{
    int bi = blockIdx.x;
    int t0 = blockIdx.y * 128;
    __shared__ float xp3[R32][128];
    int tid = threadIdx.x;
    for (int i = tid; i < R32 * 128; i += 256) {
        int r = i >> 7, j = i & 127;
        int pos = t0 + j;
        const float* x3r = g_x3 + bi * (R32 * TLEN) + r * TLEN;
        float v;
        if (pos == TLEN - 1) {
            v = x3r[TLEN - 1];
        } else {
            float d0 = dw_w[r * 3 + 0], d1 = dw_w[r * 3 + 1], d2 = dw_w[r * 3 + 2];
            float a = x3r[pos] * d0 + x3r[pos + 1] * d1 +
                      ((pos + 2 < TLEN) ? x3r[pos + 2] * d2 : 0.f);
            v = a - x3r[pos];
        }
        xp3[r][j] = v;
    }
    __syncthreads();
    for (int i = tid; i < 128 * KD; i += 256) {
        int j = i >> 6, c = i & 63;
        int pos = t0 + j;
        float gsum = 0.f;
#pragma unroll
        for (int r = 0; r < R32; ++r) gsum += xp3[r][j] * ex_w[c * R32 + r];
        float sig = sigmoid_exact(gsum);
        size_t off = ((size_t)bi * TLEN + pos) * KD + c;
        g_xin[off] = tf32r(x[off] * sig + pos_emb[pos * KD + c]);
    }
}

// ---------------- weight prep (reorder + tf32 round) ---------------------------
__global__ __launch_bounds__(256) void prep_wqk_kernel(
    const float* __restrict__ wq, const float* __restrict__ wk)
{
    int idx = blockIdx.x * 256 + threadIdx.x;     // kcol*1024 + n, tap-major kcol=mm*64+c
    if (idx >= 320 * 1024) return;
    int n = idx & 1023, kcol = idx >> 10;
    int mm = kcol >> 6, c = kcol & 63;
    float w = (n < 512) ? wq[n * 320 + c * 5 + mm] : wk[(n - 512) * 320 + c * 5 + mm];
    g_WB[idx] = tf32r(w);
}

__global__ __launch_bounds__(256) void prep_wvl_kernel(
    const float* __restrict__ wv, const float* __restrict__ wl,
    const float* __restrict__ uni_w)
{
    int idx = blockIdx.x * 256 + threadIdx.x;
    if (idx < 65536) {
        int n = idx & 1023, c = idx >> 10;
        g_WB2[idx] = tf32r((n < 512) ? wv[n * 64 + c] : wl[(n - 512) * 64 + c]);
    } else if (idx < 131072) {
        int j = idx - 65536;
        g_WU[j] = tf32r(uni_w[j]);
    }
}

// ---------------- conv GEMMs (tf32 mma, cp.async double-buffered) ---------------
// MODE 0: QK conv (K=320 tap-major, im2col fused into A loads, B=g_WB)
// MODE 1: VL conv (K=64, A=g_xin direct, B=g_WB2)
template <int MODE>
__global__ __launch_bounds__(256) void convgemm_kernel(
    const float* __restrict__ bias0, const float* __restrict__ bias1)
{
    const int NSTAGE = (MODE == 0) ? 10 : 2;
    extern __shared__ float sm[];
    float* As = sm;                   // [2][128][36]
    float* Bs = sm + 2 * 128 * 36;    // [2][32][68]
    const float* __restrict__ Bg = (MODE == 0) ? g_WB : g_WB2;

    int tid = threadIdx.x, lane = tid & 31, wid = tid >> 5;
    int wm = wid & 3, wn = wid >> 2, gi = lane >> 2, ci = lane & 3;
    int m0 = blockIdx.x * 128, n0 = blockIdx.y * 64;
    int bi = m0 >> 10, tibase = m0 & 1023;
    uint32_t sb = (uint32_t)__cvta_generic_to_shared(sm);
    uint32_t a_sb = sb, b_sb = sb + 2 * 128 * 36 * 4;

    // stage issue (all threads participate)
#define ISSUE_STAGE(s_, buf_)                                                        \
    do {                                                                             \
        int mm_ = (MODE == 0) ? ((s_) >> 1) : 0;                                     \
        int c0_ = (MODE == 0) ? (((s_) & 1) << 5) : ((s_) << 5);                     \
        int sh_ = (MODE == 0) ? (2 * mm_ - 8) : 0;                                   \
        _Pragma("unroll")                                                            \
        for (int i_ = 0; i_ < 4; ++i_) {                                             \
            int f4 = tid + i_ * 256;                                                 \
            int row = f4 >> 3, c4 = (f4 & 7) << 2;                                   \
            int tsrc = tibase + row + sh_;                                           \
            const float* srcp = g_xin + ((size_t)(bi << 10) + tsrc) * 64 + c0_ + c4; \
            uint32_t dstp = a_sb + (uint32_t)(((buf_) * 4608 + row * 36 + c4) * 4);  \
            cp16p(dstp, srcp, (tsrc >= 0) ? 16 : 0);                                 \
        }                                                                            \
        _Pragma("unroll")                                                            \
        for (int i_ = 0; i_ < 2; ++i_) {                                             \
            int f4 = tid + i_ * 256;                                                 \
            int row = f4 >> 4, c4 = (f4 & 15) << 2;                                  \
            const float* srcp = Bg + (size_t)((s_) * 32 + row) * 1024 + n0 + c4;     \
            uint32_t dstp = b_sb + (uint32_t)(((buf_) * 2176 + row * 68 + c4) * 4);  \
            cp16(dstp, srcp);                                                        \
        }                                                                            \
        CPCOMMIT();                                                                  \
    } while (0)

    float acc[2][4][4];
#pragma unroll
    for (int a = 0; a < 2; ++a)
#pragma unroll
        for (int b = 0; b < 4; ++b)
#pragma unroll
            for (int c = 0; c < 4; ++c) acc[a][b][c] = 0.f;

    ISSUE_STAGE(0, 0);
    for (int s = 0; s < NSTAGE; ++s) {
        if (s + 1 < NSTAGE) { ISSUE_STAGE(s + 1, (s + 1) & 1); CPWAIT1(); }
        else CPWAIT0();
        __syncthreads();
        const float* Ab = As + (s & 1) * 4608;
        const float* Bb = Bs + (s & 1) * 2176;
#pragma unroll
        for (int kk = 0; kk < 4; ++kk) {
            int k = kk * 8;
            uint32_t af[2][4];
#pragma unroll
            for (int mi = 0; mi < 2; ++mi) {
                int r = wm * 32 + mi * 16 + gi;
                af[mi][0] = __float_as_uint(Ab[r * 36 + k + ci]);
                af[mi][1] = __float_as_uint(Ab[(r + 8) * 36 + k + ci]);
                af[mi][2] = __float_as_uint(Ab[r * 36 + k + ci + 4]);
                af[mi][3] = __float_as_uint(Ab[(r + 8) * 36 + k + ci + 4]);
            }
            uint32_t bf[4][2];
#pragma unroll
            for (int ni = 0; ni < 4; ++ni) {
                int n = wn * 32 + ni * 8 + gi;
                bf[ni][0] = __float_as_uint(Bb[(k + ci) * 68 + n]);
                bf[ni][1] = __float_as_uint(Bb[(k + ci + 4) * 68 + n]);
            }
#pragma unroll
            for (int mi = 0; mi < 2; ++mi)
#pragma unroll
                for (int ni = 0; ni < 4; ++ni)
                    mma8(acc[mi][ni], af[mi][0], af[mi][1], af[mi][2], af[mi][3],
                         bf[ni][0], bf[ni][1]);
        }
        __syncthreads();
    }
#undef ISSUE_STAGE

#pragma unroll
    for (int mi = 0; mi < 2; ++mi)
#pragma unroll
        for (int ni = 0; ni < 4; ++ni)
#pragma unroll
            for (int j = 0; j < 4; ++j) {
                int m = m0 + wm * 32 + mi * 16 + gi + ((j >= 2) ? 8 : 0);
                int n = n0 + wn * 32 + ni * 8 + 2 * ci + (j & 1);
                float v = acc[mi][ni][j];
                int o = n & 511, ki = o >> 3, h = o & 7;
                int bb = m >> 10, ti = m & 1023;
                int gg = bb * 8 + (ti >> 7);
                int tj = ((ti & 127) << 3) | h;
                float s;
                float* dst;
                if (MODE == 0) {
                    float bias = (n < 512) ? bias0[n] : bias1[n - 512];
                    s = silu_fast(v + bias) * 0.35355339059327373f;  // / 64^0.25
                    dst = (n < 512) ? g_q : g_k;
                } else {
                    s = silu_fast(v);
                    dst = (n < 512) ? g_v : g_l;
                }
                dst[((size_t)gg * TLEN + tj) * KD + ki] = tf32r(s);
            }
}

// ---------------- flash attention (tf32 mma, 8 warps, cp.async dbl-buffered) ---
__global__ __launch_bounds__(256) void flash_mma_kernel()
{
    extern __shared__ float sm[];   // Ks[2][64][68] | Vs[2][64][68]
    int g  = blockIdx.x;
    int qy = blockIdx.y;
    int q0 = qy * 128;
    int tid = threadIdx.x, lane = tid & 31, wid = tid >> 5;
    int gi = lane >> 2, ci = lane & 3;
    uint32_t sb = (uint32_t)__cvta_generic_to_shared(sm);

    const float* Qg = g_q + (size_t)g * (TLEN * KD);
    int r0 = q0 + wid * 16 + gi;
    uint32_t qf[8][4];
#pragma unroll
    for (int kk = 0; kk < 8; ++kk) {
        int c = kk * 8 + ci;
        qf[kk][0] = __float_as_uint(Qg[(size_t)r0 * KD + c]);
        qf[kk][1] = __float_as_uint(Qg[(size_t)(r0 + 8) * KD + c]);
        qf[kk][2] = __float_as_uint(Qg[(size_t)r0 * KD + c + 4]);
        qf[kk][3] = __float_as_uint(Qg[(size_t)(r0 + 8) * KD + c + 4]);
    }

    float o[8][4];
#pragma unroll
    for (int a = 0; a < 8; ++a)
#pragma unroll
        for (int b = 0; b < 4; ++b) o[a][b] = 0.f;
    float m0v = -1e30f, m1v = -1e30f, l0 = 0.f, l1 = 0.f;

    int src_lo = (lane & ~3) | (ci >> 1);
    int src_hi = src_lo + 2;
    bool odd = ci & 1;

    const float* Kg0 = g_k + (size_t)g * (TLEN * KD);
    const float* Vg0 = g_v + (size_t)g * (TLEN * KD);
    int nkt = 2 * qy + 2;

#define FLASH_ISSUE(kt_, buf_)                                                       \
    do {                                                                             \
        const float* Kg = Kg0 + (size_t)(kt_) * 64 * 64;                             \
        const float* Vg = Vg0 + (size_t)(kt_) * 64 * 64;                             \
        _Pragma("unroll")                                                            \
        for (int i_ = 0; i_ < 4; ++i_) {                                             \
            int f4 = tid + i_ * 256;                                                 \
            int row = f4 >> 4, c4 = (f4 & 15) << 2;                                  \
            uint32_t kd = sb + (uint32_t)((((buf_) * 4352) + row * 68 + c4) * 4);    \
            uint32_t vd = sb + (uint32_t)(((8704 + (buf_) * 4352) + row * 68 + c4) * 4); \
            cp16(kd, Kg + row * 64 + c4);                                            \
            cp16(vd, Vg + row * 64 + c4);                                            \
        }                                                                            \
        CPCOMMIT();                                                                  \
    } while (0)

    FLASH_ISSUE(0, 0);
    for (int kt = 0; kt < nkt; ++kt) {
        int k0 = kt * 64;
        if (kt + 1 < nkt) { FLASH_ISSUE(kt + 1, (kt + 1) & 1); CPWAIT1(); }
        else CPWAIT0();
        __syncthreads();
        const float* Ks = sm + (kt & 1) * 4352;
        const float* Vs = sm + 8704 + (kt & 1) * 4352;
        int wrmin = q0 + wid * 16;
        if (k0 <= wrmin + 15) {
            // S = Q K^T (16 x 64 per warp)
            float s[8][4];
#pragma unroll
            for (int ni = 0; ni < 8; ++ni) {
                s[ni][0] = s[ni][1] = s[ni][2] = s[ni][3] = 0.f;
                int key = ni * 8 + gi;
#pragma unroll
                for (int kk = 0; kk < 8; ++kk) {
                    uint32_t b0 = __float_as_uint(Ks[key * 68 + kk * 8 + ci]);
                    uint32_t b1 = __float_as_uint(Ks[key * 68 + kk * 8 + ci + 4]);
                    mma8(s[ni], qf[kk][0], qf[kk][1], qf[kk][2], qf[kk][3], b0, b1);
                }
            }
            if (k0 + 63 > wrmin) {   // diagonal tile: causal mask
#pragma unroll
                for (int ni = 0; ni < 8; ++ni)
#pragma unroll
                    for (int j = 0; j < 4; ++j) {
                        int col = k0 + ni * 8 + 2 * ci + (j & 1);
                        int row = r0 + ((j >= 2) ? 8 : 0);
                        if (col > row) s[ni][j] = -1e30f;
                    }
            }
            // online softmax
            float mx0 = -1e30f, mx1 = -1e30f;
#pragma unroll
            for (int ni = 0; ni < 8; ++ni) {
                mx0 = fmaxf(mx0, fmaxf(s[ni][0], s[ni][1]));
                mx1 = fmaxf(mx1, fmaxf(s[ni][2], s[ni][3]));
            }
            mx0 = fmaxf(mx0, __shfl_xor_sync(0xffffffffu, mx0, 1));
            mx0 = fmaxf(mx0, __shfl_xor_sync(0xffffffffu, mx0, 2));
            mx1 = fmaxf(mx1, __shfl_xor_sync(0xffffffffu, mx1, 1));
            mx1 = fmaxf(mx1, __shfl_xor_sync(0xffffffffu, mx1, 2));
            float m0n = fmaxf(m0v, mx0), m1n = fmaxf(m1v, mx1);
            float corr0 = __expf(m0v - m0n), corr1 = __expf(m1v - m1n);

            float sum0 = 0.f, sum1 = 0.f;
#pragma unroll
            for (int ni = 0; ni < 8; ++ni) {
                s[ni][0] = tf32r(__expf(s[ni][0] - m0n));
                s[ni][1] = tf32r(__expf(s[ni][1] - m0n));
                s[ni][2] = tf32r(__expf(s[ni][2] - m1n));
                s[ni][3] = tf32r(__expf(s[ni][3] - m1n));
                sum0 += s[ni][0] + s[ni][1];
                sum1 += s[ni][2] + s[ni][3];
            }
            sum0 += __shfl_xor_sync(0xffffffffu, sum0, 1);
            sum0 += __shfl_xor_sync(0xffffffffu, sum0, 2);
            sum1 += __shfl_xor_sync(0xffffffffu, sum1, 1);
            sum1 += __shfl_xor_sync(0xffffffffu, sum1, 2);
            l0 = l0 * corr0 + sum0;
            l1 = l1 * corr1 + sum1;
            m0v = m0n; m1v = m1n;
#pragma unroll
            for (int nd = 0; nd < 8; ++nd) {
                o[nd][0] *= corr0; o[nd][1] *= corr0;
                o[nd][2] *= corr1; o[nd][3] *= corr1;
            }
            // P @ V with register relayout
#pragma unroll
            for (int kg = 0; kg < 8; ++kg) {
                float v00 = __shfl_sync(0xffffffffu, s[kg][0], src_lo);
                float v01 = __shfl_sync(0xffffffffu, s[kg][1], src_lo);
                float v10 = __shfl_sync(0xffffffffu, s[kg][2], src_lo);
                float v11 = __shfl_sync(0xffffffffu, s[kg][3], src_lo);
                float w00 = __shfl_sync(0xffffffffu, s[kg][0], src_hi);
                float w01 = __shfl_sync(0xffffffffu, s[kg][1], src_hi);
                float w10 = __shfl_sync(0xffffffffu, s[kg][2], src_hi);
                float w11 = __shfl_sync(0xffffffffu, s[kg][3], src_hi);
                uint32_t a0 = __float_as_uint(odd ? v01 : v00);
                uint32_t a1 = __float_as_uint(odd ? v11 : v10);
                uint32_t a2 = __float_as_uint(odd ? w01 : w00);
                uint32_t a3 = __float_as_uint(odd ? w11 : w10);
                int key = kg * 8 + ci;
#pragma unroll
                for (int nd = 0; nd < 8; ++nd) {
                    uint32_t b0 = __float_as_uint(Vs[key * 68 + nd * 8 + gi]);
                    uint32_t b1 = __float_as_uint(Vs[(key + 4) * 68 + nd * 8 + gi]);
                    mma8(o[nd], a0, a1, a2, a3, b0, b1);
                }
            }
        }
        __syncthreads();
    }
#undef FLASH_ISSUE

    float inv0 = 1.f / l0, inv1 = 1.f / l1;
    float* Og = g_og + (size_t)g * (TLEN * KD);
#pragma unroll
    for (int nd = 0; nd < 8; ++nd) {
        int c = nd * 8 + 2 * ci;
        float2 t0; t0.x = o[nd][0] * inv0; t0.y = o[nd][1] * inv0;
        float2 t1; t1.x = o[nd][2] * inv1; t1.y = o[nd][3] * inv1;
        *(float2*)&Og[(size_t)r0 * KD + c] = t0;
        *(float2*)&Og[(size_t)(r0 + 8) * KD + c] = t1;
    }
}

// ---------------- local windowed causal attention ------------------------------
__global__ __launch_bounds__(256) void local_attn_kernel()
{
    int g = blockIdx.x;
    int tjbase = blockIdx.y * 64;
    int lane = threadIdx.x & 31;
    int w = threadIdx.x >> 5;
    const float* Lg = g_l + (size_t)g * (TLEN * KD);
    float* Og = g_ol + (size_t)g * (TLEN * KD);
    for (int qi = 0; qi < 8; ++qi) {
        int tj = tjbase + w * 8 + qi;
        float a0 = Lg[tj * 64 + lane];
        float a1 = Lg[tj * 64 + lane + 32];
        float s[6];
        float mx = -1e30f;
#pragma unroll
        for (int wv = 0; wv < 6; ++wv) {
            int tp = tj - 5 + wv;
            float sc = -1e30f;
            if (tp >= 0) {
                float p = a0 * Lg[tp * 64 + lane] + a1 * Lg[tp * 64 + lane + 32];
#pragma unroll
                for (int o = 16; o; o >>= 1) p += __shfl_xor_sync(0xffffffffu, p, o);
                sc = p * 0.125f;
            }
            s[wv] = sc;
            mx = fmaxf(mx, sc);
        }
        float den = 0.f, o0 = 0.f, o1 = 0.f;
#pragma unroll
        for (int wv = 0; wv < 6; ++wv) {
            int tp = tj - 5 + wv;
            if (tp >= 0) {
                float pp = expf(s[wv] - mx);
                den += pp;
                o0 += pp * Lg[tp * 64 + lane];
                o1 += pp * Lg[tp * 64 + lane + 32];
            }
        }
        float inv = 1.f / den;
        Og[tj * 64 + lane] = o0 * inv;
        Og[tj * 64 + lane + 32] = o1 * inv;
    }
}

// ---------------- uni projection: fused gating + K-split tf32 GEMM -------------
__global__ __launch_bounds__(256) void unigemm_kernel()
{
    __shared__ float As[128][36];
    __shared__ float Bs[32][68];
    int tid = threadIdx.x, lane = tid & 31, wid = tid >> 5;
    int wm = wid & 3, wn = wid >> 2, gi = lane >> 2, ci = lane & 3;
    int m0 = blockIdx.x * 128;
    int kz = blockIdx.y;
    int bi = m0 >> 10, tib = m0 & 1023;
    uint32_t b_sb = (uint32_t)__cvta_generic_to_shared(&Bs[0][0]);

    float acc[2][4][4];
#pragma unroll
    for (int a = 0; a < 2; ++a)
#pragma unroll
        for (int b = 0; b < 4; ++b)
#pragma unroll
            for (int c = 0; c < 4; ++c) acc[a][b][c] = 0.f;

    for (int s = 0; s < 8; ++s) {
        int k0 = kz * 256 + s * 32;
        int ch = k0 >> 6, ki0 = k0 & 63;
        int h2 = ch & 7;
        bool lohalf = ch < 8;
        const float* Og = g_og + (size_t)(bi * 8 + h2) * (TLEN * KD);
        const float* Lg = g_ol + (size_t)(bi * 8 + h2) * (TLEN * KD);
        __syncthreads();
        // B tile via cp.async
#pragma unroll
        for (int i = 0; i < 2; ++i) {
            int f4 = tid + i * 256;
            int row = f4 >> 4, c4 = (f4 & 15) << 2;
            cp16(b_sb + (uint32_t)((row * 68 + c4) * 4), g_WU + (size_t)(k0 + row) * 64 + c4);
        }
        CPCOMMIT();
        // A tile: gather og/ol, gate, round, store
#pragma unroll
        for (int i = 0; i < 4; ++i) {
            int f4 = tid + i * 256;
            int row = f4 >> 3, c4 = (f4 & 7) << 2;
            int ti2 = tib + row;
            const float4 o4 = *(const float4*)(Og + (size_t)ti2 * 64 + ki0 + c4);
            const float4 l4 = *(const float4*)(Lg + (size_t)ti2 * 64 + ki0 + c4);
            float g0 = sigmoid_fast(o4.x), g1 = sigmoid_fast(o4.y);
            float g2 = sigmoid_fast(o4.z), g3 = sigmoid_fast(o4.w);
            float r0 = lohalf ? (1.f - g0) * l4.x : g0 * o4.x;
            float r1 = lohalf ? (1.f - g1) * l4.y : g1 * o4.y;
            float r2 = lohalf ? (1.f - g2) * l4.z : g2 * o4.z;
            float r3 = lohalf ? (1.f - g3) * l4.w : g3 * o4.w;
            As[row][c4 + 0] = tf32r(r0);
            As[row][c4 + 1] = tf32r(r1);
            As[row][c4 + 2] = tf32r(r2);
            As[row][c4 + 3] = tf32r(r3);
        }
        CPWAIT0();
        __syncthreads();
#pragma unroll
        for (int kk = 0; kk < 4; ++kk) {
            int k = kk * 8;
            uint32_t af[2][4];
#pragma unroll
            for (int mi = 0; mi < 2; ++mi) {
                int r = wm * 32 + mi * 16 + gi;
                af[mi][0] = __float_as_uint(As[r][k + ci]);
                af[mi][1] = __float_as_uint(As[r + 8][k + ci]);
                af[mi][2] = __float_as_uint(As[r][k + ci + 4]);
                af[mi][3] = __float_as_uint(As[r + 8][k + ci + 4]);
            }
            uint32_t bf[4][2];
#pragma unroll
            for (int ni = 0; ni < 4; ++ni) {
                int n = wn * 32 + ni * 8 + gi;
                bf[ni][0] = __float_as_uint(Bs[k + ci][n]);
                bf[ni][1] = __float_as_uint(Bs[k + ci + 4][n]);
            }
#pragma unroll
            for (int mi = 0; mi < 2; ++mi)
#pragma unroll
                for (int ni = 0; ni < 4; ++ni)
                    mma8(acc[mi][ni], af[mi][0], af[mi][1], af[mi][2], af[mi][3],
                         bf[ni][0], bf[ni][1]);
        }
    }

    float* P = g_part + ((size_t)kz * MROWS + m0) * 64;
#pragma unroll
    for (int mi = 0; mi < 2; ++mi)
#pragma unroll
        for (int ni = 0; ni < 4; ++ni)
#pragma unroll
            for (int j = 0; j < 4; j += 2) {
                int mrow = wm * 32 + mi * 16 + gi + ((j >= 2) ? 8 : 0);
                int n = wn * 32 + ni * 8 + 2 * ci;
                float2 t; t.x = acc[mi][ni][j]; t.y = acc[mi][ni][j + 1];
                *(float2*)&P[(size_t)mrow * 64 + n] = t;
            }
}

// ---------------- partial-reduce + silu + residual -> LN1 -> FF -> LN2 ---------
__global__ __launch_bounds__(256) void ffln_kernel(
    const float* __restrict__ uni_b,
    const float* __restrict__ ln1g, const float* __restrict__ ln1b,
    const float* __restrict__ ln2g, const float* __restrict__ ln2b,
    const float* __restrict__ w1, const float* __restrict__ b1,
    const float* __restrict__ w2, const float* __restrict__ b2,
    float* __restrict__ out)
{
    const int R = 16;
    __shared__ float yl[R][64];
    __shared__ float hs[R][256];
    __shared__ float fs[R][64];
    int r0 = blockIdx.x * R;
    int tid = threadIdx.x;
    int lane = tid & 31, w = tid >> 5;

    for (int rr = 0; rr < 2; ++rr) {
        int r = w * 2 + rr;
        size_t rg = (size_t)(r0 + r) * 64;
        float v0 = g_part[rg + lane] + g_part[(size_t)MROWS * 64 + rg + lane] +
                   g_part[(size_t)MROWS * 128 + rg + lane] + g_part[(size_t)MROWS * 192 + rg + lane];
        float v1 = g_part[rg + lane + 32] + g_part[(size_t)MROWS * 64 + rg + lane + 32] +
                   g_part[(size_t)MROWS * 128 + rg + lane + 32] + g_part[(size_t)MROWS * 192 + rg + lane + 32];
        v0 = silu_fast(v0 + uni_b[lane]) + g_xin[rg + lane];
        v1 = silu_fast(v1 + uni_b[lane + 32]) + g_xin[rg + lane + 32];
        float sm = v0 + v1;
#pragma unroll
        for (int o = 16; o; o >>= 1) sm += __shfl_xor_sync(0xffffffffu, sm, o);
        float mean = sm * (1.f / 64.f);
        float d0 = v0 - mean, d1 = v1 - mean;
        float vs = d0 * d0 + d1 * d1;
#pragma unroll
        for (int o = 16; o; o >>= 1) vs += __shfl_xor_sync(0xffffffffu, vs, o);
        float inv = rsqrtf(vs * (1.f / 64.f) + 1e-5f);
        yl[r][lane]      = d0 * inv * ln1g[lane] + ln1b[lane];
        yl[r][lane + 32] = d1 * inv * ln1g[lane + 32] + ln1b[lane + 32];
    }
    __syncthreads();

    {
        float acc[R];
#pragma unroll
        for (int r = 0; r < R; ++r) acc[r] = b1[tid];
        for (int c = 0; c < 64; ++c) {
            float wv = w1[c * 256 + tid];
#pragma unroll
            for (int r = 0; r < R; ++r) acc[r] += yl[r][c] * wv;
        }
#pragma unroll
        for (int r = 0; r < R; ++r) hs[r][tid] = fmaxf(acc[r], 0.f);
    }
    __syncthreads();

    {
        int j2 = tid & 63, rg = tid >> 6;
#pragma unroll
        for (int rr = 0; rr < 4; ++rr) {
            int r = rg * 4 + rr;
            float a = b2[j2];
            for (int c = 0; c < 256; ++c) a += hs[r][c] * w2[c * 64 + j2];
            fs[r][j2] = a + yl[r][j2];
        }
    }
    __syncthreads();

    for (int rr = 0; rr < 2; ++rr) {
        int r = w * 2 + rr;
        float v0 = fs[r][lane], v1 = fs[r][lane + 32];
        float sm = v0 + v1;
#pragma unroll
        for (int o = 16; o; o >>= 1) sm += __shfl_xor_sync(0xffffffffu, sm, o);
        float mean = sm * (1.f / 64.f);
        float d0 = v0 - mean, d1 = v1 - mean;
        float vs = d0 * d0 + d1 * d1;
#pragma unroll
        for (int o = 16; o; o >>= 1) vs += __shfl_xor_sync(0xffffffffu, vs, o);
        float inv = rsqrtf(vs * (1.f / 64.f) + 1e-5f);
        float* orow = out + (size_t)(r0 + r) * 64;
        orow[lane]      = d0 * inv * ln2g[lane] + ln2b[lane];
        orow[lane + 32] = d1 * inv * ln2g[lane + 32] + ln2b[lane + 32];
    }
}

// ---------------- launch ---------------------------------------------------------
extern "C" void kernel_launch(void* const* d_in, const int* in_sizes, int n_in,
                              void* d_out, int out_size)
{
    (void)in_sizes; (void)n_in; (void)out_size;
    const float* x       = (const float*)d_in[0];
    const float* sq_w    = (const float*)d_in[1];
    const float* bn_g    = (const float*)d_in[2];
    const float* bn_b    = (const float*)d_in[3];
    const float* dw_w    = (const float*)d_in[4];
    const float* ex_w    = (const float*)d_in[5];
    const float* pos_emb = (const float*)d_in[6];
    const float* wq      = (const float*)d_in[7];
    const float* bq      = (const float*)d_in[8];
    const float* wk      = (const float*)d_in[9];
    const float* bk      = (const float*)d_in[10];
    const float* wv      = (const float*)d_in[11];
    const float* wl      = (const float*)d_in[12];
    const float* uni_w   = (const float*)d_in[13];
    const float* uni_b   = (const float*)d_in[14];
    const float* ln1_g   = (const float*)d_in[15];
    const float* ln1_b   = (const float*)d_in[16];
    const float* ln2_g   = (const float*)d_in[17];
    const float* ln2_b   = (const float*)d_in[18];
    const float* ff_w1   = (const float*)d_in[19];
    const float* ff_b1   = (const float*)d_in[20];
    const float* ff_w2   = (const float*)d_in[21];
    const float* ff_b2   = (const float*)d_in[22];
    float* out = (float*)d_out;

    const int CONV_SMEM  = (2 * 128 * 36 + 2 * 32 * 68) * 4;   // 54272
    const int FLASH_SMEM = (4 * 64 * 68) * 4;                  // 69632
    cudaFuncSetAttribute(convgemm_kernel<0>, cudaFuncAttributeMaxDynamicSharedMemorySize, CONV_SMEM);
    cudaFuncSetAttribute(convgemm_kernel<1>, cudaFuncAttributeMaxDynamicSharedMemorySize, CONV_SMEM);
    cudaFuncSetAttribute(flash_mma_kernel,   cudaFuncAttributeMaxDynamicSharedMemorySize, FLASH_SMEM);

    x3_kernel<<<512, 256>>>(x, sq_w, bn_g, bn_b);
    xin_kernel<<<dim3(4, 8), 256>>>(x, dw_w, ex_w, pos_emb);

    prep_wqk_kernel<<<1280, 256>>>(wq, wk);
    prep_wvl_kernel<<<512, 256>>>(wv, wl, uni_w);

    convgemm_kernel<0><<<dim3(32, 16), 256, CONV_SMEM>>>(bq, bk);
    convgemm_kernel<1><<<dim3(32, 16), 256, CONV_SMEM>>>(nullptr, nullptr);

    flash_mma_kernel<<<dim3(32, 8), 256, FLASH_SMEM>>>();
    local_attn_kernel<<<dim3(32, 16), 256>>>();

    unigemm_kernel<<<dim3(32, 4), 256>>>();

    ffln_kernel<<<256, 256>>>(uni_b, ln1_g, ln1_b, ln2_g, ln2_b,
                              ff_w1, ff_b1, ff_w2, ff_b2, out);
}

// round 4
// speedup vs baseline: 2.5740x; 1.3178x over previous
#include <cuda_runtime.h>
#include <math.h>
#include <stdint.h>

// Problem constants (fixed by setup_inputs)
#define BATCH 4
#define TLEN  1024
#define KD    64
#define HNUM  8
#define R32   32
#define NSEQ  32      // BATCH*HNUM
#define MROWS 4096    // BATCH*TLEN

// ---------------- scratch (static device globals; no allocation) --------------
__device__ float g_xin[BATCH * TLEN * KD];          // tf32-exact
__device__ float g_WB[320 * 1024];                  // tap-major reordered wq|wk, tf32-exact
__device__ float g_WB2[64 * 1024];                  // wv|wl transposed, tf32-exact
__device__ float g_WU[1024 * 64];                   // uni_w, tf32-exact
__device__ float g_q[NSEQ * TLEN * KD];             // tf32-exact
__device__ float g_k[NSEQ * TLEN * KD];
__device__ float g_v[NSEQ * TLEN * KD];
__device__ float g_l[NSEQ * TLEN * KD];
__device__ float g_og[NSEQ * TLEN * KD];
__device__ float g_ol[NSEQ * TLEN * KD];
__device__ float g_part[4 * MROWS * KD];            // uni GEMM K-split partials

__device__ __forceinline__ float sigmoid_exact(float x) { return 1.f / (1.f + expf(-x)); }
__device__ __forceinline__ float sigmoid_fast(float x) {
    float t;
    asm("tanh.approx.f32 %0, %1;" : "=f"(t) : "f"(0.5f * x));
    return 0.5f * t + 0.5f;
}
__device__ __forceinline__ float silu_fast(float x) { return x * sigmoid_fast(x); }

// round f32 -> nearest tf32 (result is a valid f32 with low mantissa zeroed)
__device__ __forceinline__ float tf32r(float x) {
    uint32_t u;
    asm("cvt.rna.tf32.f32 %0, %1;" : "=r"(u) : "f"(x));
    return __uint_as_float(u);
}

__device__ __forceinline__ void mma8(float* c,
                                     uint32_t a0, uint32_t a1, uint32_t a2, uint32_t a3,
                                     uint32_t b0, uint32_t b1) {
    asm volatile(
        "mma.sync.aligned.m16n8k8.row.col.f32.tf32.tf32.f32 "
        "{%0,%1,%2,%3}, {%4,%5,%6,%7}, {%8,%9}, {%0,%1,%2,%3};"
        : "+f"(c[0]), "+f"(c[1]), "+f"(c[2]), "+f"(c[3])
        : "r"(a0), "r"(a1), "r"(a2), "r"(a3), "r"(b0), "r"(b1));
}

__device__ __forceinline__ void cp16(uint32_t dst, const void* src) {
    asm volatile("cp.async.ca.shared.global [%0], [%1], 16;" :: "r"(dst), "l"(src) : "memory");
}
__device__ __forceinline__ void cp16p(uint32_t dst, const void* src, int sz) {
    asm volatile("cp.async.ca.shared.global [%0], [%1], 16, %2;" :: "r"(dst), "l"(src), "r"(sz) : "memory");
}
#define CPCOMMIT() asm volatile("cp.async.commit_group;" ::: "memory")
#define CPWAIT0()  asm volatile("cp.async.wait_group 0;" ::: "memory")
#define CPWAIT1()  asm volatile("cp.async.wait_group 1;" ::: "memory")

// ================= fused action + pos_emb -> xin (tf32-exact) ==================
// grid (4, 32): block = (batch bi, 32-pos chunk). All math in smem, coalesced.
__global__ __launch_bounds__(256) void fused_xin_kernel(
    const float* __restrict__ x, const float* __restrict__ sq_w,
    const float* __restrict__ bn_g, const float* __restrict__ bn_b,
    const float* __restrict__ dw_w, const float* __restrict__ ex_w,
    const float* __restrict__ pos_emb)
{
    __shared__ float xs[34][68];     // x rows t0..t0+33 (padded)
    __shared__ float x3s[34][36];    // x3[j][r] (padded)
    __shared__ float xp3[32][32];    // diff'd gate input [j][r]
    __shared__ float sqT[64][32];    // sq_w transposed [c][r]
    __shared__ float exT[32][64];    // ex_w transposed [r][c]
    __shared__ float bng_s[32], bnb_s[32];

    int bi = blockIdx.x;
    int t0 = blockIdx.y * 32;
    int tid = threadIdx.x;
    int nrows = min(34, TLEN - t0);

    // load x tile (coalesced float4)
    for (int i = tid; i < nrows * 16; i += 256) {
        int row = i >> 4, c4 = (i & 15) << 2;
        *(float4*)&xs[row][c4] = *(const float4*)&x[((size_t)bi * TLEN + t0 + row) * KD + c4];
    }
    // sq_w[r][c] -> sqT[c][r]
    for (int i = tid; i < 2048; i += 256) { int r = i >> 6, c = i & 63; sqT[c][r] = sq_w[i]; }
    // ex_w[c][r] -> exT[r][c]
    for (int i = tid; i < 2048; i += 256) { int c = i >> 5, r = i & 31; exT[r][c] = ex_w[i]; }
    if (tid < 32) { bng_s[tid] = bn_g[tid] * 0.9999950000374997f; bnb_s[tid] = bn_b[tid]; }
    __syncthreads();

    // phase 2: x3s[j][r] = bn(x row j . sq col r)
    {
        int j = tid >> 2, rg = (tid & 3) << 3;
        if (j < nrows) {
            float acc[8];
#pragma unroll
            for (int i = 0; i < 8; ++i) acc[i] = 0.f;
#pragma unroll
            for (int c4 = 0; c4 < 64; c4 += 4) {
                float4 xv = *(const float4*)&xs[j][c4];
#pragma unroll
                for (int t = 0; t < 4; ++t) {
                    float xc = (t == 0) ? xv.x : (t == 1) ? xv.y : (t == 2) ? xv.z : xv.w;
                    float4 s0 = *(const float4*)&sqT[c4 + t][rg];
                    float4 s1 = *(const float4*)&sqT[c4 + t][rg + 4];
                    acc[0] += xc * s0.x; acc[1] += xc * s0.y;
                    acc[2] += xc * s0.z; acc[3] += xc * s0.w;
                    acc[4] += xc * s1.x; acc[5] += xc * s1.y;
                    acc[6] += xc * s1.z; acc[7] += xc * s1.w;
                }
            }
#pragma unroll
            for (int i = 0; i < 8; ++i)
                x3s[j][rg + i] = acc[i] * bng_s[rg + i] + bnb_s[rg + i];
        }
    }
    __syncthreads();

    // phase 3: depthwise diff  xp3[j][r]
    for (int idx = tid; idx < 32 * 32; idx += 256) {
        int r = idx & 31, jj = idx >> 5;
        int pos = t0 + jj;
        float base = x3s[jj][r];
        float v;
        if (pos == TLEN - 1) {
            v = base;
        } else {
            float d0 = dw_w[r * 3 + 0], d1 = dw_w[r * 3 + 1], d2 = dw_w[r * 3 + 2];
            float a = base * d0 + x3s[jj + 1][r] * d1 +
                      ((pos + 2 < TLEN) ? x3s[jj + 2][r] * d2 : 0.f);
            v = a - base;
        }
        xp3[jj][r] = v;
    }
    __syncthreads();

    // phase 4: gate + pos_emb, write xin (tf32-exact)
    for (int idx = tid; idx < 32 * 64; idx += 256) {
        int c = idx & 63, j = idx >> 6;
        int pos = t0 + j;
        float gsum = 0.f;
#pragma unroll
        for (int r = 0; r < R32; ++r) gsum += xp3[j][r] * exT[r][c];
        float sig = sigmoid_exact(gsum);
        size_t off = ((size_t)bi * TLEN + pos) * KD + c;
        g_xin[off] = tf32r(xs[j][c] * sig + pos_emb[pos * KD + c]);
    }
}

// ---------------- weight prep (reorder + tf32 round, single kernel) ------------
__global__ __launch_bounds__(256) void prep_w_kernel(
    const float* __restrict__ wq, const float* __restrict__ wk,
    const float* __restrict__ wv, const float* __restrict__ wl,
    const float* __restrict__ uni_w)
{
    int idx = blockIdx.x * 256 + threadIdx.x;
    if (idx < 320 * 1024) {
        int n = idx & 1023, kcol = idx >> 10;
        int mm = kcol >> 6, c = kcol & 63;
        float w = (n < 512) ? wq[n * 320 + c * 5 + mm] : wk[(n - 512) * 320 + c * 5 + mm];
        g_WB[idx] = tf32r(w);
    } else if (idx < 320 * 1024 + 65536) {
        int j = idx - 320 * 1024;
        int n = j & 1023, c = j >> 10;
        g_WB2[j] = tf32r((n < 512) ? wv[n * 64 + c] : wl[(n - 512) * 64 + c]);
    } else if (idx < 320 * 1024 + 131072) {
        int j = idx - (320 * 1024 + 65536);
        g_WU[j] = tf32r(uni_w[j]);
    }
}

// ---------------- conv GEMMs (tf32 mma, cp.async dbl-buffered, mode=blockIdx.z) --
// mode 0: QK conv (K=320 tap-major, im2col fused into A loads, B=g_WB)
// mode 1: VL conv (K=64, A=g_xin direct, B=g_WB2)
__global__ __launch_bounds__(256) void convgemm_kernel(
    const float* __restrict__ bias0, const float* __restrict__ bias1)
{
    int mode = blockIdx.z;
    const int NSTAGE = (mode == 0) ? 10 : 2;
    extern __shared__ float sm[];
    float* As = sm;                   // [2][128][36]
    float* Bs = sm + 2 * 128 * 36;    // [2][32][68]
    const float* __restrict__ Bg = (mode == 0) ? g_WB : g_WB2;

    int tid = threadIdx.x, lane = tid & 31, wid = tid >> 5;
    int wm = wid & 3, wn = wid >> 2, gi = lane >> 2, ci = lane & 3;
    int m0 = blockIdx.x * 128, n0 = blockIdx.y * 64;
    int bi = m0 >> 10, tibase = m0 & 1023;
    uint32_t sb = (uint32_t)__cvta_generic_to_shared(sm);
    uint32_t a_sb = sb, b_sb = sb + 2 * 128 * 36 * 4;

    auto issue_stage = [&](int s_, int buf_) {
        int mm_ = (mode == 0) ? (s_ >> 1) : 0;
        int c0_ = (mode == 0) ? ((s_ & 1) << 5) : (s_ << 5);
        int sh_ = (mode == 0) ? (2 * mm_ - 8) : 0;
#pragma unroll
        for (int i_ = 0; i_ < 4; ++i_) {
            int f4 = tid + i_ * 256;
            int row = f4 >> 3, c4 = (f4 & 7) << 2;
            int tsrc = tibase + row + sh_;
            const float* srcp = g_xin + ((size_t)(bi << 10) + tsrc) * 64 + c0_ + c4;
            uint32_t dstp = a_sb + (uint32_t)((buf_ * 4608 + row * 36 + c4) * 4);
            cp16p(dstp, srcp, (tsrc >= 0) ? 16 : 0);
        }
#pragma unroll
        for (int i_ = 0; i_ < 2; ++i_) {
            int f4 = tid + i_ * 256;
            int row = f4 >> 4, c4 = (f4 & 15) << 2;
            const float* srcp = Bg + (size_t)(s_ * 32 + row) * 1024 + n0 + c4;
            uint32_t dstp = b_sb + (uint32_t)((buf_ * 2176 + row * 68 + c4) * 4);
            cp16(dstp, srcp);
        }
        CPCOMMIT();
    };

    float acc[2][4][4];
#pragma unroll
    for (int a = 0; a < 2; ++a)
#pragma unroll
        for (int b = 0; b < 4; ++b)
#pragma unroll
            for (int c = 0; c < 4; ++c) acc[a][b][c] = 0.f;

    issue_stage(0, 0);
    for (int s = 0; s < NSTAGE; ++s) {
        if (s + 1 < NSTAGE) { issue_stage(s + 1, (s + 1) & 1); CPWAIT1(); }
        else CPWAIT0();
        __syncthreads();
        const float* Ab = As + (s & 1) * 4608;
        const float* Bb = Bs + (s & 1) * 2176;
#pragma unroll
        for (int kk = 0; kk < 4; ++kk) {
            int k = kk * 8;
            uint32_t af[2][4];
#pragma unroll
            for (int mi = 0; mi < 2; ++mi) {
                int r = wm * 32 + mi * 16 + gi;
                af[mi][0] = __float_as_uint(Ab[r * 36 + k + ci]);
                af[mi][1] = __float_as_uint(Ab[(r + 8) * 36 + k + ci]);
                af[mi][2] = __float_as_uint(Ab[r * 36 + k + ci + 4]);
                af[mi][3] = __float_as_uint(Ab[(r + 8) * 36 + k + ci + 4]);
            }
            uint32_t bf[4][2];
#pragma unroll
            for (int ni = 0; ni < 4; ++ni) {
                int n = wn * 32 + ni * 8 + gi;
                bf[ni][0] = __float_as_uint(Bb[(k + ci) * 68 + n]);
                bf[ni][1] = __float_as_uint(Bb[(k + ci + 4) * 68 + n]);
            }
#pragma unroll
            for (int mi = 0; mi < 2; ++mi)
#pragma unroll
                for (int ni = 0; ni < 4; ++ni)
                    mma8(acc[mi][ni], af[mi][0], af[mi][1], af[mi][2], af[mi][3],
                         bf[ni][0], bf[ni][1]);
        }
        __syncthreads();
    }

#pragma unroll
    for (int mi = 0; mi < 2; ++mi)
#pragma unroll
        for (int ni = 0; ni < 4; ++ni)
#pragma unroll
            for (int j = 0; j < 4; ++j) {
                int m = m0 + wm * 32 + mi * 16 + gi + ((j >= 2) ? 8 : 0);
                int n = n0 + wn * 32 + ni * 8 + 2 * ci + (j & 1);
                float v = acc[mi][ni][j];
                int o = n & 511, ki = o >> 3, h = o & 7;
                int bb = m >> 10, ti = m & 1023;
                int gg = bb * 8 + (ti >> 7);
                int tj = ((ti & 127) << 3) | h;
                float s;
                float* dst;
                if (mode == 0) {
                    float bias = (n < 512) ? bias0[n] : bias1[n - 512];
                    s = silu_fast(v + bias) * 0.35355339059327373f;  // / 64^0.25
                    dst = (n < 512) ? g_q : g_k;
                } else {
                    s = silu_fast(v);
                    dst = (n < 512) ? g_v : g_l;
                }
                dst[((size_t)gg * TLEN + tj) * KD + ki] = tf32r(s);
            }
}

// ---------------- flash attention (tf32 mma, mirrored q-tile pairing) ----------
// block (g, p): warps 0-3 handle q-tile qa=p, warps 4-7 q-tile qb=15-p.
// Loop k-tiles 0..qb; equal MMA work (17 warp-tile-quads) in every block.
__global__ __launch_bounds__(256) void flash_mma_kernel()
{
    extern __shared__ float sm[];   // Ks[2][64][68] | Vs[2][64][68]
    int g  = blockIdx.x;
    int p  = blockIdx.y;
    int qa = p, qb = 15 - p;
    int tid = threadIdx.x, lane = tid & 31, wid = tid >> 5;
    int gi = lane >> 2, ci = lane & 3;
    uint32_t sb = (uint32_t)__cvta_generic_to_shared(sm);

    int myqt   = (wid < 4) ? qa : qb;
    int qbase  = myqt * 64 + (wid & 3) * 16;
    int r0 = qbase + gi;

    const float* Qg = g_q + (size_t)g * (TLEN * KD);
    uint32_t qf[8][4];
#pragma unroll
    for (int kk = 0; kk < 8; ++kk) {
        int c = kk * 8 + ci;
        qf[kk][0] = __float_as_uint(Qg[(size_t)r0 * KD + c]);
        qf[kk][1] = __float_as_uint(Qg[(size_t)(r0 + 8) * KD + c]);
        qf[kk][2] = __float_as_uint(Qg[(size_t)r0 * KD + c + 4]);
        qf[kk][3] = __float_as_uint(Qg[(size_t)(r0 + 8) * KD + c + 4]);
    }

    float o[8][4];
#pragma unroll
    for (int a = 0; a < 8; ++a)
#pragma unroll
        for (int b = 0; b < 4; ++b) o[a][b] = 0.f;
    float m0v = -1e30f, m1v = -1e30f, l0 = 0.f, l1 = 0.f;

    int src_lo = (lane & ~3) | (ci >> 1);
    int src_hi = src_lo + 2;
    bool odd = ci & 1;

    const float* Kg0 = g_k + (size_t)g * (TLEN * KD);
    const float* Vg0 = g_v + (size_t)g * (TLEN * KD);
    int nkt = qb + 1;

#define FLASH_ISSUE(kt_, buf_)                                                       \
    do {                                                                             \
        const float* Kg = Kg0 + (size_t)(kt_) * 64 * 64;                             \
        const float* Vg = Vg0 + (size_t)(kt_) * 64 * 64;                             \
        _Pragma("unroll")                                                            \
        for (int i_ = 0; i_ < 4; ++i_) {                                             \
            int f4 = tid + i_ * 256;                                                 \
            int row = f4 >> 4, c4 = (f4 & 15) << 2;                                  \
            uint32_t kd = sb + (uint32_t)((((buf_) * 4352) + row * 68 + c4) * 4);    \
            uint32_t vd = sb + (uint32_t)(((8704 + (buf_) * 4352) + row * 68 + c4) * 4); \
            cp16(kd, Kg + row * 64 + c4);                                            \
            cp16(vd, Vg + row * 64 + c4);                                            \
        }                                                                            \
        CPCOMMIT();                                                                  \
    } while (0)

    FLASH_ISSUE(0, 0);
    for (int kt = 0; kt < nkt; ++kt) {
        int k0 = kt * 64;
        if (kt + 1 < nkt) { FLASH_ISSUE(kt + 1, (kt + 1) & 1); CPWAIT1(); }
        else CPWAIT0();
        __syncthreads();
        const float* Ks = sm + (kt & 1) * 4352;
        const float* Vs = sm + 8704 + (kt & 1) * 4352;
        if (k0 <= qbase + 15) {
            // S = Q K^T (16 x 64 per warp)
            float s[8][4];
#pragma unroll
            for (int ni = 0; ni < 8; ++ni) {
                s[ni][0] = s[ni][1] = s[ni][2] = s[ni][3] = 0.f;
                int key = ni * 8 + gi;
#pragma unroll
                for (int kk = 0; kk < 8; ++kk) {
                    uint32_t b0 = __float_as_uint(Ks[key * 68 + kk * 8 + ci]);
                    uint32_t b1 = __float_as_uint(Ks[key * 68 + kk * 8 + ci + 4]);
                    mma8(s[ni], qf[kk][0], qf[kk][1], qf[kk][2], qf[kk][3], b0, b1);
                }
            }
            if (k0 + 63 > qbase) {   // diagonal tile: causal mask
#pragma unroll
                for (int ni = 0; ni < 8; ++ni)
#pragma unroll
                    for (int j = 0; j < 4; ++j) {
                        int col = k0 + ni * 8 + 2 * ci + (j & 1);
                        int row = r0 + ((j >= 2) ? 8 : 0);
                        if (col > row) s[ni][j] = -1e30f;
                    }
            }
            // online softmax
            float mx0 = -1e30f, mx1 = -1e30f;
#pragma unroll
            for (int ni = 0; ni < 8; ++ni) {
                mx0 = fmaxf(mx0, fmaxf(s[ni][0], s[ni][1]));
                mx1 = fmaxf(mx1, fmaxf(s[ni][2], s[ni][3]));
            }
            mx0 = fmaxf(mx0, __shfl_xor_sync(0xffffffffu, mx0, 1));
            mx0 = fmaxf(mx0, __shfl_xor_sync(0xffffffffu, mx0, 2));
            mx1 = fmaxf(mx1, __shfl_xor_sync(0xffffffffu, mx1, 1));
            mx1 = fmaxf(mx1, __shfl_xor_sync(0xffffffffu, mx1, 2));
            float m0n = fmaxf(m0v, mx0), m1n = fmaxf(m1v, mx1);
            float corr0 = __expf(m0v - m0n), corr1 = __expf(m1v - m1n);

            float sum0 = 0.f, sum1 = 0.f;
#pragma unroll
            for (int ni = 0; ni < 8; ++ni) {
                s[ni][0] = tf32r(__expf(s[ni][0] - m0n));
                s[ni][1] = tf32r(__expf(s[ni][1] - m0n));
                s[ni][2] = tf32r(__expf(s[ni][2] - m1n));
                s[ni][3] = tf32r(__expf(s[ni][3] - m1n));
                sum0 += s[ni][0] + s[ni][1];
                sum1 += s[ni][2] + s[ni][3];
            }
            sum0 += __shfl_xor_sync(0xffffffffu, sum0, 1);
            sum0 += __shfl_xor_sync(0xffffffffu, sum0, 2);
            sum1 += __shfl_xor_sync(0xffffffffu, sum1, 1);
            sum1 += __shfl_xor_sync(0xffffffffu, sum1, 2);
            l0 = l0 * corr0 + sum0;
            l1 = l1 * corr1 + sum1;
            m0v = m0n; m1v = m1n;
#pragma unroll
            for (int nd = 0; nd < 8; ++nd) {
                o[nd][0] *= corr0; o[nd][1] *= corr0;
                o[nd][2] *= corr1; o[nd][3] *= corr1;
            }
            // P @ V with register relayout
#pragma unroll
            for (int kg = 0; kg < 8; ++kg) {
                float v00 = __shfl_sync(0xffffffffu, s[kg][0], src_lo);
                float v01 = __shfl_sync(0xffffffffu, s[kg][1], src_lo);
                float v10 = __shfl_sync(0xffffffffu, s[kg][2], src_lo);
                float v11 = __shfl_sync(0xffffffffu, s[kg][3], src_lo);
                float w00 = __shfl_sync(0xffffffffu, s[kg][0], src_hi);
                float w01 = __shfl_sync(0xffffffffu, s[kg][1], src_hi);
                float w10 = __shfl_sync(0xffffffffu, s[kg][2], src_hi);
                float w11 = __shfl_sync(0xffffffffu, s[kg][3], src_hi);
                uint32_t a0 = __float_as_uint(odd ? v01 : v00);
                uint32_t a1 = __float_as_uint(odd ? v11 : v10);
                uint32_t a2 = __float_as_uint(odd ? w01 : w00);
                uint32_t a3 = __float_as_uint(odd ? w11 : w10);
                int key = kg * 8 + ci;
#pragma unroll
                for (int nd = 0; nd < 8; ++nd) {
                    uint32_t b0 = __float_as_uint(Vs[key * 68 + nd * 8 + gi]);
                    uint32_t b1 = __float_as_uint(Vs[(key + 4) * 68 + nd * 8 + gi]);
                    mma8(o[nd], a0, a1, a2, a3, b0, b1);
                }
            }
        }
        __syncthreads();
    }
#undef FLASH_ISSUE

    float inv0 = 1.f / l0, inv1 = 1.f / l1;
    float* Og = g_og + (size_t)g * (TLEN * KD);
#pragma unroll
    for (int nd = 0; nd < 8; ++nd) {
        int c = nd * 8 + 2 * ci;
        float2 t0; t0.x = o[nd][0] * inv0; t0.y = o[nd][1] * inv0;
        float2 t1; t1.x = o[nd][2] * inv1; t1.y = o[nd][3] * inv1;
        *(float2*)&Og[(size_t)r0 * KD + c] = t0;
        *(float2*)&Og[(size_t)(r0 + 8) * KD + c] = t1;
    }
}

// ---------------- local windowed causal attention ------------------------------
__global__ __launch_bounds__(256) void local_attn_kernel()
{
    int g = blockIdx.x;
    int tjbase = blockIdx.y * 64;
    int lane = threadIdx.x & 31;
    int w = threadIdx.x >> 5;
    const float* Lg = g_l + (size_t)g * (TLEN * KD);
    float* Og = g_ol + (size_t)g * (TLEN * KD);
    for (int qi = 0; qi < 8; ++qi) {
        int tj = tjbase + w * 8 + qi;
        float a0 = Lg[tj * 64 + lane];
        float a1 = Lg[tj * 64 + lane + 32];
        float s[6];
        float mx = -1e30f;
#pragma unroll
        for (int wv = 0; wv < 6; ++wv) {
            int tp = tj - 5 + wv;
            float sc = -1e30f;
            if (tp >= 0) {
                float p = a0 * Lg[tp * 64 + lane] + a1 * Lg[tp * 64 + lane + 32];
#pragma unroll
                for (int o = 16; o; o >>= 1) p += __shfl_xor_sync(0xffffffffu, p, o);
                sc = p * 0.125f;
            }
            s[wv] = sc;
            mx = fmaxf(mx, sc);
        }
        float den = 0.f, o0 = 0.f, o1 = 0.f;
#pragma unroll
        for (int wv = 0; wv < 6; ++wv) {
            int tp = tj - 5 + wv;
            if (tp >= 0) {
                float pp = expf(s[wv] - mx);
                den += pp;
                o0 += pp * Lg[tp * 64 + lane];
                o1 += pp * Lg[tp * 64 + lane + 32];
            }
        }
        float inv = 1.f / den;
        Og[tj * 64 + lane] = o0 * inv;
        Og[tj * 64 + lane + 32] = o1 * inv;
    }
}

// ---------------- uni projection: fused gating + K-split tf32 GEMM -------------
__global__ __launch_bounds__(256) void unigemm_kernel()
{
    __shared__ float As[128][36];
    __shared__ float Bs[32][68];
    int tid = threadIdx.x, lane = tid & 31, wid = tid >> 5;
    int wm = wid & 3, wn = wid >> 2, gi = lane >> 2, ci = lane & 3;
    int m0 = blockIdx.x * 128;
    int kz = blockIdx.y;
    int bi = m0 >> 10, tib = m0 & 1023;
    uint32_t b_sb = (uint32_t)__cvta_generic_to_shared(&Bs[0][0]);

    float acc[2][4][4];
#pragma unroll
    for (int a = 0; a < 2; ++a)
#pragma unroll
        for (int b = 0; b < 4; ++b)
#pragma unroll
            for (int c = 0; c < 4; ++c) acc[a][b][c] = 0.f;

    for (int s = 0; s < 8; ++s) {
        int k0 = kz * 256 + s * 32;
        int ch = k0 >> 6, ki0 = k0 & 63;
        int h2 = ch & 7;
        bool lohalf = ch < 8;
        const float* Og = g_og + (size_t)(bi * 8 + h2) * (TLEN * KD);
        const float* Lg = g_ol + (size_t)(bi * 8 + h2) * (TLEN * KD);
        __syncthreads();
#pragma unroll
        for (int i = 0; i < 2; ++i) {
            int f4 = tid + i * 256;
            int row = f4 >> 4, c4 = (f4 & 15) << 2;
            cp16(b_sb + (uint32_t)((row * 68 + c4) * 4), g_WU + (size_t)(k0 + row) * 64 + c4);
        }
        CPCOMMIT();
#pragma unroll
        for (int i = 0; i < 4; ++i) {
            int f4 = tid + i * 256;
            int row = f4 >> 3, c4 = (f4 & 7) << 2;
            int ti2 = tib + row;
            const float4 o4 = *(const float4*)(Og + (size_t)ti2 * 64 + ki0 + c4);
            const float4 l4 = *(const float4*)(Lg + (size_t)ti2 * 64 + ki0 + c4);
            float g0 = sigmoid_fast(o4.x), g1 = sigmoid_fast(o4.y);
            float g2 = sigmoid_fast(o4.z), g3 = sigmoid_fast(o4.w);
            float r0 = lohalf ? (1.f - g0) * l4.x : g0 * o4.x;
            float r1 = lohalf ? (1.f - g1) * l4.y : g1 * o4.y;
            float r2 = lohalf ? (1.f - g2) * l4.z : g2 * o4.z;
            float r3 = lohalf ? (1.f - g3) * l4.w : g3 * o4.w;
            As[row][c4 + 0] = tf32r(r0);
            As[row][c4 + 1] = tf32r(r1);
            As[row][c4 + 2] = tf32r(r2);
            As[row][c4 + 3] = tf32r(r3);
        }
        CPWAIT0();
        __syncthreads();
#pragma unroll
        for (int kk = 0; kk < 4; ++kk) {
            int k = kk * 8;
            uint32_t af[2][4];
#pragma unroll
            for (int mi = 0; mi < 2; ++mi) {
                int r = wm * 32 + mi * 16 + gi;
                af[mi][0] = __float_as_uint(As[r][k + ci]);
                af[mi][1] = __float_as_uint(As[r + 8][k + ci]);
                af[mi][2] = __float_as_uint(As[r][k + ci + 4]);
                af[mi][3] = __float_as_uint(As[r + 8][k + ci + 4]);
            }
            uint32_t bf[4][2];
#pragma unroll
            for (int ni = 0; ni < 4; ++ni) {
                int n = wn * 32 + ni * 8 + gi;
                bf[ni][0] = __float_as_uint(Bs[k + ci][n]);
                bf[ni][1] = __float_as_uint(Bs[k + ci + 4][n]);
            }
#pragma unroll
            for (int mi = 0; mi < 2; ++mi)
#pragma unroll
                for (int ni = 0; ni < 4; ++ni)
                    mma8(acc[mi][ni], af[mi][0], af[mi][1], af[mi][2], af[mi][3],
                         bf[ni][0], bf[ni][1]);
        }
    }

    float* P = g_part + ((size_t)kz * MROWS + m0) * 64;
#pragma unroll
    for (int mi = 0; mi < 2; ++mi)
#pragma unroll
        for (int ni = 0; ni < 4; ++ni)
#pragma unroll
            for (int j = 0; j < 4; j += 2) {
                int mrow = wm * 32 + mi * 16 + gi + ((j >= 2) ? 8 : 0);
                int n = wn * 32 + ni * 8 + 2 * ci;
                float2 t; t.x = acc[mi][ni][j]; t.y = acc[mi][ni][j + 1];
                *(float2*)&P[(size_t)mrow * 64 + n] = t;
            }
}

// ---------------- partial-reduce + silu + residual -> LN1 -> FF -> LN2 ---------
__global__ __launch_bounds__(256) void ffln_kernel(
    const float* __restrict__ uni_b,
    const float* __restrict__ ln1g, const float* __restrict__ ln1b,
    const float* __restrict__ ln2g, const float* __restrict__ ln2b,
    const float* __restrict__ w1, const float* __restrict__ b1,
    const float* __restrict__ w2, const float* __restrict__ b2,
    float* __restrict__ out)
{
    const int R = 16;
    __shared__ float yl[R][64];
    __shared__ float hs[R][256];
    __shared__ float fs[R][64];
    int r0 = blockIdx.x * R;
    int tid = threadIdx.x;
    int lane = tid & 31, w = tid >> 5;

    for (int rr = 0; rr < 2; ++rr) {
        int r = w * 2 + rr;
        size_t rg = (size_t)(r0 + r) * 64;
        float v0 = g_part[rg + lane] + g_part[(size_t)MROWS * 64 + rg + lane] +
                   g_part[(size_t)MROWS * 128 + rg + lane] + g_part[(size_t)MROWS * 192 + rg + lane];
        float v1 = g_part[rg + lane + 32] + g_part[(size_t)MROWS * 64 + rg + lane + 32] +
                   g_part[(size_t)MROWS * 128 + rg + lane + 32] + g_part[(size_t)MROWS * 192 + rg + lane + 32];
        v0 = silu_fast(v0 + uni_b[lane]) + g_xin[rg + lane];
        v1 = silu_fast(v1 + uni_b[lane + 32]) + g_xin[rg + lane + 32];
        float sm = v0 + v1;
#pragma unroll
        for (int o = 16; o; o >>= 1) sm += __shfl_xor_sync(0xffffffffu, sm, o);
        float mean = sm * (1.f / 64.f);
        float d0 = v0 - mean, d1 = v1 - mean;
        float vs = d0 * d0 + d1 * d1;
#pragma unroll
        for (int o = 16; o; o >>= 1) vs += __shfl_xor_sync(0xffffffffu, vs, o);
        float inv = rsqrtf(vs * (1.f / 64.f) + 1e-5f);
        yl[r][lane]      = d0 * inv * ln1g[lane] + ln1b[lane];
        yl[r][lane + 32] = d1 * inv * ln1g[lane + 32] + ln1b[lane + 32];
    }
    __syncthreads();

    {
        float acc[R];
#pragma unroll
        for (int r = 0; r < R; ++r) acc[r] = b1[tid];
        for (int c = 0; c < 64; ++c) {
            float wv = w1[c * 256 + tid];
#pragma unroll
            for (int r = 0; r < R; ++r) acc[r] += yl[r][c] * wv;
        }
#pragma unroll
        for (int r = 0; r < R; ++r) hs[r][tid] = fmaxf(acc[r], 0.f);
    }
    __syncthreads();

    {
        int j2 = tid & 63, rg = tid >> 6;
#pragma unroll
        for (int rr = 0; rr < 4; ++rr) {
            int r = rg * 4 + rr;
            float a = b2[j2];
            for (int c = 0; c < 256; ++c) a += hs[r][c] * w2[c * 64 + j2];
            fs[r][j2] = a + yl[r][j2];
        }
    }
    __syncthreads();

    for (int rr = 0; rr < 2; ++rr) {
        int r = w * 2 + rr;
        float v0 = fs[r][lane], v1 = fs[r][lane + 32];
        float sm = v0 + v1;
#pragma unroll
        for (int o = 16; o; o >>= 1) sm += __shfl_xor_sync(0xffffffffu, sm, o);
        float mean = sm * (1.f / 64.f);
        float d0 = v0 - mean, d1 = v1 - mean;
        float vs = d0 * d0 + d1 * d1;
#pragma unroll
        for (int o = 16; o; o >>= 1) vs += __shfl_xor_sync(0xffffffffu, vs, o);
        float inv = rsqrtf(vs * (1.f / 64.f) + 1e-5f);
        float* orow = out + (size_t)(r0 + r) * 64;
        orow[lane]      = d0 * inv * ln2g[lane] + ln2b[lane];
        orow[lane + 32] = d1 * inv * ln2g[lane + 32] + ln2b[lane + 32];
    }
}

// ---------------- launch ---------------------------------------------------------
extern "C" void kernel_launch(void* const* d_in, const int* in_sizes, int n_in,
                              void* d_out, int out_size)
{
    (void)in_sizes; (void)n_in; (void)out_size;
    const float* x       = (const float*)d_in[0];
    const float* sq_w    = (const float*)d_in[1];
    const float* bn_g    = (const float*)d_in[2];
    const float* bn_b    = (const float*)d_in[3];
    const float* dw_w    = (const float*)d_in[4];
    const float* ex_w    = (const float*)d_in[5];
    const float* pos_emb = (const float*)d_in[6];
    const float* wq      = (const float*)d_in[7];
    const float* bq      = (const float*)d_in[8];
    const float* wk      = (const float*)d_in[9];
    const float* bk      = (const float*)d_in[10];
    const float* wv      = (const float*)d_in[11];
    const float* wl      = (const float*)d_in[12];
    const float* uni_w   = (const float*)d_in[13];
    const float* uni_b   = (const float*)d_in[14];
    const float* ln1_g   = (const float*)d_in[15];
    const float* ln1_b   = (const float*)d_in[16];
    const float* ln2_g   = (const float*)d_in[17];
    const float* ln2_b   = (const float*)d_in[18];
    const float* ff_w1   = (const float*)d_in[19];
    const float* ff_b1   = (const float*)d_in[20];
    const float* ff_w2   = (const float*)d_in[21];
    const float* ff_b2   = (const float*)d_in[22];
    float* out = (float*)d_out;

    const int CONV_SMEM  = (2 * 128 * 36 + 2 * 32 * 68) * 4;   // 54272
    const int FLASH_SMEM = (4 * 64 * 68) * 4;                  // 69632
    cudaFuncSetAttribute(convgemm_kernel, cudaFuncAttributeMaxDynamicSharedMemorySize, CONV_SMEM);
    cudaFuncSetAttribute(flash_mma_kernel, cudaFuncAttributeMaxDynamicSharedMemorySize, FLASH_SMEM);

    fused_xin_kernel<<<dim3(4, 32), 256>>>(x, sq_w, bn_g, bn_b, dw_w, ex_w, pos_emb);
    prep_w_kernel<<<1792, 256>>>(wq, wk, wv, wl, uni_w);

    convgemm_kernel<<<dim3(32, 16, 2), 256, CONV_SMEM>>>(bq, bk);

    flash_mma_kernel<<<dim3(32, 8), 256, FLASH_SMEM>>>();   // launch index 3 -> ncu target
    local_attn_kernel<<<dim3(32, 16), 256>>>();

    unigemm_kernel<<<dim3(32, 4), 256>>>();

    ffln_kernel<<<256, 256>>>(uni_b, ln1_g, ln1_b, ln2_g, ln2_b,
                              ff_w1, ff_b1, ff_w2, ff_b2, out);
}

// round 5
// speedup vs baseline: 2.7306x; 1.0608x over previous
#include <cuda_runtime.h>
#include <math.h>
#include <stdint.h>

// Problem constants (fixed by setup_inputs)
#define BATCH 4
#define TLEN  1024
#define KD    64
#define HNUM  8
#define R32   32
#define NSEQ  32      // BATCH*HNUM
#define MROWS 4096    // BATCH*TLEN

// ---------------- scratch (static device globals; no allocation) --------------
__device__ float g_xin[BATCH * TLEN * KD];          // tf32-exact
__device__ float g_WB[320 * 1024];                  // tap-major reordered wq|wk, tf32-exact
__device__ float g_WB2[64 * 1024];                  // wv|wl transposed, tf32-exact
__device__ float g_WU[1024 * 64];                   // uni_w, tf32-exact
__device__ float g_q[NSEQ * TLEN * KD];             // [g][t][p(d)] tf32-exact
__device__ float g_k[NSEQ * TLEN * KD];             // [g][t][p(d)]
__device__ float g_v[NSEQ * KD * TLEN];             // [g][d][t-tilewise p(key)]  (transposed!)
__device__ float g_l[NSEQ * TLEN * KD];             // natural
__device__ float g_og[NSEQ * TLEN * KD];
__device__ float g_ol[NSEQ * TLEN * KD];
__device__ float g_part[4 * MROWS * KD];            // uni GEMM K-split partials

__device__ __forceinline__ float sigmoid_exact(float x) { return 1.f / (1.f + expf(-x)); }
__device__ __forceinline__ float sigmoid_fast(float x) {
    float t;
    asm("tanh.approx.f32 %0, %1;" : "=f"(t) : "f"(0.5f * x));
    return 0.5f * t + 0.5f;
}
__device__ __forceinline__ float silu_fast(float x) { return x * sigmoid_fast(x); }

// round f32 -> nearest tf32 (result is a valid f32 with low mantissa zeroed)
__device__ __forceinline__ float tf32r(float x) {
    uint32_t u;
    asm("cvt.rna.tf32.f32 %0, %1;" : "=r"(u) : "f"(x));
    return __uint_as_float(u);
}

// fragment-vectorization permutation of a 64-long contraction dim.
// slot kappa = 8*kk + ci + 4*v  -> word = ci<<3 | b<<5 | r<<2 | u<<1 | v
// (kk = 4b+2r+u). Thread ci's 16 slots land in float4 chunks {2ci,2ci+1,2ci+8,2ci+9}.
__device__ __forceinline__ int pqk(int k) {
    return ((k & 3) << 3) | ((k >> 5) << 5) | (((k >> 4) & 1) << 2) |
           (((k >> 3) & 1) << 1) | ((k >> 2) & 1);
}

__device__ __forceinline__ void mma8(float* c,
                                     uint32_t a0, uint32_t a1, uint32_t a2, uint32_t a3,
                                     uint32_t b0, uint32_t b1) {
    asm volatile(
        "mma.sync.aligned.m16n8k8.row.col.f32.tf32.tf32.f32 "
        "{%0,%1,%2,%3}, {%4,%5,%6,%7}, {%8,%9}, {%0,%1,%2,%3};"
        : "+f"(c[0]), "+f"(c[1]), "+f"(c[2]), "+f"(c[3])
        : "r"(a0), "r"(a1), "r"(a2), "r"(a3), "r"(b0), "r"(b1));
}

__device__ __forceinline__ void cp16(uint32_t dst, const void* src) {
    asm volatile("cp.async.ca.shared.global [%0], [%1], 16;" :: "r"(dst), "l"(src) : "memory");
}
__device__ __forceinline__ void cp16p(uint32_t dst, const void* src, int sz) {
    asm volatile("cp.async.ca.shared.global [%0], [%1], 16, %2;" :: "r"(dst), "l"(src), "r"(sz) : "memory");
}
#define CPCOMMIT() asm volatile("cp.async.commit_group;" ::: "memory")
#define CPWAIT0()  asm volatile("cp.async.wait_group 0;" ::: "memory")
#define CPWAIT1()  asm volatile("cp.async.wait_group 1;" ::: "memory")

// ================= fused action + pos_emb -> xin (tf32-exact) ==================
__global__ __launch_bounds__(256) void fused_xin_kernel(
    const float* __restrict__ x, const float* __restrict__ sq_w,
    const float* __restrict__ bn_g, const float* __restrict__ bn_b,
    const float* __restrict__ dw_w, const float* __restrict__ ex_w,
    const float* __restrict__ pos_emb)
{
    __shared__ float xs[34][68];
    __shared__ float x3s[34][36];
    __shared__ float xp3[32][32];
    __shared__ float sqT[64][32];
    __shared__ float exT[32][64];
    __shared__ float bng_s[32], bnb_s[32];

    int bi = blockIdx.x;
    int t0 = blockIdx.y * 32;
    int tid = threadIdx.x;
    int nrows = min(34, TLEN - t0);

    for (int i = tid; i < nrows * 16; i += 256) {
        int row = i >> 4, c4 = (i & 15) << 2;
        *(float4*)&xs[row][c4] = *(const float4*)&x[((size_t)bi * TLEN + t0 + row) * KD + c4];
    }
    for (int i = tid; i < 2048; i += 256) { int r = i >> 6, c = i & 63; sqT[c][r] = sq_w[i]; }
    for (int i = tid; i < 2048; i += 256) { int c = i >> 5, r = i & 31; exT[r][c] = ex_w[i]; }
    if (tid < 32) { bng_s[tid] = bn_g[tid] * 0.9999950000374997f; bnb_s[tid] = bn_b[tid]; }
    __syncthreads();

    {
        int j = tid >> 2, rg = (tid & 3) << 3;
        if (j < nrows) {
            float acc[8];
#pragma unroll
            for (int i = 0; i < 8; ++i) acc[i] = 0.f;
#pragma unroll
            for (int c4 = 0; c4 < 64; c4 += 4) {
                float4 xv = *(const float4*)&xs[j][c4];
#pragma unroll
                for (int t = 0; t < 4; ++t) {
                    float xc = (t == 0) ? xv.x : (t == 1) ? xv.y : (t == 2) ? xv.z : xv.w;
                    float4 s0 = *(const float4*)&sqT[c4 + t][rg];
                    float4 s1 = *(const float4*)&sqT[c4 + t][rg + 4];
                    acc[0] += xc * s0.x; acc[1] += xc * s0.y;
                    acc[2] += xc * s0.z; acc[3] += xc * s0.w;
                    acc[4] += xc * s1.x; acc[5] += xc * s1.y;
                    acc[6] += xc * s1.z; acc[7] += xc * s1.w;
                }
            }
#pragma unroll
            for (int i = 0; i < 8; ++i)
                x3s[j][rg + i] = acc[i] * bng_s[rg + i] + bnb_s[rg + i];
        }
    }
    __syncthreads();

    for (int idx = tid; idx < 32 * 32; idx += 256) {
        int r = idx & 31, jj = idx >> 5;
        int pos = t0 + jj;
        float base = x3s[jj][r];
        float v;
        if (pos == TLEN - 1) {
            v = base;
        } else {
            float d0 = dw_w[r * 3 + 0], d1 = dw_w[r * 3 + 1], d2 = dw_w[r * 3 + 2];
            float a = base * d0 + x3s[jj + 1][r] * d1 +
                      ((pos + 2 < TLEN) ? x3s[jj + 2][r] * d2 : 0.f);
            v = a - base;
        }
        xp3[jj][r] = v;
    }
    __syncthreads();

    for (int idx = tid; idx < 32 * 64; idx += 256) {
        int c = idx & 63, j = idx >> 6;
        int pos = t0 + j;
        float gsum = 0.f;
#pragma unroll
        for (int r = 0; r < R32; ++r) gsum += xp3[j][r] * exT[r][c];
        float sig = sigmoid_exact(gsum);
        size_t off = ((size_t)bi * TLEN + pos) * KD + c;
        g_xin[off] = tf32r(xs[j][c] * sig + pos_emb[pos * KD + c]);
    }
}

// ---------------- weight prep (reorder + tf32 round, single kernel) ------------
__global__ __launch_bounds__(256) void prep_w_kernel(
    const float* __restrict__ wq, const float* __restrict__ wk,
    const float* __restrict__ wv, const float* __restrict__ wl,
    const float* __restrict__ uni_w)
{
    int idx = blockIdx.x * 256 + threadIdx.x;
    if (idx < 320 * 1024) {
        int n = idx & 1023, kcol = idx >> 10;
        int mm = kcol >> 6, c = kcol & 63;
        float w = (n < 512) ? wq[n * 320 + c * 5 + mm] : wk[(n - 512) * 320 + c * 5 + mm];
        g_WB[idx] = tf32r(w);
    } else if (idx < 320 * 1024 + 65536) {
        int j = idx - 320 * 1024;
        int n = j & 1023, c = j >> 10;
        g_WB2[j] = tf32r((n < 512) ? wv[n * 64 + c] : wl[(n - 512) * 64 + c]);
    } else if (idx < 320 * 1024 + 131072) {
        int j = idx - (320 * 1024 + 65536);
        g_WU[j] = tf32r(uni_w[j]);
    }
}

// ---------------- conv GEMMs (tf32 mma, cp.async dbl-buffered, mode=blockIdx.z) --
__global__ __launch_bounds__(256) void convgemm_kernel(
    const float* __restrict__ bias0, const float* __restrict__ bias1)
{
    int mode = blockIdx.z;
    const int NSTAGE = (mode == 0) ? 10 : 2;
    extern __shared__ float sm[];
    float* As = sm;                   // [2][128][36]
    float* Bs = sm + 2 * 128 * 36;    // [2][32][68]
    const float* __restrict__ Bg = (mode == 0) ? g_WB : g_WB2;

    int tid = threadIdx.x, lane = tid & 31, wid = tid >> 5;
    int wm = wid & 3, wn = wid >> 2, gi = lane >> 2, ci = lane & 3;
    int m0 = blockIdx.x * 128, n0 = blockIdx.y * 64;
    int bi = m0 >> 10, tibase = m0 & 1023;
    uint32_t sb = (uint32_t)__cvta_generic_to_shared(sm);
    uint32_t a_sb = sb, b_sb = sb + 2 * 128 * 36 * 4;

    auto issue_stage = [&](int s_, int buf_) {
        int mm_ = (mode == 0) ? (s_ >> 1) : 0;
        int c0_ = (mode == 0) ? ((s_ & 1) << 5) : (s_ << 5);
        int sh_ = (mode == 0) ? (2 * mm_ - 8) : 0;
#pragma unroll
        for (int i_ = 0; i_ < 4; ++i_) {
            int f4 = tid + i_ * 256;
            int row = f4 >> 3, c4 = (f4 & 7) << 2;
            int tsrc = tibase + row + sh_;
            const float* srcp = g_xin + ((size_t)(bi << 10) + tsrc) * 64 + c0_ + c4;
            uint32_t dstp = a_sb + (uint32_t)((buf_ * 4608 + row * 36 + c4) * 4);
            cp16p(dstp, srcp, (tsrc >= 0) ? 16 : 0);
        }
#pragma unroll
        for (int i_ = 0; i_ < 2; ++i_) {
            int f4 = tid + i_ * 256;
            int row = f4 >> 4, c4 = (f4 & 15) << 2;
            const float* srcp = Bg + (size_t)(s_ * 32 + row) * 1024 + n0 + c4;
            uint32_t dstp = b_sb + (uint32_t)((buf_ * 2176 + row * 68 + c4) * 4);
            cp16(dstp, srcp);
        }
        CPCOMMIT();
    };

    float acc[2][4][4];
#pragma unroll
    for (int a = 0; a < 2; ++a)
#pragma unroll
        for (int b = 0; b < 4; ++b)
#pragma unroll
            for (int c = 0; c < 4; ++c) acc[a][b][c] = 0.f;

    issue_stage(0, 0);
    for (int s = 0; s < NSTAGE; ++s) {
        if (s + 1 < NSTAGE) { issue_stage(s + 1, (s + 1) & 1); CPWAIT1(); }
        else CPWAIT0();
        __syncthreads();
        const float* Ab = As + (s & 1) * 4608;
        const float* Bb = Bs + (s & 1) * 2176;
#pragma unroll
        for (int kk = 0; kk < 4; ++kk) {
            int k = kk * 8;
            uint32_t af[2][4];
#pragma unroll
            for (int mi = 0; mi < 2; ++mi) {
                int r = wm * 32 + mi * 16 + gi;
                af[mi][0] = __float_as_uint(Ab[r * 36 + k + ci]);
                af[mi][1] = __float_as_uint(Ab[(r + 8) * 36 + k + ci]);
                af[mi][2] = __float_as_uint(Ab[r * 36 + k + ci + 4]);
                af[mi][3] = __float_as_uint(Ab[(r + 8) * 36 + k + ci + 4]);
            }
            uint32_t bf[4][2];
#pragma unroll
            for (int ni = 0; ni < 4; ++ni) {
                int n = wn * 32 + ni * 8 + gi;
                bf[ni][0] = __float_as_uint(Bb[(k + ci) * 68 + n]);
                bf[ni][1] = __float_as_uint(Bb[(k + ci + 4) * 68 + n]);
            }
#pragma unroll
            for (int mi = 0; mi < 2; ++mi)
#pragma unroll
                for (int ni = 0; ni < 4; ++ni)
                    mma8(acc[mi][ni], af[mi][0], af[mi][1], af[mi][2], af[mi][3],
                         bf[ni][0], bf[ni][1]);
        }
        __syncthreads();
    }

#pragma unroll
    for (int mi = 0; mi < 2; ++mi)
#pragma unroll
        for (int ni = 0; ni < 4; ++ni)
#pragma unroll
            for (int j = 0; j < 4; ++j) {
                int m = m0 + wm * 32 + mi * 16 + gi + ((j >= 2) ? 8 : 0);
                int n = n0 + wn * 32 + ni * 8 + 2 * ci + (j & 1);
                float v = acc[mi][ni][j];
                int o = n & 511, ki = o >> 3, h = o & 7;
                int bb = m >> 10, ti = m & 1023;
                int gg = bb * 8 + (ti >> 7);
                int tj = ((ti & 127) << 3) | h;
                if (mode == 0) {
                    float bias = (n < 512) ? bias0[n] : bias1[n - 512];
                    float s = silu_fast(v + bias) * 0.35355339059327373f;  // / 64^0.25
                    float* dst = (n < 512) ? g_q : g_k;
                    dst[((size_t)gg * TLEN + tj) * KD + pqk(ki)] = tf32r(s);
                } else {
                    float s = silu_fast(v);
                    if (n < 512) {
                        // V transposed [g][d][t], key dim permuted within 64-tiles
                        g_v[((size_t)gg * KD + ki) * TLEN + (tj & ~63) + pqk(tj & 63)] = tf32r(s);
                    } else {
                        g_l[((size_t)gg * TLEN + tj) * KD + ki] = tf32r(s);
                    }
                }
            }
}

// ---------------- flash attention (tf32 mma, vectorized LDS128 fragments) ------
// block (g, p): warps 0-3 handle q-tile qa=p, warps 4-7 q-tile qb=15-p.
__global__ __launch_bounds__(256) void flash_mma_kernel()
{
    extern __shared__ float sm[];   // Ks[2][64*64] | Vt[2][64*64], XOR-swizzled
    int g  = blockIdx.x;
    int p  = blockIdx.y;
    int qa = p, qb = 15 - p;
    int tid = threadIdx.x, lane = tid & 31, wid = tid >> 5;
    int gi = lane >> 2, ci = lane & 3;
    uint32_t sb = (uint32_t)__cvta_generic_to_shared(sm);

    int myqt  = (wid < 4) ? qa : qb;
    int qbase = myqt * 64 + (wid & 3) * 16;
    int r0 = qbase + gi;

    // Q fragments: 8 LDG128 (permuted layout)
    const float* Qg = g_q + (size_t)g * (TLEN * KD);
    uint32_t qf[8][4];
#pragma unroll
    for (int t4 = 0; t4 < 4; ++t4) {
        int woff = (2 * ci + (t4 & 1) + ((t4 >> 1) << 3)) << 2;
        float4 lo = *(const float4*)&Qg[(size_t)r0 * KD + woff];
        float4 hi = *(const float4*)&Qg[(size_t)(r0 + 8) * KD + woff];
        int kk0 = ((t4 >> 1) << 2) + ((t4 & 1) << 1);
        qf[kk0][0]     = __float_as_uint(lo.x); qf[kk0][2]     = __float_as_uint(lo.y);
        qf[kk0 + 1][0] = __float_as_uint(lo.z); qf[kk0 + 1][2] = __float_as_uint(lo.w);
        qf[kk0][1]     = __float_as_uint(hi.x); qf[kk0][3]     = __float_as_uint(hi.y);
        qf[kk0 + 1][1] = __float_as_uint(hi.z); qf[kk0 + 1][3] = __float_as_uint(hi.w);
    }

    float o[8][4];
#pragma unroll
    for (int a = 0; a < 8; ++a)
#pragma unroll
        for (int b = 0; b < 4; ++b) o[a][b] = 0.f;
    float m0v = -1e30f, m1v = -1e30f, l0 = 0.f, l1 = 0.f;

    int src_lo = (lane & ~3) | (ci >> 1);
    int src_hi = src_lo + 2;
    bool odd = ci & 1;

    const float* Kg0 = g_k + (size_t)g * (TLEN * KD);
    const float* Vg0 = g_v + (size_t)g * (KD * TLEN);
    int nkt = qb + 1;

#define FLASH_ISSUE(kt_, buf_)                                                        \
    do {                                                                              \
        _Pragma("unroll")                                                             \
        for (int i_ = 0; i_ < 4; ++i_) {                                              \
            int f4 = tid + i_ * 256;                                                  \
            int row = f4 >> 4, chunk = f4 & 15;                                       \
            int swc = chunk ^ (row & 7);                                              \
            cp16(sb + (uint32_t)(((buf_) * 4096 + row * 64 + swc * 4) * 4),           \
                 Kg0 + (size_t)(kt_) * 4096 + row * 64 + chunk * 4);                  \
            cp16(sb + (uint32_t)(((8192 + (buf_) * 4096) + row * 64 + swc * 4) * 4),  \
                 Vg0 + (size_t)row * TLEN + (kt_) * 64 + chunk * 4);                  \
        }                                                                             \
        CPCOMMIT();                                                                   \
    } while (0)

    FLASH_ISSUE(0, 0);
    for (int kt = 0; kt < nkt; ++kt) {
        int k0 = kt * 64;
        if (kt + 1 < nkt) { FLASH_ISSUE(kt + 1, (kt + 1) & 1); CPWAIT1(); }
        else CPWAIT0();
        __syncthreads();
        const float* Ks = sm + (kt & 1) * 4096;
        const float* Vs = sm + 8192 + (kt & 1) * 4096;
        if (k0 <= qbase + 15) {
            // S = Q K^T : per ni, 4 LDS128 + 8 MMA
            float s[8][4];
#pragma unroll
            for (int ni = 0; ni < 8; ++ni) {
                s[ni][0] = s[ni][1] = s[ni][2] = s[ni][3] = 0.f;
                int key = ni * 8 + gi;
                const uint32_t* Krow = (const uint32_t*)(Ks + key * 64);
                int sw = key & 7;
#pragma unroll
                for (int t4 = 0; t4 < 4; ++t4) {
                    int chunk = 2 * ci + (t4 & 1) + ((t4 >> 1) << 3);
                    uint4 F = *(const uint4*)(Krow + ((chunk ^ sw) << 2));
                    int kk0 = ((t4 >> 1) << 2) + ((t4 & 1) << 1);
                    mma8(s[ni], qf[kk0][0], qf[kk0][1], qf[kk0][2], qf[kk0][3], F.x, F.y);
                    mma8(s[ni], qf[kk0 + 1][0], qf[kk0 + 1][1], qf[kk0 + 1][2], qf[kk0 + 1][3], F.z, F.w);
                }
            }
            if (k0 + 63 > qbase) {   // diagonal tile: causal mask
#pragma unroll
                for (int ni = 0; ni < 8; ++ni)
#pragma unroll
                    for (int j = 0; j < 4; ++j) {
                        int col = k0 + ni * 8 + 2 * ci + (j & 1);
                        int row = r0 + ((j >= 2) ? 8 : 0);
                        if (col > row) s[ni][j] = -1e30f;
                    }
            }
            // online softmax
            float mx0 = -1e30f, mx1 = -1e30f;
#pragma unroll
            for (int ni = 0; ni < 8; ++ni) {
                mx0 = fmaxf(mx0, fmaxf(s[ni][0], s[ni][1]));
                mx1 = fmaxf(mx1, fmaxf(s[ni][2], s[ni][3]));
            }
            mx0 = fmaxf(mx0, __shfl_xor_sync(0xffffffffu, mx0, 1));
            mx0 = fmaxf(mx0, __shfl_xor_sync(0xffffffffu, mx0, 2));
            mx1 = fmaxf(mx1, __shfl_xor_sync(0xffffffffu, mx1, 1));
            mx1 = fmaxf(mx1, __shfl_xor_sync(0xffffffffu, mx1, 2));
            float m0n = fmaxf(m0v, mx0), m1n = fmaxf(m1v, mx1);
            float corr0 = __expf(m0v - m0n), corr1 = __expf(m1v - m1n);

            float sum0 = 0.f, sum1 = 0.f;
#pragma unroll
            for (int ni = 0; ni < 8; ++ni) {
                s[ni][0] = tf32r(__expf(s[ni][0] - m0n));
                s[ni][1] = tf32r(__expf(s[ni][1] - m0n));
                s[ni][2] = tf32r(__expf(s[ni][2] - m1n));
                s[ni][3] = tf32r(__expf(s[ni][3] - m1n));
                sum0 += s[ni][0] + s[ni][1];
                sum1 += s[ni][2] + s[ni][3];
            }
            sum0 += __shfl_xor_sync(0xffffffffu, sum0, 1);
            sum0 += __shfl_xor_sync(0xffffffffu, sum0, 2);
            sum1 += __shfl_xor_sync(0xffffffffu, sum1, 1);
            sum1 += __shfl_xor_sync(0xffffffffu, sum1, 2);
            l0 = l0 * corr0 + sum0;
            l1 = l1 * corr1 + sum1;
            m0v = m0n; m1v = m1n;
#pragma unroll
            for (int nd = 0; nd < 8; ++nd) {
                o[nd][0] *= corr0; o[nd][1] *= corr0;
                o[nd][2] *= corr1; o[nd][3] *= corr1;
            }
            // P C-layout -> A-fragments, in place (reuse s registers)
#pragma unroll
            for (int kg = 0; kg < 8; ++kg) {
                float v00 = __shfl_sync(0xffffffffu, s[kg][0], src_lo);
                float v01 = __shfl_sync(0xffffffffu, s[kg][1], src_lo);
                float v10 = __shfl_sync(0xffffffffu, s[kg][2], src_lo);
                float v11 = __shfl_sync(0xffffffffu, s[kg][3], src_lo);
                float w00 = __shfl_sync(0xffffffffu, s[kg][0], src_hi);
                float w01 = __shfl_sync(0xffffffffu, s[kg][1], src_hi);
                float w10 = __shfl_sync(0xffffffffu, s[kg][2], src_hi);
                float w11 = __shfl_sync(0xffffffffu, s[kg][3], src_hi);
                s[kg][0] = odd ? v01 : v00;
                s[kg][1] = odd ? v11 : v10;
                s[kg][2] = odd ? w01 : w00;
                s[kg][3] = odd ? w11 : w10;
            }
            // P @ V : per nd, 4 LDS128 + 8 MMA
#pragma unroll
            for (int nd = 0; nd < 8; ++nd) {
                int row = nd * 8 + gi;
                const uint32_t* Vrow = (const uint32_t*)(Vs + row * 64);
                int sw = row & 7;
#pragma unroll
                for (int t4 = 0; t4 < 4; ++t4) {
                    int chunk = 2 * ci + (t4 & 1) + ((t4 >> 1) << 3);
                    uint4 F = *(const uint4*)(Vrow + ((chunk ^ sw) << 2));
                    int kg0 = ((t4 >> 1) << 2) + ((t4 & 1) << 1);
                    mma8(o[nd], __float_as_uint(s[kg0][0]), __float_as_uint(s[kg0][1]),
                         __float_as_uint(s[kg0][2]), __float_as_uint(s[kg0][3]), F.x, F.y);
                    mma8(o[nd], __float_as_uint(s[kg0 + 1][0]), __float_as_uint(s[kg0 + 1][1]),
                         __float_as_uint(s[kg0 + 1][2]), __float_as_uint(s[kg0 + 1][3]), F.z, F.w);
                }
            }
        }
        __syncthreads();
    }
#undef FLASH_ISSUE

    float inv0 = 1.f / l0, inv1 = 1.f / l1;
    float* Og = g_og + (size_t)g * (TLEN * KD);
#pragma unroll
    for (int nd = 0; nd < 8; ++nd) {
        int c = nd * 8 + 2 * ci;
        float2 t0; t0.x = o[nd][0] * inv0; t0.y = o[nd][1] * inv0;
        float2 t1; t1.x = o[nd][2] * inv1; t1.y = o[nd][3] * inv1;
        *(float2*)&Og[(size_t)r0 * KD + c] = t0;
        *(float2*)&Og[(size_t)(r0 + 8) * KD + c] = t1;
    }
}

// ---------------- local windowed causal attention ------------------------------
__global__ __launch_bounds__(256) void local_attn_kernel()
{
    int g = blockIdx.x;
    int tjbase = blockIdx.y * 64;
    int lane = threadIdx.x & 31;
    int w = threadIdx.x >> 5;
    const float* Lg = g_l + (size_t)g * (TLEN * KD);
    float* Og = g_ol + (size_t)g * (TLEN * KD);
    for (int qi = 0; qi < 8; ++qi) {
        int tj = tjbase + w * 8 + qi;
        float a0 = Lg[tj * 64 + lane];
        float a1 = Lg[tj * 64 + lane + 32];
        float s[6];
        float mx = -1e30f;
#pragma unroll
        for (int wv = 0; wv < 6; ++wv) {
            int tp = tj - 5 + wv;
            float sc = -1e30f;
            if (tp >= 0) {
                float p = a0 * Lg[tp * 64 + lane] + a1 * Lg[tp * 64 + lane + 32];
#pragma unroll
                for (int o = 16; o; o >>= 1) p += __shfl_xor_sync(0xffffffffu, p, o);
                sc = p * 0.125f;
            }
            s[wv] = sc;
            mx = fmaxf(mx, sc);
        }
        float den = 0.f, o0 = 0.f, o1 = 0.f;
#pragma unroll
        for (int wv = 0; wv < 6; ++wv) {
            int tp = tj - 5 + wv;
            if (tp >= 0) {
                float pp = expf(s[wv] - mx);
                den += pp;
                o0 += pp * Lg[tp * 64 + lane];
                o1 += pp * Lg[tp * 64 + lane + 32];
            }
        }
        float inv = 1.f / den;
        Og[tj * 64 + lane] = o0 * inv;
        Og[tj * 64 + lane + 32] = o1 * inv;
    }
}

// ---------------- uni projection: fused gating + K-split tf32 GEMM -------------
__global__ __launch_bounds__(256) void unigemm_kernel()
{
    __shared__ float As[128][36];
    __shared__ float Bs[32][68];
    int tid = threadIdx.x, lane = tid & 31, wid = tid >> 5;
    int wm = wid & 3, wn = wid >> 2, gi = lane >> 2, ci = lane & 3;
    int m0 = blockIdx.x * 128;
    int kz = blockIdx.y;
    int bi = m0 >> 10, tib = m0 & 1023;
    uint32_t b_sb = (uint32_t)__cvta_generic_to_shared(&Bs[0][0]);

    float acc[2][4][4];
#pragma unroll
    for (int a = 0; a < 2; ++a)
#pragma unroll
        for (int b = 0; b < 4; ++b)
#pragma unroll
            for (int c = 0; c < 4; ++c) acc[a][b][c] = 0.f;

    for (int s = 0; s < 8; ++s) {
        int k0 = kz * 256 + s * 32;
        int ch = k0 >> 6, ki0 = k0 & 63;
        int h2 = ch & 7;
        bool lohalf = ch < 8;
        const float* Og = g_og + (size_t)(bi * 8 + h2) * (TLEN * KD);
        const float* Lg = g_ol + (size_t)(bi * 8 + h2) * (TLEN * KD);
        __syncthreads();
#pragma unroll
        for (int i = 0; i < 2; ++i) {
            int f4 = tid + i * 256;
            int row = f4 >> 4, c4 = (f4 & 15) << 2;
            cp16(b_sb + (uint32_t)((row * 68 + c4) * 4), g_WU + (size_t)(k0 + row) * 64 + c4);
        }
        CPCOMMIT();
#pragma unroll
        for (int i = 0; i < 4; ++i) {
            int f4 = tid + i * 256;
            int row = f4 >> 3, c4 = (f4 & 7) << 2;
            int ti2 = tib + row;
            const float4 o4 = *(const float4*)(Og + (size_t)ti2 * 64 + ki0 + c4);
            const float4 l4 = *(const float4*)(Lg + (size_t)ti2 * 64 + ki0 + c4);
            float g0 = sigmoid_fast(o4.x), g1 = sigmoid_fast(o4.y);
            float g2 = sigmoid_fast(o4.z), g3 = sigmoid_fast(o4.w);
            float r0 = lohalf ? (1.f - g0) * l4.x : g0 * o4.x;
            float r1 = lohalf ? (1.f - g1) * l4.y : g1 * o4.y;
            float r2 = lohalf ? (1.f - g2) * l4.z : g2 * o4.z;
            float r3 = lohalf ? (1.f - g3) * l4.w : g3 * o4.w;
            As[row][c4 + 0] = tf32r(r0);
            As[row][c4 + 1] = tf32r(r1);
            As[row][c4 + 2] = tf32r(r2);
            As[row][c4 + 3] = tf32r(r3);
        }
        CPWAIT0();
        __syncthreads();
#pragma unroll
        for (int kk = 0; kk < 4; ++kk) {
            int k = kk * 8;
            uint32_t af[2][4];
#pragma unroll
            for (int mi = 0; mi < 2; ++mi) {
                int r = wm * 32 + mi * 16 + gi;
                af[mi][0] = __float_as_uint(As[r][k + ci]);
                af[mi][1] = __float_as_uint(As[r + 8][k + ci]);
                af[mi][2] = __float_as_uint(As[r][k + ci + 4]);
                af[mi][3] = __float_as_uint(As[r + 8][k + ci + 4]);
            }
            uint32_t bf[4][2];
#pragma unroll
            for (int ni = 0; ni < 4; ++ni) {
                int n = wn * 32 + ni * 8 + gi;
                bf[ni][0] = __float_as_uint(Bs[k + ci][n]);
                bf[ni][1] = __float_as_uint(Bs[k + ci + 4][n]);
            }
#pragma unroll
            for (int mi = 0; mi < 2; ++mi)
#pragma unroll
                for (int ni = 0; ni < 4; ++ni)
                    mma8(acc[mi][ni], af[mi][0], af[mi][1], af[mi][2], af[mi][3],
                         bf[ni][0], bf[ni][1]);
        }
    }

    float* P = g_part + ((size_t)kz * MROWS + m0) * 64;
#pragma unroll
    for (int mi = 0; mi < 2; ++mi)
#pragma unroll
        for (int ni = 0; ni < 4; ++ni)
#pragma unroll
            for (int j = 0; j < 4; j += 2) {
                int mrow = wm * 32 + mi * 16 + gi + ((j >= 2) ? 8 : 0);
                int n = wn * 32 + ni * 8 + 2 * ci;
                float2 t; t.x = acc[mi][ni][j]; t.y = acc[mi][ni][j + 1];
                *(float2*)&P[(size_t)mrow * 64 + n] = t;
            }
}

// ---------------- partial-reduce + silu + residual -> LN1 -> FF -> LN2 ---------
__global__ __launch_bounds__(256) void ffln_kernel(
    const float* __restrict__ uni_b,
    const float* __restrict__ ln1g, const float* __restrict__ ln1b,
    const float* __restrict__ ln2g, const float* __restrict__ ln2b,
    const float* __restrict__ w1, const float* __restrict__ b1,
    const float* __restrict__ w2, const float* __restrict__ b2,
    float* __restrict__ out)
{
    const int R = 16;
    __shared__ float yl[R][64];
    __shared__ float hs[R][256];
    __shared__ float fs[R][64];
    int r0 = blockIdx.x * R;
    int tid = threadIdx.x;
    int lane = tid & 31, w = tid >> 5;

    for (int rr = 0; rr < 2; ++rr) {
        int r = w * 2 + rr;
        size_t rg = (size_t)(r0 + r) * 64;
        float v0 = g_part[rg + lane] + g_part[(size_t)MROWS * 64 + rg + lane] +
                   g_part[(size_t)MROWS * 128 + rg + lane] + g_part[(size_t)MROWS * 192 + rg + lane];
        float v1 = g_part[rg + lane + 32] + g_part[(size_t)MROWS * 64 + rg + lane + 32] +
                   g_part[(size_t)MROWS * 128 + rg + lane + 32] + g_part[(size_t)MROWS * 192 + rg + lane + 32];
        v0 = silu_fast(v0 + uni_b[lane]) + g_xin[rg + lane];
        v1 = silu_fast(v1 + uni_b[lane + 32]) + g_xin[rg + lane + 32];
        float sm = v0 + v1;
#pragma unroll
        for (int o = 16; o; o >>= 1) sm += __shfl_xor_sync(0xffffffffu, sm, o);
        float mean = sm * (1.f / 64.f);
        float d0 = v0 - mean, d1 = v1 - mean;
        float vs = d0 * d0 + d1 * d1;
#pragma unroll
        for (int o = 16; o; o >>= 1) vs += __shfl_xor_sync(0xffffffffu, vs, o);
        float inv = rsqrtf(vs * (1.f / 64.f) + 1e-5f);
        yl[r][lane]      = d0 * inv * ln1g[lane] + ln1b[lane];
        yl[r][lane + 32] = d1 * inv * ln1g[lane + 32] + ln1b[lane + 32];
    }
    __syncthreads();

    {
        float acc[R];
#pragma unroll
        for (int r = 0; r < R; ++r) acc[r] = b1[tid];
        for (int c = 0; c < 64; ++c) {
            float wv = w1[c * 256 + tid];
#pragma unroll
            for (int r = 0; r < R; ++r) acc[r] += yl[r][c] * wv;
        }
#pragma unroll
        for (int r = 0; r < R; ++r) hs[r][tid] = fmaxf(acc[r], 0.f);
    }
    __syncthreads();

    {
        int j2 = tid & 63, rg = tid >> 6;
#pragma unroll
        for (int rr = 0; rr < 4; ++rr) {
            int r = rg * 4 + rr;
            float a = b2[j2];
            for (int c = 0; c < 256; ++c) a += hs[r][c] * w2[c * 64 + j2];
            fs[r][j2] = a + yl[r][j2];
        }
    }
    __syncthreads();

    for (int rr = 0; rr < 2; ++rr) {
        int r = w * 2 + rr;
        float v0 = fs[r][lane], v1 = fs[r][lane + 32];
        float sm = v0 + v1;
#pragma unroll
        for (int o = 16; o; o >>= 1) sm += __shfl_xor_sync(0xffffffffu, sm, o);
        float mean = sm * (1.f / 64.f);
        float d0 = v0 - mean, d1 = v1 - mean;
        float vs = d0 * d0 + d1 * d1;
#pragma unroll
        for (int o = 16; o; o >>= 1) vs += __shfl_xor_sync(0xffffffffu, vs, o);
        float inv = rsqrtf(vs * (1.f / 64.f) + 1e-5f);
        float* orow = out + (size_t)(r0 + r) * 64;
        orow[lane]      = d0 * inv * ln2g[lane] + ln2b[lane];
        orow[lane + 32] = d1 * inv * ln2g[lane + 32] + ln2b[lane + 32];
    }
}

// ---------------- launch ---------------------------------------------------------
extern "C" void kernel_launch(void* const* d_in, const int* in_sizes, int n_in,
                              void* d_out, int out_size)
{
    (void)in_sizes; (void)n_in; (void)out_size;
    const float* x       = (const float*)d_in[0];
    const float* sq_w    = (const float*)d_in[1];
    const float* bn_g    = (const float*)d_in[2];
    const float* bn_b    = (const float*)d_in[3];
    const float* dw_w    = (const float*)d_in[4];
    const float* ex_w    = (const float*)d_in[5];
    const float* pos_emb = (const float*)d_in[6];
    const float* wq      = (const float*)d_in[7];
    const float* bq      = (const float*)d_in[8];
    const float* wk      = (const float*)d_in[9];
    const float* bk      = (const float*)d_in[10];
    const float* wv      = (const float*)d_in[11];
    const float* wl      = (const float*)d_in[12];
    const float* uni_w   = (const float*)d_in[13];
    const float* uni_b   = (const float*)d_in[14];
    const float* ln1_g   = (const float*)d_in[15];
    const float* ln1_b   = (const float*)d_in[16];
    const float* ln2_g   = (const float*)d_in[17];
    const float* ln2_b   = (const float*)d_in[18];
    const float* ff_w1   = (const float*)d_in[19];
    const float* ff_b1   = (const float*)d_in[20];
    const float* ff_w2   = (const float*)d_in[21];
    const float* ff_b2   = (const float*)d_in[22];
    float* out = (float*)d_out;

    const int CONV_SMEM  = (2 * 128 * 36 + 2 * 32 * 68) * 4;   // 54272
    const int FLASH_SMEM = 4 * 64 * 64 * 4;                    // 65536
    cudaFuncSetAttribute(convgemm_kernel, cudaFuncAttributeMaxDynamicSharedMemorySize, CONV_SMEM);
    cudaFuncSetAttribute(flash_mma_kernel, cudaFuncAttributeMaxDynamicSharedMemorySize, FLASH_SMEM);

    fused_xin_kernel<<<dim3(4, 32), 256>>>(x, sq_w, bn_g, bn_b, dw_w, ex_w, pos_emb);
    prep_w_kernel<<<1792, 256>>>(wq, wk, wv, wl, uni_w);

    convgemm_kernel<<<dim3(32, 16, 2), 256, CONV_SMEM>>>(bq, bk);

    flash_mma_kernel<<<dim3(32, 8), 256, FLASH_SMEM>>>();
    local_attn_kernel<<<dim3(32, 16), 256>>>();

    unigemm_kernel<<<dim3(32, 4), 256>>>();

    ffln_kernel<<<256, 256>>>(uni_b, ln1_g, ln1_b, ln2_g, ln2_b,
                              ff_w1, ff_b1, ff_w2, ff_b2, out);
}

// round 6
// speedup vs baseline: 3.3085x; 1.2116x over previous
#include <cuda_runtime.h>
#include <math.h>
#include <stdint.h>

// Problem constants (fixed by setup_inputs)
#define BATCH 4
#define TLEN  1024
#define KD    64
#define HNUM  8
#define R32   32
#define NSEQ  32      // BATCH*HNUM
#define MROWS 4096    // BATCH*TLEN

// ---------------- scratch (static device globals; no allocation) --------------
__device__ float g_xin[BATCH * TLEN * KD];          // tf32-exact
__device__ float g_WB[320 * 1024];                  // tap-major reordered wq|wk, tf32-exact
__device__ float g_WB2[64 * 1024];                  // wv|wl transposed, tf32-exact
__device__ float g_WU[1024 * 64];                   // uni_w, tf32-exact
__device__ float g_q[NSEQ * TLEN * KD];             // [g][t][p(d)] tf32-exact
__device__ float g_k[NSEQ * TLEN * KD];             // [g][t][p(d)]
__device__ float g_v[NSEQ * KD * TLEN];             // [g][d][t-tilewise p(key)]  (transposed!)
__device__ float g_l[NSEQ * TLEN * KD];             // natural
__device__ float g_og[NSEQ * TLEN * KD];
__device__ float g_ol[NSEQ * TLEN * KD];
__device__ float g_part[4 * MROWS * KD];            // uni GEMM K-split partials

__device__ __forceinline__ float sigmoid_exact(float x) { return 1.f / (1.f + expf(-x)); }
__device__ __forceinline__ float sigmoid_fast(float x) {
    float t;
    asm("tanh.approx.f32 %0, %1;" : "=f"(t) : "f"(0.5f * x));
    return 0.5f * t + 0.5f;
}
__device__ __forceinline__ float silu_fast(float x) { return x * sigmoid_fast(x); }

// round f32 -> nearest tf32 (result is a valid f32 with low mantissa zeroed)
__device__ __forceinline__ float tf32r(float x) {
    uint32_t u;
    asm("cvt.rna.tf32.f32 %0, %1;" : "=r"(u) : "f"(x));
    return __uint_as_float(u);
}

// fragment-vectorization permutation of a 64-long contraction dim.
__device__ __forceinline__ int pqk(int k) {
    return ((k & 3) << 3) | ((k >> 5) << 5) | (((k >> 4) & 1) << 2) |
           (((k >> 3) & 1) << 1) | ((k >> 2) & 1);
}

__device__ __forceinline__ void mma8(float* c,
                                     uint32_t a0, uint32_t a1, uint32_t a2, uint32_t a3,
                                     uint32_t b0, uint32_t b1) {
    asm volatile(
        "mma.sync.aligned.m16n8k8.row.col.f32.tf32.tf32.f32 "
        "{%0,%1,%2,%3}, {%4,%5,%6,%7}, {%8,%9}, {%0,%1,%2,%3};"
        : "+f"(c[0]), "+f"(c[1]), "+f"(c[2]), "+f"(c[3])
        : "r"(a0), "r"(a1), "r"(a2), "r"(a3), "r"(b0), "r"(b1));
}

__device__ __forceinline__ void cp16(uint32_t dst, const void* src) {
    asm volatile("cp.async.ca.shared.global [%0], [%1], 16;" :: "r"(dst), "l"(src) : "memory");
}
__device__ __forceinline__ void cp16p(uint32_t dst, const void* src, int sz) {
    asm volatile("cp.async.ca.shared.global [%0], [%1], 16, %2;" :: "r"(dst), "l"(src), "r"(sz) : "memory");
}
#define CPCOMMIT() asm volatile("cp.async.commit_group;" ::: "memory")
#define CPWAIT0()  asm volatile("cp.async.wait_group 0;" ::: "memory")
#define CPWAIT1()  asm volatile("cp.async.wait_group 1;" ::: "memory")

// ================= fused action + pos_emb -> xin (tf32-exact) ==================
__global__ __launch_bounds__(256) void fused_xin_kernel(
    const float* __restrict__ x, const float* __restrict__ sq_w,
    const float* __restrict__ bn_g, const float* __restrict__ bn_b,
    const float* __restrict__ dw_w, const float* __restrict__ ex_w,
    const float* __restrict__ pos_emb)
{
    __shared__ float xs[34][68];
    __shared__ float x3s[34][36];
    __shared__ float xp3[32][32];
    __shared__ float sqT[64][32];
    __shared__ float exT[32][64];
    __shared__ float bng_s[32], bnb_s[32];

    int bi = blockIdx.x;
    int t0 = blockIdx.y * 32;
    int tid = threadIdx.x;
    int nrows = min(34, TLEN - t0);

    for (int i = tid; i < nrows * 16; i += 256) {
        int row = i >> 4, c4 = (i & 15) << 2;
        *(float4*)&xs[row][c4] = *(const float4*)&x[((size_t)bi * TLEN + t0 + row) * KD + c4];
    }
    for (int i = tid; i < 2048; i += 256) { int r = i >> 6, c = i & 63; sqT[c][r] = sq_w[i]; }
    for (int i = tid; i < 2048; i += 256) { int c = i >> 5, r = i & 31; exT[r][c] = ex_w[i]; }
    if (tid < 32) { bng_s[tid] = bn_g[tid] * 0.9999950000374997f; bnb_s[tid] = bn_b[tid]; }
    __syncthreads();

    {
        int j = tid >> 2, rg = (tid & 3) << 3;
        if (j < nrows) {
            float acc[8];
#pragma unroll
            for (int i = 0; i < 8; ++i) acc[i] = 0.f;
#pragma unroll
            for (int c4 = 0; c4 < 64; c4 += 4) {
                float4 xv = *(const float4*)&xs[j][c4];
#pragma unroll
                for (int t = 0; t < 4; ++t) {
                    float xc = (t == 0) ? xv.x : (t == 1) ? xv.y : (t == 2) ? xv.z : xv.w;
                    float4 s0 = *(const float4*)&sqT[c4 + t][rg];
                    float4 s1 = *(const float4*)&sqT[c4 + t][rg + 4];
                    acc[0] += xc * s0.x; acc[1] += xc * s0.y;
                    acc[2] += xc * s0.z; acc[3] += xc * s0.w;
                    acc[4] += xc * s1.x; acc[5] += xc * s1.y;
                    acc[6] += xc * s1.z; acc[7] += xc * s1.w;
                }
            }
#pragma unroll
            for (int i = 0; i < 8; ++i)
                x3s[j][rg + i] = acc[i] * bng_s[rg + i] + bnb_s[rg + i];
        }
    }
    __syncthreads();

    for (int idx = tid; idx < 32 * 32; idx += 256) {
        int r = idx & 31, jj = idx >> 5;
        int pos = t0 + jj;
        float base = x3s[jj][r];
        float v;
        if (pos == TLEN - 1) {
            v = base;
        } else {
            float d0 = dw_w[r * 3 + 0], d1 = dw_w[r * 3 + 1], d2 = dw_w[r * 3 + 2];
            float a = base * d0 + x3s[jj + 1][r] * d1 +
                      ((pos + 2 < TLEN) ? x3s[jj + 2][r] * d2 : 0.f);
            v = a - base;
        }
        xp3[jj][r] = v;
    }
    __syncthreads();

    for (int idx = tid; idx < 32 * 64; idx += 256) {
        int c = idx & 63, j = idx >> 6;
        int pos = t0 + j;
        float gsum = 0.f;
#pragma unroll
        for (int r = 0; r < R32; ++r) gsum += xp3[j][r] * exT[r][c];
        float sig = sigmoid_exact(gsum);
        size_t off = ((size_t)bi * TLEN + pos) * KD + c;
        g_xin[off] = tf32r(xs[j][c] * sig + pos_emb[pos * KD + c]);
    }
}

// ---------------- weight prep (reorder + tf32 round, single kernel) ------------
__global__ __launch_bounds__(256) void prep_w_kernel(
    const float* __restrict__ wq, const float* __restrict__ wk,
    const float* __restrict__ wv, const float* __restrict__ wl,
    const float* __restrict__ uni_w)
{
    int idx = blockIdx.x * 256 + threadIdx.x;
    if (idx < 320 * 1024) {
        int n = idx & 1023, kcol = idx >> 10;
        int mm = kcol >> 6, c = kcol & 63;
        float w = (n < 512) ? wq[n * 320 + c * 5 + mm] : wk[(n - 512) * 320 + c * 5 + mm];
        g_WB[idx] = tf32r(w);
    } else if (idx < 320 * 1024 + 65536) {
        int j = idx - 320 * 1024;
        int n = j & 1023, c = j >> 10;
        g_WB2[j] = tf32r((n < 512) ? wv[n * 64 + c] : wl[(n - 512) * 64 + c]);
    } else if (idx < 320 * 1024 + 131072) {
        int j = idx - (320 * 1024 + 65536);
        g_WU[j] = tf32r(uni_w[j]);
    }
}

// ---------------- conv GEMMs (tf32 mma, cp.async dbl-buffered, mode=blockIdx.z) --
__global__ __launch_bounds__(256, 2) void convgemm_kernel(
    const float* __restrict__ bias0, const float* __restrict__ bias1)
{
    int mode = blockIdx.z;
    const int NSTAGE = (mode == 0) ? 10 : 2;
    extern __shared__ float sm[];
    float* As = sm;                   // [2][128][36]
    float* Bs = sm + 2 * 128 * 36;    // [2][32][68]
    const float* __restrict__ Bg = (mode == 0) ? g_WB : g_WB2;

    int tid = threadIdx.x, lane = tid & 31, wid = tid >> 5;
    int wm = wid & 3, wn = wid >> 2, gi = lane >> 2, ci = lane & 3;
    int m0 = blockIdx.x * 128, n0 = blockIdx.y * 64;
    int bi = m0 >> 10, tibase = m0 & 1023;
    uint32_t sb = (uint32_t)__cvta_generic_to_shared(sm);
    uint32_t a_sb = sb, b_sb = sb + 2 * 128 * 36 * 4;

    auto issue_stage = [&](int s_, int buf_) {
        int mm_ = (mode == 0) ? (s_ >> 1) : 0;
        int c0_ = (mode == 0) ? ((s_ & 1) << 5) : (s_ << 5);
        int sh_ = (mode == 0) ? (2 * mm_ - 8) : 0;
#pragma unroll
        for (int i_ = 0; i_ < 4; ++i_) {
            int f4 = tid + i_ * 256;
            int row = f4 >> 3, c4 = (f4 & 7) << 2;
            int tsrc = tibase + row + sh_;
            const float* srcp = g_xin + ((size_t)(bi << 10) + tsrc) * 64 + c0_ + c4;
            uint32_t dstp = a_sb + (uint32_t)((buf_ * 4608 + row * 36 + c4) * 4);
            cp16p(dstp, srcp, (tsrc >= 0) ? 16 : 0);
        }
#pragma unroll
        for (int i_ = 0; i_ < 2; ++i_) {
            int f4 = tid + i_ * 256;
            int row = f4 >> 4, c4 = (f4 & 15) << 2;
            const float* srcp = Bg + (size_t)(s_ * 32 + row) * 1024 + n0 + c4;
            uint32_t dstp = b_sb + (uint32_t)((buf_ * 2176 + row * 68 + c4) * 4);
            cp16(dstp, srcp);
        }
        CPCOMMIT();
    };

    float acc[2][4][4];
#pragma unroll
    for (int a = 0; a < 2; ++a)
#pragma unroll
        for (int b = 0; b < 4; ++b)
#pragma unroll
            for (int c = 0; c < 4; ++c) acc[a][b][c] = 0.f;

    issue_stage(0, 0);
    for (int s = 0; s < NSTAGE; ++s) {
        if (s + 1 < NSTAGE) { issue_stage(s + 1, (s + 1) & 1); CPWAIT1(); }
        else CPWAIT0();
        __syncthreads();
        const float* Ab = As + (s & 1) * 4608;
        const float* Bb = Bs + (s & 1) * 2176;
#pragma unroll
        for (int kk = 0; kk < 4; ++kk) {
            int k = kk * 8;
            uint32_t af[2][4];
#pragma unroll
            for (int mi = 0; mi < 2; ++mi) {
                int r = wm * 32 + mi * 16 + gi;
                af[mi][0] = __float_as_uint(Ab[r * 36 + k + ci]);
                af[mi][1] = __float_as_uint(Ab[(r + 8) * 36 + k + ci]);
                af[mi][2] = __float_as_uint(Ab[r * 36 + k + ci + 4]);
                af[mi][3] = __float_as_uint(Ab[(r + 8) * 36 + k + ci + 4]);
            }
            uint32_t bf[4][2];
#pragma unroll
            for (int ni = 0; ni < 4; ++ni) {
                int n = wn * 32 + ni * 8 + gi;
                bf[ni][0] = __float_as_uint(Bb[(k + ci) * 68 + n]);
                bf[ni][1] = __float_as_uint(Bb[(k + ci + 4) * 68 + n]);
            }
#pragma unroll
            for (int mi = 0; mi < 2; ++mi)
#pragma unroll
                for (int ni = 0; ni < 4; ++ni)
                    mma8(acc[mi][ni], af[mi][0], af[mi][1], af[mi][2], af[mi][3],
                         bf[ni][0], bf[ni][1]);
        }
        __syncthreads();
    }

#pragma unroll
    for (int mi = 0; mi < 2; ++mi)
#pragma unroll
        for (int ni = 0; ni < 4; ++ni)
#pragma unroll
            for (int j = 0; j < 4; ++j) {
                int m = m0 + wm * 32 + mi * 16 + gi + ((j >= 2) ? 8 : 0);
                int n = n0 + wn * 32 + ni * 8 + 2 * ci + (j & 1);
                float v = acc[mi][ni][j];
                int o = n & 511, ki = o >> 3, h = o & 7;
                int bb = m >> 10, ti = m & 1023;
                int gg = bb * 8 + (ti >> 7);
                int tj = ((ti & 127) << 3) | h;
                if (mode == 0) {
                    float bias = (n < 512) ? bias0[n] : bias1[n - 512];
                    float s = silu_fast(v + bias) * 0.35355339059327373f;  // / 64^0.25
                    float* dst = (n < 512) ? g_q : g_k;
                    dst[((size_t)gg * TLEN + tj) * KD + pqk(ki)] = tf32r(s);
                } else {
                    float s = silu_fast(v);
                    if (n < 512) {
                        g_v[((size_t)gg * KD + ki) * TLEN + (tj & ~63) + pqk(tj & 63)] = tf32r(s);
                    } else {
                        g_l[((size_t)gg * TLEN + tj) * KD + ki] = tf32r(s);
                    }
                }
            }
}

// ---------------- flash attention (tf32 mma, vectorized LDS128 fragments) ------
// block (g, p): warps 0-3 handle q-tile qa=p, warps 4-7 q-tile qb=15-p.
// __launch_bounds__(256,2): cap regs at 128 so 2 blocks/SM -> 256-block grid
// is fully resident in ONE wave (296 slots on 148 SMs).
__global__ __launch_bounds__(256, 2) void flash_mma_kernel()
{
    extern __shared__ float sm[];   // Ks[2][64*64] | Vt[2][64*64], XOR-swizzled
    int g  = blockIdx.x;
    int p  = blockIdx.y;
    int qa = p, qb = 15 - p;
    int tid = threadIdx.x, lane = tid & 31, wid = tid >> 5;
    int gi = lane >> 2, ci = lane & 3;
    uint32_t sb = (uint32_t)__cvta_generic_to_shared(sm);

    int myqt  = (wid < 4) ? qa : qb;
    int qbase = myqt * 64 + (wid & 3) * 16;
    int r0 = qbase + gi;

    // Q fragments: 8 LDG128 (permuted layout)
    const float* Qg = g_q + (size_t)g * (TLEN * KD);
    uint32_t qf[8][4];
#pragma unroll
    for (int t4 = 0; t4 < 4; ++t4) {
        int woff = (2 * ci + (t4 & 1) + ((t4 >> 1) << 3)) << 2;
        float4 lo = *(const float4*)&Qg[(size_t)r0 * KD + woff];
        float4 hi = *(const float4*)&Qg[(size_t)(r0 + 8) * KD + woff];
        int kk0 = ((t4 >> 1) << 2) + ((t4 & 1) << 1);
        qf[kk0][0]     = __float_as_uint(lo.x); qf[kk0][2]     = __float_as_uint(lo.y);
        qf[kk0 + 1][0] = __float_as_uint(lo.z); qf[kk0 + 1][2] = __float_as_uint(lo.w);
        qf[kk0][1]     = __float_as_uint(hi.x); qf[kk0][3]     = __float_as_uint(hi.y);
        qf[kk0 + 1][1] = __float_as_uint(hi.z); qf[kk0 + 1][3] = __float_as_uint(hi.w);
    }

    float o[8][4];
#pragma unroll
    for (int a = 0; a < 8; ++a)
#pragma unroll
        for (int b = 0; b < 4; ++b) o[a][b] = 0.f;
    float m0v = -1e30f, m1v = -1e30f, l0 = 0.f, l1 = 0.f;

    int src_lo = (lane & ~3) | (ci >> 1);
    int src_hi = src_lo + 2;
    bool odd = ci & 1;

    const float* Kg0 = g_k + (size_t)g * (TLEN * KD);
    const float* Vg0 = g_v + (size_t)g * (KD * TLEN);
    int nkt = qb + 1;

#define FLASH_ISSUE(kt_, buf_)                                                        \
    do {                                                                              \
        _Pragma("unroll")                                                             \
        for (int i_ = 0; i_ < 4; ++i_) {                                              \
            int f4 = tid + i_ * 256;                                                  \
            int row = f4 >> 4, chunk = f4 & 15;                                       \
            int swc = chunk ^ (row & 7);                                              \
            cp16(sb + (uint32_t)(((buf_) * 4096 + row * 64 + swc * 4) * 4),           \
                 Kg0 + (size_t)(kt_) * 4096 + row * 64 + chunk * 4);                  \
            cp16(sb + (uint32_t)(((8192 + (buf_) * 4096) + row * 64 + swc * 4) * 4),  \
                 Vg0 + (size_t)row * TLEN + (kt_) * 64 + chunk * 4);                  \
        }                                                                             \
        CPCOMMIT();                                                                   \
    } while (0)

    FLASH_ISSUE(0, 0);
    for (int kt = 0; kt < nkt; ++kt) {
        int k0 = kt * 64;
        if (kt + 1 < nkt) { FLASH_ISSUE(kt + 1, (kt + 1) & 1); CPWAIT1(); }
        else CPWAIT0();
        __syncthreads();
        const float* Ks = sm + (kt & 1) * 4096;
        const float* Vs = sm + 8192 + (kt & 1) * 4096;
        if (k0 <= qbase + 15) {
            // S = Q K^T : per ni, 4 LDS128 + 8 MMA
            float s[8][4];
#pragma unroll
            for (int ni = 0; ni < 8; ++ni) {
                s[ni][0] = s[ni][1] = s[ni][2] = s[ni][3] = 0.f;
                int key = ni * 8 + gi;
                const uint32_t* Krow = (const uint32_t*)(Ks + key * 64);
                int sw = key & 7;
#pragma unroll
                for (int t4 = 0; t4 < 4; ++t4) {
                    int chunk = 2 * ci + (t4 & 1) + ((t4 >> 1) << 3);
                    uint4 F = *(const uint4*)(Krow + ((chunk ^ sw) << 2));
                    int kk0 = ((t4 >> 1) << 2) + ((t4 & 1) << 1);
                    mma8(s[ni], qf[kk0][0], qf[kk0][1], qf[kk0][2], qf[kk0][3], F.x, F.y);
                    mma8(s[ni], qf[kk0 + 1][0], qf[kk0 + 1][1], qf[kk0 + 1][2], qf[kk0 + 1][3], F.z, F.w);
                }
            }
            if (k0 + 63 > qbase) {   // diagonal tile: causal mask
#pragma unroll
                for (int ni = 0; ni < 8; ++ni)
#pragma unroll
                    for (int j = 0; j < 4; ++j) {
                        int col = k0 + ni * 8 + 2 * ci + (j & 1);
                        int row = r0 + ((j >= 2) ? 8 : 0);
                        if (col > row) s[ni][j] = -1e30f;
                    }
            }
            // online softmax
            float mx0 = -1e30f, mx1 = -1e30f;
#pragma unroll
            for (int ni = 0; ni < 8; ++ni) {
                mx0 = fmaxf(mx0, fmaxf(s[ni][0], s[ni][1]));
                mx1 = fmaxf(mx1, fmaxf(s[ni][2], s[ni][3]));
            }
            mx0 = fmaxf(mx0, __shfl_xor_sync(0xffffffffu, mx0, 1));
            mx0 = fmaxf(mx0, __shfl_xor_sync(0xffffffffu, mx0, 2));
            mx1 = fmaxf(mx1, __shfl_xor_sync(0xffffffffu, mx1, 1));
            mx1 = fmaxf(mx1, __shfl_xor_sync(0xffffffffu, mx1, 2));
            float m0n = fmaxf(m0v, mx0), m1n = fmaxf(m1v, mx1);
            float corr0 = __expf(m0v - m0n), corr1 = __expf(m1v - m1n);

            float sum0 = 0.f, sum1 = 0.f;
#pragma unroll
            for (int ni = 0; ni < 8; ++ni) {
                s[ni][0] = tf32r(__expf(s[ni][0] - m0n));
                s[ni][1] = tf32r(__expf(s[ni][1] - m0n));
                s[ni][2] = tf32r(__expf(s[ni][2] - m1n));
                s[ni][3] = tf32r(__expf(s[ni][3] - m1n));
                sum0 += s[ni][0] + s[ni][1];
                sum1 += s[ni][2] + s[ni][3];
            }
            sum0 += __shfl_xor_sync(0xffffffffu, sum0, 1);
            sum0 += __shfl_xor_sync(0xffffffffu, sum0, 2);
            sum1 += __shfl_xor_sync(0xffffffffu, sum1, 1);
            sum1 += __shfl_xor_sync(0xffffffffu, sum1, 2);
            l0 = l0 * corr0 + sum0;
            l1 = l1 * corr1 + sum1;
            m0v = m0n; m1v = m1n;
#pragma unroll
            for (int nd = 0; nd < 8; ++nd) {
                o[nd][0] *= corr0; o[nd][1] *= corr0;
                o[nd][2] *= corr1; o[nd][3] *= corr1;
            }
            // P C-layout -> A-fragments, in place (reuse s registers)
#pragma unroll
            for (int kg = 0; kg < 8; ++kg) {
                float v00 = __shfl_sync(0xffffffffu, s[kg][0], src_lo);
                float v01 = __shfl_sync(0xffffffffu, s[kg][1], src_lo);
                float v10 = __shfl_sync(0xffffffffu, s[kg][2], src_lo);
                float v11 = __shfl_sync(0xffffffffu, s[kg][3], src_lo);
                float w00 = __shfl_sync(0xffffffffu, s[kg][0], src_hi);
                float w01 = __shfl_sync(0xffffffffu, s[kg][1], src_hi);
                float w10 = __shfl_sync(0xffffffffu, s[kg][2], src_hi);
                float w11 = __shfl_sync(0xffffffffu, s[kg][3], src_hi);
                s[kg][0] = odd ? v01 : v00;
                s[kg][1] = odd ? v11 : v10;
                s[kg][2] = odd ? w01 : w00;
                s[kg][3] = odd ? w11 : w10;
            }
            // P @ V : per nd, 4 LDS128 + 8 MMA
#pragma unroll
            for (int nd = 0; nd < 8; ++nd) {
                int row = nd * 8 + gi;
                const uint32_t* Vrow = (const uint32_t*)(Vs + row * 64);
                int sw = row & 7;
#pragma unroll
                for (int t4 = 0; t4 < 4; ++t4) {
                    int chunk = 2 * ci + (t4 & 1) + ((t4 >> 1) << 3);
                    uint4 F = *(const uint4*)(Vrow + ((chunk ^ sw) << 2));
                    int kg0 = ((t4 >> 1) << 2) + ((t4 & 1) << 1);
                    mma8(o[nd], __float_as_uint(s[kg0][0]), __float_as_uint(s[kg0][1]),
                         __float_as_uint(s[kg0][2]), __float_as_uint(s[kg0][3]), F.x, F.y);
                    mma8(o[nd], __float_as_uint(s[kg0 + 1][0]), __float_as_uint(s[kg0 + 1][1]),
                         __float_as_uint(s[kg0 + 1][2]), __float_as_uint(s[kg0 + 1][3]), F.z, F.w);
                }
            }
        }
        __syncthreads();
    }
#undef FLASH_ISSUE

    float inv0 = 1.f / l0, inv1 = 1.f / l1;
    float* Og = g_og + (size_t)g * (TLEN * KD);
#pragma unroll
    for (int nd = 0; nd < 8; ++nd) {
        int c = nd * 8 + 2 * ci;
        float2 t0; t0.x = o[nd][0] * inv0; t0.y = o[nd][1] * inv0;
        float2 t1; t1.x = o[nd][2] * inv1; t1.y = o[nd][3] * inv1;
        *(float2*)&Og[(size_t)r0 * KD + c] = t0;
        *(float2*)&Og[(size_t)(r0 + 8) * KD + c] = t1;
    }
}

// ---------------- local windowed causal attention ------------------------------
__global__ __launch_bounds__(256) void local_attn_kernel()
{
    int g = blockIdx.x;
    int tjbase = blockIdx.y * 64;
    int lane = threadIdx.x & 31;
    int w = threadIdx.x >> 5;
    const float* Lg = g_l + (size_t)g * (TLEN * KD);
    float* Og = g_ol + (size_t)g * (TLEN * KD);
    for (int qi = 0; qi < 8; ++qi) {
        int tj = tjbase + w * 8 + qi;
        float a0 = Lg[tj * 64 + lane];
        float a1 = Lg[tj * 64 + lane + 32];
        float s[6];
        float mx = -1e30f;
#pragma unroll
        for (int wv = 0; wv < 6; ++wv) {
            int tp = tj - 5 + wv;
            float sc = -1e30f;
            if (tp >= 0) {
                float p = a0 * Lg[tp * 64 + lane] + a1 * Lg[tp * 64 + lane + 32];
#pragma unroll
                for (int o = 16; o; o >>= 1) p += __shfl_xor_sync(0xffffffffu, p, o);
                sc = p * 0.125f;
            }
            s[wv] = sc;
            mx = fmaxf(mx, sc);
        }
        float den = 0.f, o0 = 0.f, o1 = 0.f;
#pragma unroll
        for (int wv = 0; wv < 6; ++wv) {
            int tp = tj - 5 + wv;
            if (tp >= 0) {
                float pp = expf(s[wv] - mx);
                den += pp;
                o0 += pp * Lg[tp * 64 + lane];
                o1 += pp * Lg[tp * 64 + lane + 32];
            }
        }
        float inv = 1.f / den;
        Og[tj * 64 + lane] = o0 * inv;
        Og[tj * 64 + lane + 32] = o1 * inv;
    }
}

// ---------------- uni projection: fused gating + K-split tf32 GEMM -------------
__global__ __launch_bounds__(256, 2) void unigemm_kernel()
{
    __shared__ float As[128][36];
    __shared__ float Bs[32][68];
    int tid = threadIdx.x, lane = tid & 31, wid = tid >> 5;
    int wm = wid & 3, wn = wid >> 2, gi = lane >> 2, ci = lane & 3;
    int m0 = blockIdx.x * 128;
    int kz = blockIdx.y;
    int bi = m0 >> 10, tib = m0 & 1023;
    uint32_t b_sb = (uint32_t)__cvta_generic_to_shared(&Bs[0][0]);

    float acc[2][4][4];
#pragma unroll
    for (int a = 0; a < 2; ++a)
#pragma unroll
        for (int b = 0; b < 4; ++b)
#pragma unroll
            for (int c = 0; c < 4; ++c) acc[a][b][c] = 0.f;

    for (int s = 0; s < 8; ++s) {
        int k0 = kz * 256 + s * 32;
        int ch = k0 >> 6, ki0 = k0 & 63;
        int h2 = ch & 7;
        bool lohalf = ch < 8;
        const float* Og = g_og + (size_t)(bi * 8 + h2) * (TLEN * KD);
        const float* Lg = g_ol + (size_t)(bi * 8 + h2) * (TLEN * KD);
        __syncthreads();
#pragma unroll
        for (int i = 0; i < 2; ++i) {
            int f4 = tid + i * 256;
            int row = f4 >> 4, c4 = (f4 & 15) << 2;
            cp16(b_sb + (uint32_t)((row * 68 + c4) * 4), g_WU + (size_t)(k0 + row) * 64 + c4);
        }
        CPCOMMIT();
#pragma unroll
        for (int i = 0; i < 4; ++i) {
            int f4 = tid + i * 256;
            int row = f4 >> 3, c4 = (f4 & 7) << 2;
            int ti2 = tib + row;
            const float4 o4 = *(const float4*)(Og + (size_t)ti2 * 64 + ki0 + c4);
            const float4 l4 = *(const float4*)(Lg + (size_t)ti2 * 64 + ki0 + c4);
            float g0 = sigmoid_fast(o4.x), g1 = sigmoid_fast(o4.y);
            float g2 = sigmoid_fast(o4.z), g3 = sigmoid_fast(o4.w);
            float r0 = lohalf ? (1.f - g0) * l4.x : g0 * o4.x;
            float r1 = lohalf ? (1.f - g1) * l4.y : g1 * o4.y;
            float r2 = lohalf ? (1.f - g2) * l4.z : g2 * o4.z;
            float r3 = lohalf ? (1.f - g3) * l4.w : g3 * o4.w;
            As[row][c4 + 0] = tf32r(r0);
            As[row][c4 + 1] = tf32r(r1);
            As[row][c4 + 2] = tf32r(r2);
            As[row][c4 + 3] = tf32r(r3);
        }
        CPWAIT0();
        __syncthreads();
#pragma unroll
        for (int kk = 0; kk < 4; ++kk) {
            int k = kk * 8;
            uint32_t af[2][4];
#pragma unroll
            for (int mi = 0; mi < 2; ++mi) {
                int r = wm * 32 + mi * 16 + gi;
                af[mi][0] = __float_as_uint(As[r][k + ci]);
                af[mi][1] = __float_as_uint(As[r + 8][k + ci]);
                af[mi][2] = __float_as_uint(As[r][k + ci + 4]);
                af[mi][3] = __float_as_uint(As[r + 8][k + ci + 4]);
            }
            uint32_t bf[4][2];
#pragma unroll
            for (int ni = 0; ni < 4; ++ni) {
                int n = wn * 32 + ni * 8 + gi;
                bf[ni][0] = __float_as_uint(Bs[k + ci][n]);
                bf[ni][1] = __float_as_uint(Bs[k + ci + 4][n]);
            }
#pragma unroll
            for (int mi = 0; mi < 2; ++mi)
#pragma unroll
                for (int ni = 0; ni < 4; ++ni)
                    mma8(acc[mi][ni], af[mi][0], af[mi][1], af[mi][2], af[mi][3],
                         bf[ni][0], bf[ni][1]);
        }
    }

    float* P = g_part + ((size_t)kz * MROWS + m0) * 64;
#pragma unroll
    for (int mi = 0; mi < 2; ++mi)
#pragma unroll
        for (int ni = 0; ni < 4; ++ni)
#pragma unroll
            for (int j = 0; j < 4; j += 2) {
                int mrow = wm * 32 + mi * 16 + gi + ((j >= 2) ? 8 : 0);
                int n = wn * 32 + ni * 8 + 2 * ci;
                float2 t; t.x = acc[mi][ni][j]; t.y = acc[mi][ni][j + 1];
                *(float2*)&P[(size_t)mrow * 64 + n] = t;
            }
}

// ---------------- partial-reduce + silu + residual -> LN1 -> FF -> LN2 ---------
__global__ __launch_bounds__(256) void ffln_kernel(
    const float* __restrict__ uni_b,
    const float* __restrict__ ln1g, const float* __restrict__ ln1b,
    const float* __restrict__ ln2g, const float* __restrict__ ln2b,
    const float* __restrict__ w1, const float* __restrict__ b1,
    const float* __restrict__ w2, const float* __restrict__ b2,
    float* __restrict__ out)
{
    const int R = 16;
    __shared__ float yl[R][64];
    __shared__ float hs[R][256];
    __shared__ float fs[R][64];
    int r0 = blockIdx.x * R;
    int tid = threadIdx.x;
    int lane = tid & 31, w = tid >> 5;

    for (int rr = 0; rr < 2; ++rr) {
        int r = w * 2 + rr;
        size_t rg = (size_t)(r0 + r) * 64;
        float v0 = g_part[rg + lane] + g_part[(size_t)MROWS * 64 + rg + lane] +
                   g_part[(size_t)MROWS * 128 + rg + lane] + g_part[(size_t)MROWS * 192 + rg + lane];
        float v1 = g_part[rg + lane + 32] + g_part[(size_t)MROWS * 64 + rg + lane + 32] +
                   g_part[(size_t)MROWS * 128 + rg + lane + 32] + g_part[(size_t)MROWS * 192 + rg + lane + 32];
        v0 = silu_fast(v0 + uni_b[lane]) + g_xin[rg + lane];
        v1 = silu_fast(v1 + uni_b[lane + 32]) + g_xin[rg + lane + 32];
        float sm = v0 + v1;
#pragma unroll
        for (int o = 16; o; o >>= 1) sm += __shfl_xor_sync(0xffffffffu, sm, o);
        float mean = sm * (1.f / 64.f);
        float d0 = v0 - mean, d1 = v1 - mean;
        float vs = d0 * d0 + d1 * d1;
#pragma unroll
        for (int o = 16; o; o >>= 1) vs += __shfl_xor_sync(0xffffffffu, vs, o);
        float inv = rsqrtf(vs * (1.f / 64.f) + 1e-5f);
        yl[r][lane]      = d0 * inv * ln1g[lane] + ln1b[lane];
        yl[r][lane + 32] = d1 * inv * ln1g[lane + 32] + ln1b[lane + 32];
    }
    __syncthreads();

    {
        float acc[R];
#pragma unroll
        for (int r = 0; r < R; ++r) acc[r] = b1[tid];
        for (int c = 0; c < 64; ++c) {
            float wv = w1[c * 256 + tid];
#pragma unroll
            for (int r = 0; r < R; ++r) acc[r] += yl[r][c] * wv;
        }
#pragma unroll
        for (int r = 0; r < R; ++r) hs[r][tid] = fmaxf(acc[r], 0.f);
    }
    __syncthreads();

    {
        int j2 = tid & 63, rg = tid >> 6;
        float acc[4];
#pragma unroll
        for (int rr = 0; rr < 4; ++rr) acc[rr] = b2[j2];
        for (int c = 0; c < 256; ++c) {
            float wv = w2[c * 64 + j2];
#pragma unroll
            for (int rr = 0; rr < 4; ++rr) acc[rr] += hs[rg * 4 + rr][c] * wv;
        }
#pragma unroll
        for (int rr = 0; rr < 4; ++rr) fs[rg * 4 + rr][j2] = acc[rr] + yl[rg * 4 + rr][j2];
    }
    __syncthreads();

    for (int rr = 0; rr < 2; ++rr) {
        int r = w * 2 + rr;
        float v0 = fs[r][lane], v1 = fs[r][lane + 32];
        float sm = v0 + v1;
#pragma unroll
        for (int o = 16; o; o >>= 1) sm += __shfl_xor_sync(0xffffffffu, sm, o);
        float mean = sm * (1.f / 64.f);
        float d0 = v0 - mean, d1 = v1 - mean;
        float vs = d0 * d0 + d1 * d1;
#pragma unroll
        for (int o = 16; o; o >>= 1) vs += __shfl_xor_sync(0xffffffffu, vs, o);
        float inv = rsqrtf(vs * (1.f / 64.f) + 1e-5f);
        float* orow = out + (size_t)(r0 + r) * 64;
        orow[lane]      = d0 * inv * ln2g[lane] + ln2b[lane];
        orow[lane + 32] = d1 * inv * ln2g[lane + 32] + ln2b[lane + 32];
    }
}

// ---------------- launch ---------------------------------------------------------
extern "C" void kernel_launch(void* const* d_in, const int* in_sizes, int n_in,
                              void* d_out, int out_size)
{
    (void)in_sizes; (void)n_in; (void)out_size;
    const float* x       = (const float*)d_in[0];
    const float* sq_w    = (const float*)d_in[1];
    const float* bn_g    = (const float*)d_in[2];
    const float* bn_b    = (const float*)d_in[3];
    const float* dw_w    = (const float*)d_in[4];
    const float* ex_w    = (const float*)d_in[5];
    const float* pos_emb = (const float*)d_in[6];
    const float* wq      = (const float*)d_in[7];
    const float* bq      = (const float*)d_in[8];
    const float* wk      = (const float*)d_in[9];
    const float* bk      = (const float*)d_in[10];
    const float* wv      = (const float*)d_in[11];
    const float* wl      = (const float*)d_in[12];
    const float* uni_w   = (const float*)d_in[13];
    const float* uni_b   = (const float*)d_in[14];
    const float* ln1_g   = (const float*)d_in[15];
    const float* ln1_b   = (const float*)d_in[16];
    const float* ln2_g   = (const float*)d_in[17];
    const float* ln2_b   = (const float*)d_in[18];
    const float* ff_w1   = (const float*)d_in[19];
    const float* ff_b1   = (const float*)d_in[20];
    const float* ff_w2   = (const float*)d_in[21];
    const float* ff_b2   = (const float*)d_in[22];
    float* out = (float*)d_out;

    const int CONV_SMEM  = (2 * 128 * 36 + 2 * 32 * 68) * 4;   // 54272
    const int FLASH_SMEM = 4 * 64 * 64 * 4;                    // 65536
    cudaFuncSetAttribute(convgemm_kernel, cudaFuncAttributeMaxDynamicSharedMemorySize, CONV_SMEM);
    cudaFuncSetAttribute(flash_mma_kernel, cudaFuncAttributeMaxDynamicSharedMemorySize, FLASH_SMEM);

    fused_xin_kernel<<<dim3(4, 32), 256>>>(x, sq_w, bn_g, bn_b, dw_w, ex_w, pos_emb);
    prep_w_kernel<<<1792, 256>>>(wq, wk, wv, wl, uni_w);

    convgemm_kernel<<<dim3(32, 16, 2), 256, CONV_SMEM>>>(bq, bk);

    flash_mma_kernel<<<dim3(32, 8), 256, FLASH_SMEM>>>();
    local_attn_kernel<<<dim3(32, 16), 256>>>();

    unigemm_kernel<<<dim3(32, 4), 256>>>();

    ffln_kernel<<<256, 256>>>(uni_b, ln1_g, ln1_b, ln2_g, ln2_b,
                              ff_w1, ff_b1, ff_w2, ff_b2, out);
}

// round 7
// speedup vs baseline: 3.3391x; 1.0093x over previous
#include <cuda_runtime.h>
#include <math.h>
#include <stdint.h>

// Problem constants (fixed by setup_inputs)
#define BATCH 4
#define TLEN  1024
#define KD    64
#define HNUM  8
#define R32   32
#define NSEQ  32      // BATCH*HNUM
#define MROWS 4096    // BATCH*TLEN

// ---------------- scratch (static device globals; no allocation) --------------
__device__ float g_xin[BATCH * TLEN * KD];          // tf32-exact
__device__ float g_WB[320 * 1024];                  // tap-major reordered wq|wk, tf32-exact
__device__ float g_WB2[64 * 1024];                  // wv|wl transposed, tf32-exact
__device__ float g_WU[1024 * 64];                   // uni_w, tf32-exact
__device__ float g_q[NSEQ * TLEN * KD];             // [g][t][p64(d)] tf32-exact
__device__ float g_k[NSEQ * TLEN * KD];             // [g][t][p64(d)]
__device__ float g_v[NSEQ * KD * TLEN];             // [g][d][t: 32-tilewise p32(key)]
__device__ float g_l[NSEQ * TLEN * KD];             // natural
__device__ float g_og[NSEQ * TLEN * KD];
__device__ float g_ol[NSEQ * TLEN * KD];
__device__ float g_part[4 * MROWS * KD];            // uni GEMM K-split partials

__device__ __forceinline__ float sigmoid_exact(float x) { return 1.f / (1.f + expf(-x)); }
__device__ __forceinline__ float sigmoid_fast(float x) {
    float t;
    asm("tanh.approx.f32 %0, %1;" : "=f"(t) : "f"(0.5f * x));
    return 0.5f * t + 0.5f;
}
__device__ __forceinline__ float silu_fast(float x) { return x * sigmoid_fast(x); }

// round f32 -> nearest tf32 (result is a valid f32 with low mantissa zeroed)
__device__ __forceinline__ float tf32r(float x) {
    uint32_t u;
    asm("cvt.rna.tf32.f32 %0, %1;" : "=r"(u) : "f"(x));
    return __uint_as_float(u);
}

// fragment-vectorization permutation of a 64-long contraction dim (Q/K d-dim)
__device__ __forceinline__ int pqk(int k) {
    return ((k & 3) << 3) | ((k >> 5) << 5) | (((k >> 4) & 1) << 2) |
           (((k >> 3) & 1) << 1) | ((k >> 2) & 1);
}
// same idea for a 32-long contraction dim (V key-dim within 32-key tiles):
// slot kappa = 8*kg + ci + 4*v (kg=2u+w) -> word = ci<<3 | u<<2 | w<<1 | v
__device__ __forceinline__ int p32(int t) {
    return ((t & 3) << 3) | (((t >> 4) & 1) << 2) | (((t >> 3) & 1) << 1) | ((t >> 2) & 1);
}

__device__ __forceinline__ void mma8(float* c,
                                     uint32_t a0, uint32_t a1, uint32_t a2, uint32_t a3,
                                     uint32_t b0, uint32_t b1) {
    asm volatile(
        "mma.sync.aligned.m16n8k8.row.col.f32.tf32.tf32.f32 "
        "{%0,%1,%2,%3}, {%4,%5,%6,%7}, {%8,%9}, {%0,%1,%2,%3};"
        : "+f"(c[0]), "+f"(c[1]), "+f"(c[2]), "+f"(c[3])
        : "r"(a0), "r"(a1), "r"(a2), "r"(a3), "r"(b0), "r"(b1));
}

__device__ __forceinline__ void cp16(uint32_t dst, const void* src) {
    asm volatile("cp.async.ca.shared.global [%0], [%1], 16;" :: "r"(dst), "l"(src) : "memory");
}
__device__ __forceinline__ void cp16p(uint32_t dst, const void* src, int sz) {
    asm volatile("cp.async.ca.shared.global [%0], [%1], 16, %2;" :: "r"(dst), "l"(src), "r"(sz) : "memory");
}
#define CPCOMMIT() asm volatile("cp.async.commit_group;" ::: "memory")
#define CPWAIT0()  asm volatile("cp.async.wait_group 0;" ::: "memory")
#define CPWAIT1()  asm volatile("cp.async.wait_group 1;" ::: "memory")

// ================= fused action + pos_emb -> xin (tf32-exact) ==================
__global__ __launch_bounds__(256) void fused_xin_kernel(
    const float* __restrict__ x, const float* __restrict__ sq_w,
    const float* __restrict__ bn_g, const float* __restrict__ bn_b,
    const float* __restrict__ dw_w, const float* __restrict__ ex_w,
    const float* __restrict__ pos_emb)
{
    __shared__ float xs[34][68];
    __shared__ float x3s[34][36];
    __shared__ float xp3[32][32];
    __shared__ float sqT[64][32];
    __shared__ float exT[32][64];
    __shared__ float bng_s[32], bnb_s[32];

    int bi = blockIdx.x;
    int t0 = blockIdx.y * 32;
    int tid = threadIdx.x;
    int nrows = min(34, TLEN - t0);

    for (int i = tid; i < nrows * 16; i += 256) {
        int row = i >> 4, c4 = (i & 15) << 2;
        *(float4*)&xs[row][c4] = *(const float4*)&x[((size_t)bi * TLEN + t0 + row) * KD + c4];
    }
    for (int i = tid; i < 2048; i += 256) { int r = i >> 6, c = i & 63; sqT[c][r] = sq_w[i]; }
    for (int i = tid; i < 2048; i += 256) { int c = i >> 5, r = i & 31; exT[r][c] = ex_w[i]; }
    if (tid < 32) { bng_s[tid] = bn_g[tid] * 0.9999950000374997f; bnb_s[tid] = bn_b[tid]; }
    __syncthreads();

    {
        int j = tid >> 2, rg = (tid & 3) << 3;
        if (j < nrows) {
            float acc[8];
#pragma unroll
            for (int i = 0; i < 8; ++i) acc[i] = 0.f;
#pragma unroll
            for (int c4 = 0; c4 < 64; c4 += 4) {
                float4 xv = *(const float4*)&xs[j][c4];
#pragma unroll
                for (int t = 0; t < 4; ++t) {
                    float xc = (t == 0) ? xv.x : (t == 1) ? xv.y : (t == 2) ? xv.z : xv.w;
                    float4 s0 = *(const float4*)&sqT[c4 + t][rg];
                    float4 s1 = *(const float4*)&sqT[c4 + t][rg + 4];
                    acc[0] += xc * s0.x; acc[1] += xc * s0.y;
                    acc[2] += xc * s0.z; acc[3] += xc * s0.w;
                    acc[4] += xc * s1.x; acc[5] += xc * s1.y;
                    acc[6] += xc * s1.z; acc[7] += xc * s1.w;
                }
            }
#pragma unroll
            for (int i = 0; i < 8; ++i)
                x3s[j][rg + i] = acc[i] * bng_s[rg + i] + bnb_s[rg + i];
        }
    }
    __syncthreads();

    for (int idx = tid; idx < 32 * 32; idx += 256) {
        int r = idx & 31, jj = idx >> 5;
        int pos = t0 + jj;
        float base = x3s[jj][r];
        float v;
        if (pos == TLEN - 1) {
            v = base;
        } else {
            float d0 = dw_w[r * 3 + 0], d1 = dw_w[r * 3 + 1], d2 = dw_w[r * 3 + 2];
            float a = base * d0 + x3s[jj + 1][r] * d1 +
                      ((pos + 2 < TLEN) ? x3s[jj + 2][r] * d2 : 0.f);
            v = a - base;
        }
        xp3[jj][r] = v;
    }
    __syncthreads();

    for (int idx = tid; idx < 32 * 64; idx += 256) {
        int c = idx & 63, j = idx >> 6;
        int pos = t0 + j;
        float gsum = 0.f;
#pragma unroll
        for (int r = 0; r < R32; ++r) gsum += xp3[j][r] * exT[r][c];
        float sig = sigmoid_exact(gsum);
        size_t off = ((size_t)bi * TLEN + pos) * KD + c;
        g_xin[off] = tf32r(xs[j][c] * sig + pos_emb[pos * KD + c]);
    }
}

// ---------------- weight prep (reorder + tf32 round, single kernel) ------------
__global__ __launch_bounds__(256) void prep_w_kernel(
    const float* __restrict__ wq, const float* __restrict__ wk,
    const float* __restrict__ wv, const float* __restrict__ wl,
    const float* __restrict__ uni_w)
{
    int idx = blockIdx.x * 256 + threadIdx.x;
    if (idx < 320 * 1024) {
        int n = idx & 1023, kcol = idx >> 10;
        int mm = kcol >> 6, c = kcol & 63;
        float w = (n < 512) ? wq[n * 320 + c * 5 + mm] : wk[(n - 512) * 320 + c * 5 + mm];
        g_WB[idx] = tf32r(w);
    } else if (idx < 320 * 1024 + 65536) {
        int j = idx - 320 * 1024;
        int n = j & 1023, c = j >> 10;
        g_WB2[j] = tf32r((n < 512) ? wv[n * 64 + c] : wl[(n - 512) * 64 + c]);
    } else if (idx < 320 * 1024 + 131072) {
        int j = idx - (320 * 1024 + 65536);
        g_WU[j] = tf32r(uni_w[j]);
    }
}

// ---------------- conv GEMMs (tf32 mma, cp.async dbl-buffered, mode=blockIdx.z) --
__global__ __launch_bounds__(256, 2) void convgemm_kernel(
    const float* __restrict__ bias0, const float* __restrict__ bias1)
{
    int mode = blockIdx.z;
    const int NSTAGE = (mode == 0) ? 10 : 2;
    extern __shared__ float sm[];
    float* As = sm;                   // [2][128][36]
    float* Bs = sm + 2 * 128 * 36;    // [2][32][68]
    const float* __restrict__ Bg = (mode == 0) ? g_WB : g_WB2;

    int tid = threadIdx.x, lane = tid & 31, wid = tid >> 5;
    int wm = wid & 3, wn = wid >> 2, gi = lane >> 2, ci = lane & 3;
    int m0 = blockIdx.x * 128, n0 = blockIdx.y * 64;
    int bi = m0 >> 10, tibase = m0 & 1023;
    uint32_t sb = (uint32_t)__cvta_generic_to_shared(sm);
    uint32_t a_sb = sb, b_sb = sb + 2 * 128 * 36 * 4;

    auto issue_stage = [&](int s_, int buf_) {
        int mm_ = (mode == 0) ? (s_ >> 1) : 0;
        int c0_ = (mode == 0) ? ((s_ & 1) << 5) : (s_ << 5);
        int sh_ = (mode == 0) ? (2 * mm_ - 8) : 0;
#pragma unroll
        for (int i_ = 0; i_ < 4; ++i_) {
            int f4 = tid + i_ * 256;
            int row = f4 >> 3, c4 = (f4 & 7) << 2;
            int tsrc = tibase + row + sh_;
            const float* srcp = g_xin + ((size_t)(bi << 10) + tsrc) * 64 + c0_ + c4;
            uint32_t dstp = a_sb + (uint32_t)((buf_ * 4608 + row * 36 + c4) * 4);
            cp16p(dstp, srcp, (tsrc >= 0) ? 16 : 0);
        }
#pragma unroll
        for (int i_ = 0; i_ < 2; ++i_) {
            int f4 = tid + i_ * 256;
            int row = f4 >> 4, c4 = (f4 & 15) << 2;
            const float* srcp = Bg + (size_t)(s_ * 32 + row) * 1024 + n0 + c4;
            uint32_t dstp = b_sb + (uint32_t)((buf_ * 2176 + row * 68 + c4) * 4);
            cp16(dstp, srcp);
        }
        CPCOMMIT();
    };

    float acc[2][4][4];
#pragma unroll
    for (int a = 0; a < 2; ++a)
#pragma unroll
        for (int b = 0; b < 4; ++b)
#pragma unroll
            for (int c = 0; c < 4; ++c) acc[a][b][c] = 0.f;

    issue_stage(0, 0);
    for (int s = 0; s < NSTAGE; ++s) {
        if (s + 1 < NSTAGE) { issue_stage(s + 1, (s + 1) & 1); CPWAIT1(); }
        else CPWAIT0();
        __syncthreads();
        const float* Ab = As + (s & 1) * 4608;
        const float* Bb = Bs + (s & 1) * 2176;
#pragma unroll
        for (int kk = 0; kk < 4; ++kk) {
            int k = kk * 8;
            uint32_t af[2][4];
#pragma unroll
            for (int mi = 0; mi < 2; ++mi) {
                int r = wm * 32 + mi * 16 + gi;
                af[mi][0] = __float_as_uint(Ab[r * 36 + k + ci]);
                af[mi][1] = __float_as_uint(Ab[(r + 8) * 36 + k + ci]);
                af[mi][2] = __float_as_uint(Ab[r * 36 + k + ci + 4]);
                af[mi][3] = __float_as_uint(Ab[(r + 8) * 36 + k + ci + 4]);
            }
            uint32_t bf[4][2];
#pragma unroll
            for (int ni = 0; ni < 4; ++ni) {
                int n = wn * 32 + ni * 8 + gi;
                bf[ni][0] = __float_as_uint(Bb[(k + ci) * 68 + n]);
                bf[ni][1] = __float_as_uint(Bb[(k + ci + 4) * 68 + n]);
            }
#pragma unroll
            for (int mi = 0; mi < 2; ++mi)
#pragma unroll
                for (int ni = 0; ni < 4; ++ni)
                    mma8(acc[mi][ni], af[mi][0], af[mi][1], af[mi][2], af[mi][3],
                         bf[ni][0], bf[ni][1]);
        }
        __syncthreads();
    }

#pragma unroll
    for (int mi = 0; mi < 2; ++mi)
#pragma unroll
        for (int ni = 0; ni < 4; ++ni)
#pragma unroll
            for (int j = 0; j < 4; ++j) {
                int m = m0 + wm * 32 + mi * 16 + gi + ((j >= 2) ? 8 : 0);
                int n = n0 + wn * 32 + ni * 8 + 2 * ci + (j & 1);
                float v = acc[mi][ni][j];
                int o = n & 511, ki = o >> 3, h = o & 7;
                int bb = m >> 10, ti = m & 1023;
                int gg = bb * 8 + (ti >> 7);
                int tj = ((ti & 127) << 3) | h;
                if (mode == 0) {
                    float bias = (n < 512) ? bias0[n] : bias1[n - 512];
                    float s = silu_fast(v + bias) * 0.35355339059327373f;  // / 64^0.25
                    float* dst = (n < 512) ? g_q : g_k;
                    dst[((size_t)gg * TLEN + tj) * KD + pqk(ki)] = tf32r(s);
                } else {
                    float s = silu_fast(v);
                    if (n < 512) {
                        g_v[((size_t)gg * KD + ki) * TLEN + (tj & ~31) + p32(tj & 31)] = tf32r(s);
                    } else {
                        g_l[((size_t)gg * TLEN + tj) * KD + ki] = tf32r(s);
                    }
                }
            }
}

// ---------------- flash attention v3: decoupled warp-group k-streams -----------
// block (g, p): group A (warps 0-3) does q-tile p fully (2p+2 32-key tiles) then
// q-tile 15-p keys 544.. (15-2p tiles); group B (warps 4-7) does q-tile 15-p keys
// 0..543 (17 tiles). Both groups: exactly 17 lockstep iterations; split-KV merge
// for q-tile 15-p at the end via smem.
__global__ __launch_bounds__(256, 2) void flash_mma_kernel()
{
    extern __shared__ float sm[];   // [A: K[2][2048] V[2][2048] | B: same] = 16384 floats
    int g  = blockIdx.x;
    int p  = blockIdx.y;
    int qa = p, qb = 15 - p;
    int tid = threadIdx.x, lane = tid & 31, wid = tid >> 5;
    int gi = lane >> 2, ci = lane & 3;
    int wa = wid & 3;
    bool grpB = wid >= 4;
    int Na = 2 * p + 2;
    uint32_t sb = (uint32_t)__cvta_generic_to_shared(sm);
    int gK = grpB ? 8192 : 0;
    int gV = gK + 4096;
    int lt = wa * 32 + lane;        // 0..127 within group

    const float* Qg  = g_q + (size_t)g * (TLEN * KD);
    const float* Kg0 = g_k + (size_t)g * (TLEN * KD);
    const float* Vg0 = g_v + (size_t)g * (KD * TLEN);

    int qt = grpB ? qb : qa;
    int qbase = qt * 64 + wa * 16;
    int r0 = qbase + gi;

    uint32_t qf[8][4];
    auto load_qf = [&]() {
#pragma unroll
        for (int t4 = 0; t4 < 4; ++t4) {
            int woff = (2 * ci + (t4 & 1) + ((t4 >> 1) << 3)) << 2;
            float4 lo = *(const float4*)&Qg[(size_t)r0 * KD + woff];
            float4 hi = *(const float4*)&Qg[(size_t)(r0 + 8) * KD + woff];
            int kk0 = ((t4 >> 1) << 2) + ((t4 & 1) << 1);
            qf[kk0][0]     = __float_as_uint(lo.x); qf[kk0][2]     = __float_as_uint(lo.y);
            qf[kk0 + 1][0] = __float_as_uint(lo.z); qf[kk0 + 1][2] = __float_as_uint(lo.w);
            qf[kk0][1]     = __float_as_uint(hi.x); qf[kk0][3]     = __float_as_uint(hi.y);
            qf[kk0 + 1][1] = __float_as_uint(hi.z); qf[kk0 + 1][3] = __float_as_uint(hi.w);
        }
    };
    load_qf();

    float o[8][4];
#pragma unroll
    for (int a = 0; a < 8; ++a)
#pragma unroll
        for (int b = 0; b < 4; ++b) o[a][b] = 0.f;
    float m0v = -1e30f, m1v = -1e30f, l0 = 0.f, l1 = 0.f;

    int src_lo = (lane & ~3) | (ci >> 1);
    int src_hi = src_lo + 2;
    bool odd = ci & 1;

    // tile index i (0..16) -> absolute 32-key tile
    auto kt_of = [&](int i) {
        if (grpB) return i;
        return (i < Na) ? i : (17 + i - Na);
    };

    auto issue = [&](int i, int buf) {
        int k0 = kt_of(i) * 32;
#pragma unroll
        for (int j = 0; j < 4; ++j) {      // K: 32 rows x 16 chunks
            int f4 = lt + j * 128;
            int row = f4 >> 4, chunk = f4 & 15;
            int swc = chunk ^ (row & 7);
            cp16(sb + (uint32_t)((gK + buf * 2048 + row * 64 + swc * 4) * 4),
                 Kg0 + (size_t)(k0 + row) * 64 + chunk * 4);
        }
#pragma unroll
        for (int j = 0; j < 4; ++j) {      // V: 64 rows x 8 chunks
            int f4 = lt + j * 128;
            int row = f4 >> 3, chunk = f4 & 7;
            int swc = chunk ^ (row & 7);
            cp16(sb + (uint32_t)((gV + buf * 2048 + row * 32 + swc * 4) * 4),
                 Vg0 + (size_t)row * TLEN + k0 + chunk * 4);
        }
        CPCOMMIT();
    };

    auto epilogue_store = [&]() {
        float inv0 = 1.f / l0, inv1 = 1.f / l1;
        float* Og = g_og + (size_t)g * (TLEN * KD);
#pragma unroll
        for (int nd = 0; nd < 8; ++nd) {
            int c = nd * 8 + 2 * ci;
            float2 t0; t0.x = o[nd][0] * inv0; t0.y = o[nd][1] * inv0;
            float2 t1; t1.x = o[nd][2] * inv1; t1.y = o[nd][3] * inv1;
            *(float2*)&Og[(size_t)r0 * KD + c] = t0;
            *(float2*)&Og[(size_t)(r0 + 8) * KD + c] = t1;
        }
    };

    issue(0, 0);
    for (int i = 0; i < 17; ++i) {
        if (i + 1 < 17) { issue(i + 1, (i + 1) & 1); CPWAIT1(); }
        else CPWAIT0();
        __syncthreads();

        // group A: switch from qa to qb partial
        if (!grpB && i == Na) {
            epilogue_store();                 // finalize qa
#pragma unroll
            for (int a = 0; a < 8; ++a)
#pragma unroll
                for (int b = 0; b < 4; ++b) o[a][b] = 0.f;
            m0v = -1e30f; m1v = -1e30f; l0 = 0.f; l1 = 0.f;
            qt = qb; qbase = qt * 64 + wa * 16; r0 = qbase + gi;
            load_qf();
        }

        int k0 = kt_of(i) * 32;
        const float* Ks = sm + gK + (i & 1) * 2048;
        const float* Vs = sm + gV + (i & 1) * 2048;
        if (k0 <= qbase + 15) {
            // S = Q K^T : 16 x 32 per warp
            float s[4][4];
#pragma unroll
            for (int ni = 0; ni < 4; ++ni) {
                s[ni][0] = s[ni][1] = s[ni][2] = s[ni][3] = 0.f;
                int key = ni * 8 + gi;
                const uint32_t* Krow = (const uint32_t*)(Ks + key * 64);
                int sw = key & 7;
#pragma unroll
                for (int t4 = 0; t4 < 4; ++t4) {
                    int chunk = 2 * ci + (t4 & 1) + ((t4 >> 1) << 3);
                    uint4 F = *(const uint4*)(Krow + ((chunk ^ sw) << 2));
                    int kk0 = ((t4 >> 1) << 2) + ((t4 & 1) << 1);
                    mma8(s[ni], qf[kk0][0], qf[kk0][1], qf[kk0][2], qf[kk0][3], F.x, F.y);
                    mma8(s[ni], qf[kk0 + 1][0], qf[kk0 + 1][1], qf[kk0 + 1][2], qf[kk0 + 1][3], F.z, F.w);
                }
            }
            if (k0 + 31 > qbase) {           // masking needed
#pragma unroll
                for (int ni = 0; ni < 4; ++ni)
#pragma unroll
                    for (int j = 0; j < 4; ++j) {
                        int col = k0 + ni * 8 + 2 * ci + (j & 1);
                        int row = r0 + ((j >= 2) ? 8 : 0);
                        if (col > row) s[ni][j] = -1e30f;
                    }
            }
            // online softmax
            float mx0 = -1e30f, mx1 = -1e30f;
#pragma unroll
            for (int ni = 0; ni < 4; ++ni) {
                mx0 = fmaxf(mx0, fmaxf(s[ni][0], s[ni][1]));
                mx1 = fmaxf(mx1, fmaxf(s[ni][2], s[ni][3]));
            }
            mx0 = fmaxf(mx0, __shfl_xor_sync(0xffffffffu, mx0, 1));
            mx0 = fmaxf(mx0, __shfl_xor_sync(0xffffffffu, mx0, 2));
            mx1 = fmaxf(mx1, __shfl_xor_sync(0xffffffffu, mx1, 1));
            mx1 = fmaxf(mx1, __shfl_xor_sync(0xffffffffu, mx1, 2));
            float m0n = fmaxf(m0v, mx0), m1n = fmaxf(m1v, mx1);
            float corr0 = __expf(m0v - m0n), corr1 = __expf(m1v - m1n);

            float sum0 = 0.f, sum1 = 0.f;
#pragma unroll
            for (int ni = 0; ni < 4; ++ni) {
                s[ni][0] = tf32r(__expf(s[ni][0] - m0n));
                s[ni][1] = tf32r(__expf(s[ni][1] - m0n));
                s[ni][2] = tf32r(__expf(s[ni][2] - m1n));
                s[ni][3] = tf32r(__expf(s[ni][3] - m1n));
                sum0 += s[ni][0] + s[ni][1];
                sum1 += s[ni][2] + s[ni][3];
            }
            sum0 += __shfl_xor_sync(0xffffffffu, sum0, 1);
            sum0 += __shfl_xor_sync(0xffffffffu, sum0, 2);
            sum1 += __shfl_xor_sync(0xffffffffu, sum1, 1);
            sum1 += __shfl_xor_sync(0xffffffffu, sum1, 2);
            l0 = l0 * corr0 + sum0;
            l1 = l1 * corr1 + sum1;
            m0v = m0n; m1v = m1n;
#pragma unroll
            for (int nd = 0; nd < 8; ++nd) {
                o[nd][0] *= corr0; o[nd][1] *= corr0;
                o[nd][2] *= corr1; o[nd][3] *= corr1;
            }
            // P C-layout -> A-fragments in place (4 key groups)
#pragma unroll
            for (int kg = 0; kg < 4; ++kg) {
                float v00 = __shfl_sync(0xffffffffu, s[kg][0], src_lo);
                float v01 = __shfl_sync(0xffffffffu, s[kg][1], src_lo);
                float v10 = __shfl_sync(0xffffffffu, s[kg][2], src_lo);
                float v11 = __shfl_sync(0xffffffffu, s[kg][3], src_lo);
                float w00 = __shfl_sync(0xffffffffu, s[kg][0], src_hi);
                float w01 = __shfl_sync(0xffffffffu, s[kg][1], src_hi);
                float w10 = __shfl_sync(0xffffffffu, s[kg][2], src_hi);
                float w11 = __shfl_sync(0xffffffffu, s[kg][3], src_hi);
                s[kg][0] = odd ? v01 : v00;
                s[kg][1] = odd ? v11 : v10;
                s[kg][2] = odd ? w01 : w00;
                s[kg][3] = odd ? w11 : w10;
            }
            // P @ V
#pragma unroll
            for (int nd = 0; nd < 8; ++nd) {
                int row = nd * 8 + gi;
                const uint32_t* Vrow = (const uint32_t*)(Vs + row * 32);
                int sw = row & 7;
#pragma unroll
                for (int u = 0; u < 2; ++u) {
                    int chunk = (ci << 1) | u;
                    uint4 F = *(const uint4*)(Vrow + ((chunk ^ sw) << 2));
                    int kg0 = 2 * u;
                    mma8(o[nd], __float_as_uint(s[kg0][0]), __float_as_uint(s[kg0][1]),
                         __float_as_uint(s[kg0][2]), __float_as_uint(s[kg0][3]), F.x, F.y);
                    mma8(o[nd], __float_as_uint(s[kg0 + 1][0]), __float_as_uint(s[kg0 + 1][1]),
                         __float_as_uint(s[kg0 + 1][2]), __float_as_uint(s[kg0 + 1][3]), F.z, F.w);
                }
            }
        }
        __syncthreads();
    }

    // ---- split-KV merge for q-tile qb (partials: group A tiles 17.., group B 0..16)
    float* ob = sm;             // [64][68] floats (reuses group A's K buffers; safe post-loop)
    float* mb = sm + 4352;
    float* lb = sm + 4416;
    if (grpB) {
        int rr = wa * 16 + gi;
#pragma unroll
        for (int nd = 0; nd < 8; ++nd) {
            int c = nd * 8 + 2 * ci;
            *(float2*)&ob[rr * 68 + c]       = make_float2(o[nd][0], o[nd][1]);
            *(float2*)&ob[(rr + 8) * 68 + c] = make_float2(o[nd][2], o[nd][3]);
        }
        if (ci == 0) {
            mb[rr] = m0v; lb[rr] = l0;
            mb[rr + 8] = m1v; lb[rr + 8] = l1;
        }
    }
    __syncthreads();
    if (!grpB) {
        int rr = wa * 16 + gi;
        float mB0 = mb[rr], lB0 = lb[rr], mB1 = mb[rr + 8], lB1 = lb[rr + 8];
        float mS0 = fmaxf(m0v, mB0), mS1 = fmaxf(m1v, mB1);
        float cA0 = __expf(m0v - mS0), cB0 = __expf(mB0 - mS0);
        float cA1 = __expf(m1v - mS1), cB1 = __expf(mB1 - mS1);
        l0 = l0 * cA0 + lB0 * cB0;
        l1 = l1 * cA1 + lB1 * cB1;
#pragma unroll
        for (int nd = 0; nd < 8; ++nd) {
            int c = nd * 8 + 2 * ci;
            float2 b0 = *(float2*)&ob[rr * 68 + c];
            float2 b1 = *(float2*)&ob[(rr + 8) * 68 + c];
            o[nd][0] = o[nd][0] * cA0 + b0.x * cB0;
            o[nd][1] = o[nd][1] * cA0 + b0.y * cB0;
            o[nd][2] = o[nd][2] * cA1 + b1.x * cB1;
            o[nd][3] = o[nd][3] * cA1 + b1.y * cB1;
        }
        epilogue_store();   // r0/qbase already point at qb
    }
}

// ---------------- local windowed causal attention (smem, quad-per-query) -------
__global__ __launch_bounds__(256) void local_attn_kernel()
{
    __shared__ float Ls[69][68];
    int g = blockIdx.x, t0 = blockIdx.y * 64;
    int tid = threadIdx.x;
    const float* Lg = g_l + (size_t)g * (TLEN * KD);
    for (int i = tid; i < 69 * 16; i += 256) {
        int r = i >> 4, c4 = (i & 15) << 2;
        int tg = t0 - 5 + r;
        float4 v = make_float4(0.f, 0.f, 0.f, 0.f);
        if (tg >= 0) v = *(const float4*)&Lg[(size_t)tg * 64 + c4];
        *(float4*)&Ls[r][c4] = v;
    }
    __syncthreads();

    int q = tid >> 2, pi = tid & 3;
    int tj = t0 + q;
    float4 xq[4];
#pragma unroll
    for (int i = 0; i < 4; ++i)
        xq[i] = *(const float4*)&Ls[q + 5][pi * 4 + i * 16];

    float sc[6], mx = -1e30f;
#pragma unroll
    for (int w = 0; w < 6; ++w) {
        float d = 0.f;
#pragma unroll
        for (int i = 0; i < 4; ++i) {
            float4 rv = *(const float4*)&Ls[q + w][pi * 4 + i * 16];
            d += xq[i].x * rv.x + xq[i].y * rv.y + xq[i].z * rv.z + xq[i].w * rv.w;
        }
        d += __shfl_xor_sync(0xffffffffu, d, 1);
        d += __shfl_xor_sync(0xffffffffu, d, 2);
        sc[w] = (tj - 5 + w >= 0) ? d * 0.125f : -1e30f;   // / sqrt(64)
        mx = fmaxf(mx, sc[w]);
    }
    float e[6], den = 0.f;
#pragma unroll
    for (int w = 0; w < 6; ++w) { e[w] = __expf(sc[w] - mx); den += e[w]; }
    float inv = 1.f / den;

    float4 acc[4];
#pragma unroll
    for (int i = 0; i < 4; ++i) acc[i] = make_float4(0.f, 0.f, 0.f, 0.f);
#pragma unroll
    for (int w = 0; w < 6; ++w) {
        float ew = e[w];
#pragma unroll
        for (int i = 0; i < 4; ++i) {
            float4 rv = *(const float4*)&Ls[q + w][pi * 4 + i * 16];
            acc[i].x += ew * rv.x; acc[i].y += ew * rv.y;
            acc[i].z += ew * rv.z; acc[i].w += ew * rv.w;
        }
    }
    float* Og = g_ol + (size_t)g * (TLEN * KD) + (size_t)tj * 64;
#pragma unroll
    for (int i = 0; i < 4; ++i) {
        float4 t;
        t.x = acc[i].x * inv; t.y = acc[i].y * inv;
        t.z = acc[i].z * inv; t.w = acc[i].w * inv;
        *(float4*)&Og[pi * 4 + i * 16] = t;
    }
}

// ---------------- uni projection: fused gating + K-split tf32 GEMM -------------
__global__ __launch_bounds__(256, 2) void unigemm_kernel()
{
    __shared__ float As[128][36];
    __shared__ float Bs[32][68];
    int tid = threadIdx.x, lane = tid & 31, wid = tid >> 5;
    int wm = wid & 3, wn = wid >> 2, gi = lane >> 2, ci = lane & 3;
    int m0 = blockIdx.x * 128;
    int kz = blockIdx.y;
    int bi = m0 >> 10, tib = m0 & 1023;
    uint32_t b_sb = (uint32_t)__cvta_generic_to_shared(&Bs[0][0]);

    float acc[2][4][4];
#pragma unroll
    for (int a = 0; a < 2; ++a)
#pragma unroll
        for (int b = 0; b < 4; ++b)
#pragma unroll
            for (int c = 0; c < 4; ++c) acc[a][b][c] = 0.f;

    for (int s = 0; s < 8; ++s) {
        int k0 = kz * 256 + s * 32;
        int ch = k0 >> 6, ki0 = k0 & 63;
        int h2 = ch & 7;
        bool lohalf = ch < 8;
        const float* Og = g_og + (size_t)(bi * 8 + h2) * (TLEN * KD);
        const float* Lg = g_ol + (size_t)(bi * 8 + h2) * (TLEN * KD);
        __syncthreads();
#pragma unroll
        for (int i = 0; i < 2; ++i) {
            int f4 = tid + i * 256;
            int row = f4 >> 4, c4 = (f4 & 15) << 2;
            cp16(b_sb + (uint32_t)((row * 68 + c4) * 4), g_WU + (size_t)(k0 + row) * 64 + c4);
        }
        CPCOMMIT();
#pragma unroll
        for (int i = 0; i < 4; ++i) {
            int f4 = tid + i * 256;
            int row = f4 >> 3, c4 = (f4 & 7) << 2;
            int ti2 = tib + row;
            const float4 o4 = *(const float4*)(Og + (size_t)ti2 * 64 + ki0 + c4);
            const float4 l4 = *(const float4*)(Lg + (size_t)ti2 * 64 + ki0 + c4);
            float g0 = sigmoid_fast(o4.x), g1 = sigmoid_fast(o4.y);
            float g2 = sigmoid_fast(o4.z), g3 = sigmoid_fast(o4.w);
            float r0 = lohalf ? (1.f - g0) * l4.x : g0 * o4.x;
            float r1 = lohalf ? (1.f - g1) * l4.y : g1 * o4.y;
            float r2 = lohalf ? (1.f - g2) * l4.z : g2 * o4.z;
            float r3 = lohalf ? (1.f - g3) * l4.w : g3 * o4.w;
            As[row][c4 + 0] = tf32r(r0);
            As[row][c4 + 1] = tf32r(r1);
            As[row][c4 + 2] = tf32r(r2);
            As[row][c4 + 3] = tf32r(r3);
        }
        CPWAIT0();
        __syncthreads();
#pragma unroll
        for (int kk = 0; kk < 4; ++kk) {
            int k = kk * 8;
            uint32_t af[2][4];
#pragma unroll
            for (int mi = 0; mi < 2; ++mi) {
                int r = wm * 32 + mi * 16 + gi;
                af[mi][0] = __float_as_uint(As[r][k + ci]);
                af[mi][1] = __float_as_uint(As[r + 8][k + ci]);
                af[mi][2] = __float_as_uint(As[r][k + ci + 4]);
                af[mi][3] = __float_as_uint(As[r + 8][k + ci + 4]);
            }
            uint32_t bf[4][2];
#pragma unroll
            for (int ni = 0; ni < 4; ++ni) {
                int n = wn * 32 + ni * 8 + gi;
                bf[ni][0] = __float_as_uint(Bs[k + ci][n]);
                bf[ni][1] = __float_as_uint(Bs[k + ci + 4][n]);
            }
#pragma unroll
            for (int mi = 0; mi < 2; ++mi)
#pragma unroll
                for (int ni = 0; ni < 4; ++ni)
                    mma8(acc[mi][ni], af[mi][0], af[mi][1], af[mi][2], af[mi][3],
                         bf[ni][0], bf[ni][1]);
        }
    }

    float* P = g_part + ((size_t)kz * MROWS + m0) * 64;
#pragma unroll
    for (int mi = 0; mi < 2; ++mi)
#pragma unroll
        for (int ni = 0; ni < 4; ++ni)
#pragma unroll
            for (int j = 0; j < 4; j += 2) {
                int mrow = wm * 32 + mi * 16 + gi + ((j >= 2) ? 8 : 0);
                int n = wn * 32 + ni * 8 + 2 * ci;
                float2 t; t.x = acc[mi][ni][j]; t.y = acc[mi][ni][j + 1];
                *(float2*)&P[(size_t)mrow * 64 + n] = t;
            }
}

// ---------------- partial-reduce + silu + residual -> LN1 -> FF -> LN2 ---------
__global__ __launch_bounds__(256) void ffln_kernel(
    const float* __restrict__ uni_b,
    const float* __restrict__ ln1g, const float* __restrict__ ln1b,
    const float* __restrict__ ln2g, const float* __restrict__ ln2b,
    const float* __restrict__ w1, const float* __restrict__ b1,
    const float* __restrict__ w2, const float* __restrict__ b2,
    float* __restrict__ out)
{
    const int R = 16;
    __shared__ float yl[R][64];
    __shared__ float hs[R][256];
    __shared__ float fs[R][64];
    int r0 = blockIdx.x * R;
    int tid = threadIdx.x;
    int lane = tid & 31, w = tid >> 5;

    for (int rr = 0; rr < 2; ++rr) {
        int r = w * 2 + rr;
        size_t rg = (size_t)(r0 + r) * 64;
        float v0 = g_part[rg + lane] + g_part[(size_t)MROWS * 64 + rg + lane] +
                   g_part[(size_t)MROWS * 128 + rg + lane] + g_part[(size_t)MROWS * 192 + rg + lane];
        float v1 = g_part[rg + lane + 32] + g_part[(size_t)MROWS * 64 + rg + lane + 32] +
                   g_part[(size_t)MROWS * 128 + rg + lane + 32] + g_part[(size_t)MROWS * 192 + rg + lane + 32];
        v0 = silu_fast(v0 + uni_b[lane]) + g_xin[rg + lane];
        v1 = silu_fast(v1 + uni_b[lane + 32]) + g_xin[rg + lane + 32];
        float sm = v0 + v1;
#pragma unroll
        for (int o = 16; o; o >>= 1) sm += __shfl_xor_sync(0xffffffffu, sm, o);
        float mean = sm * (1.f / 64.f);
        float d0 = v0 - mean, d1 = v1 - mean;
        float vs = d0 * d0 + d1 * d1;
#pragma unroll
        for (int o = 16; o; o >>= 1) vs += __shfl_xor_sync(0xffffffffu, vs, o);
        float inv = rsqrtf(vs * (1.f / 64.f) + 1e-5f);
        yl[r][lane]      = d0 * inv * ln1g[lane] + ln1b[lane];
        yl[r][lane + 32] = d1 * inv * ln1g[lane + 32] + ln1b[lane + 32];
    }
    __syncthreads();

    {
        float acc[R];
#pragma unroll
        for (int r = 0; r < R; ++r) acc[r] = b1[tid];
        for (int c = 0; c < 64; ++c) {
            float wv = w1[c * 256 + tid];
#pragma unroll
            for (int r = 0; r < R; ++r) acc[r] += yl[r][c] * wv;
        }
#pragma unroll
        for (int r = 0; r < R; ++r) hs[r][tid] = fmaxf(acc[r], 0.f);
    }
    __syncthreads();

    {
        int j2 = tid & 63, rg = tid >> 6;
        float acc[4];
#pragma unroll
        for (int rr = 0; rr < 4; ++rr) acc[rr] = b2[j2];
        for (int c = 0; c < 256; ++c) {
            float wv = w2[c * 64 + j2];
#pragma unroll
            for (int rr = 0; rr < 4; ++rr) acc[rr] += hs[rg * 4 + rr][c] * wv;
        }
#pragma unroll
        for (int rr = 0; rr < 4; ++rr) fs[rg * 4 + rr][j2] = acc[rr] + yl[rg * 4 + rr][j2];
    }
    __syncthreads();

    for (int rr = 0; rr < 2; ++rr) {
        int r = w * 2 + rr;
        float v0 = fs[r][lane], v1 = fs[r][lane + 32];
        float sm = v0 + v1;
#pragma unroll
        for (int o = 16; o; o >>= 1) sm += __shfl_xor_sync(0xffffffffu, sm, o);
        float mean = sm * (1.f / 64.f);
        float d0 = v0 - mean, d1 = v1 - mean;
        float vs = d0 * d0 + d1 * d1;
#pragma unroll
        for (int o = 16; o; o >>= 1) vs += __shfl_xor_sync(0xffffffffu, vs, o);
        float inv = rsqrtf(vs * (1.f / 64.f) + 1e-5f);
        float* orow = out + (size_t)(r0 + r) * 64;
        orow[lane]      = d0 * inv * ln2g[lane] + ln2b[lane];
        orow[lane + 32] = d1 * inv * ln2g[lane + 32] + ln2b[lane + 32];
    }
}

// ---------------- launch ---------------------------------------------------------
extern "C" void kernel_launch(void* const* d_in, const int* in_sizes, int n_in,
                              void* d_out, int out_size)
{
    (void)in_sizes; (void)n_in; (void)out_size;
    const float* x       = (const float*)d_in[0];
    const float* sq_w    = (const float*)d_in[1];
    const float* bn_g    = (const float*)d_in[2];
    const float* bn_b    = (const float*)d_in[3];
    const float* dw_w    = (const float*)d_in[4];
    const float* ex_w    = (const float*)d_in[5];
    const float* pos_emb = (const float*)d_in[6];
    const float* wq      = (const float*)d_in[7];
    const float* bq      = (const float*)d_in[8];
    const float* wk      = (const float*)d_in[9];
    const float* bk      = (const float*)d_in[10];
    const float* wv      = (const float*)d_in[11];
    const float* wl      = (const float*)d_in[12];
    const float* uni_w   = (const float*)d_in[13];
    const float* uni_b   = (const float*)d_in[14];
    const float* ln1_g   = (const float*)d_in[15];
    const float* ln1_b   = (const float*)d_in[16];
    const float* ln2_g   = (const float*)d_in[17];
    const float* ln2_b   = (const float*)d_in[18];
    const float* ff_w1   = (const float*)d_in[19];
    const float* ff_b1   = (const float*)d_in[20];
    const float* ff_w2   = (const float*)d_in[21];
    const float* ff_b2   = (const float*)d_in[22];
    float* out = (float*)d_out;

    const int CONV_SMEM  = (2 * 128 * 36 + 2 * 32 * 68) * 4;   // 54272
    const int FLASH_SMEM = 16384 * 4;                          // 65536
    cudaFuncSetAttribute(convgemm_kernel, cudaFuncAttributeMaxDynamicSharedMemorySize, CONV_SMEM);
    cudaFuncSetAttribute(flash_mma_kernel, cudaFuncAttributeMaxDynamicSharedMemorySize, FLASH_SMEM);

    fused_xin_kernel<<<dim3(4, 32), 256>>>(x, sq_w, bn_g, bn_b, dw_w, ex_w, pos_emb);
    prep_w_kernel<<<1792, 256>>>(wq, wk, wv, wl, uni_w);

    convgemm_kernel<<<dim3(32, 16, 2), 256, CONV_SMEM>>>(bq, bk);

    flash_mma_kernel<<<dim3(32, 8), 256, FLASH_SMEM>>>();
    local_attn_kernel<<<dim3(32, 16), 256>>>();

    unigemm_kernel<<<dim3(32, 4), 256>>>();

    ffln_kernel<<<256, 256>>>(uni_b, ln1_g, ln1_b, ln2_g, ln2_b,
                              ff_w1, ff_b1, ff_w2, ff_b2, out);
}

// round 8
// speedup vs baseline: 3.3894x; 1.0151x over previous
#include <cuda_runtime.h>
#include <math.h>
#include <stdint.h>

// Problem constants (fixed by setup_inputs)
#define BATCH 4
#define TLEN  1024
#define KD    64
#define HNUM  8
#define R32   32
#define NSEQ  32      // BATCH*HNUM
#define MROWS 4096    // BATCH*TLEN

// ---------------- scratch (static device globals; no allocation) --------------
__device__ float g_xin[BATCH * TLEN * KD];          // tf32-exact
__device__ float g_WB[320 * 1024];                  // tap-major reordered wq|wk, tf32-exact
__device__ float g_WB2[64 * 1024];                  // wv|wl transposed, tf32-exact
__device__ float g_WU[1024 * 64];                   // uni_w, tf32-exact
__device__ float g_q[NSEQ * TLEN * KD];             // [g][t][p64(d)] tf32-exact
__device__ float g_k[NSEQ * TLEN * KD];             // [g][t][p64(d)]
__device__ float g_v[NSEQ * KD * TLEN];             // [g][d][t: 64-tilewise p64(key)]
__device__ float g_l[NSEQ * TLEN * KD];             // natural
__device__ float g_og[NSEQ * TLEN * KD];
__device__ float g_ol[NSEQ * TLEN * KD];
__device__ float g_part[4 * MROWS * KD];            // uni GEMM K-split partials

__device__ __forceinline__ float sigmoid_exact(float x) { return 1.f / (1.f + expf(-x)); }
__device__ __forceinline__ float sigmoid_fast(float x) {
    float t;
    asm("tanh.approx.f32 %0, %1;" : "=f"(t) : "f"(0.5f * x));
    return 0.5f * t + 0.5f;
}
__device__ __forceinline__ float silu_fast(float x) { return x * sigmoid_fast(x); }

// round f32 -> nearest tf32 (result is a valid f32 with low mantissa zeroed)
__device__ __forceinline__ float tf32r(float x) {
    uint32_t u;
    asm("cvt.rna.tf32.f32 %0, %1;" : "=r"(u) : "f"(x));
    return __uint_as_float(u);
}

// fragment-vectorization permutation of a 64-long contraction dim
__device__ __forceinline__ int pqk(int k) {
    return ((k & 3) << 3) | ((k >> 5) << 5) | (((k >> 4) & 1) << 2) |
           (((k >> 3) & 1) << 1) | ((k >> 2) & 1);
}

__device__ __forceinline__ void mma8(float* c,
                                     uint32_t a0, uint32_t a1, uint32_t a2, uint32_t a3,
                                     uint32_t b0, uint32_t b1) {
    asm volatile(
        "mma.sync.aligned.m16n8k8.row.col.f32.tf32.tf32.f32 "
        "{%0,%1,%2,%3}, {%4,%5,%6,%7}, {%8,%9}, {%0,%1,%2,%3};"
        : "+f"(c[0]), "+f"(c[1]), "+f"(c[2]), "+f"(c[3])
        : "r"(a0), "r"(a1), "r"(a2), "r"(a3), "r"(b0), "r"(b1));
}

__device__ __forceinline__ void cp16(uint32_t dst, const void* src) {
    asm volatile("cp.async.ca.shared.global [%0], [%1], 16;" :: "r"(dst), "l"(src) : "memory");
}
__device__ __forceinline__ void cp16p(uint32_t dst, const void* src, int sz) {
    asm volatile("cp.async.ca.shared.global [%0], [%1], 16, %2;" :: "r"(dst), "l"(src), "r"(sz) : "memory");
}
#define CPCOMMIT() asm volatile("cp.async.commit_group;" ::: "memory")
#define CPWAIT0()  asm volatile("cp.async.wait_group 0;" ::: "memory")
#define CPWAIT1()  asm volatile("cp.async.wait_group 1;" ::: "memory")
#define CPWAIT2()  asm volatile("cp.async.wait_group 2;" ::: "memory")

__device__ __forceinline__ void barg(int id) {
    asm volatile("bar.sync %0, 128;" :: "r"(id) : "memory");
}

// ================= fused action + pos_emb -> xin (tf32-exact) ==================
__global__ __launch_bounds__(256) void fused_xin_kernel(
    const float* __restrict__ x, const float* __restrict__ sq_w,
    const float* __restrict__ bn_g, const float* __restrict__ bn_b,
    const float* __restrict__ dw_w, const float* __restrict__ ex_w,
    const float* __restrict__ pos_emb)
{
    __shared__ float xs[34][68];
    __shared__ float x3s[34][36];
    __shared__ float xp3[32][32];
    __shared__ float sqT[64][32];
    __shared__ float exT[32][64];
    __shared__ float bng_s[32], bnb_s[32];

    int bi = blockIdx.x;
    int t0 = blockIdx.y * 32;
    int tid = threadIdx.x;
    int nrows = min(34, TLEN - t0);

    for (int i = tid; i < nrows * 16; i += 256) {
        int row = i >> 4, c4 = (i & 15) << 2;
        *(float4*)&xs[row][c4] = *(const float4*)&x[((size_t)bi * TLEN + t0 + row) * KD + c4];
    }
    for (int i = tid; i < 2048; i += 256) { int r = i >> 6, c = i & 63; sqT[c][r] = sq_w[i]; }
    for (int i = tid; i < 2048; i += 256) { int c = i >> 5, r = i & 31; exT[r][c] = ex_w[i]; }
    if (tid < 32) { bng_s[tid] = bn_g[tid] * 0.9999950000374997f; bnb_s[tid] = bn_b[tid]; }
    __syncthreads();

    {
        int j = tid >> 2, rg = (tid & 3) << 3;
        if (j < nrows) {
            float acc[8];
#pragma unroll
            for (int i = 0; i < 8; ++i) acc[i] = 0.f;
#pragma unroll
            for (int c4 = 0; c4 < 64; c4 += 4) {
                float4 xv = *(const float4*)&xs[j][c4];
#pragma unroll
                for (int t = 0; t < 4; ++t) {
                    float xc = (t == 0) ? xv.x : (t == 1) ? xv.y : (t == 2) ? xv.z : xv.w;
                    float4 s0 = *(const float4*)&sqT[c4 + t][rg];
                    float4 s1 = *(const float4*)&sqT[c4 + t][rg + 4];
                    acc[0] += xc * s0.x; acc[1] += xc * s0.y;
                    acc[2] += xc * s0.z; acc[3] += xc * s0.w;
                    acc[4] += xc * s1.x; acc[5] += xc * s1.y;
                    acc[6] += xc * s1.z; acc[7] += xc * s1.w;
                }
            }
#pragma unroll
            for (int i = 0; i < 8; ++i)
                x3s[j][rg + i] = acc[i] * bng_s[rg + i] + bnb_s[rg + i];
        }
    }
    __syncthreads();

    for (int idx = tid; idx < 32 * 32; idx += 256) {
        int r = idx & 31, jj = idx >> 5;
        int pos = t0 + jj;
        float base = x3s[jj][r];
        float v;
        if (pos == TLEN - 1) {
            v = base;
        } else {
            float d0 = dw_w[r * 3 + 0], d1 = dw_w[r * 3 + 1], d2 = dw_w[r * 3 + 2];
            float a = base * d0 + x3s[jj + 1][r] * d1 +
                      ((pos + 2 < TLEN) ? x3s[jj + 2][r] * d2 : 0.f);
            v = a - base;
        }
        xp3[jj][r] = v;
    }
    __syncthreads();

    for (int idx = tid; idx < 32 * 64; idx += 256) {
        int c = idx & 63, j = idx >> 6;
        int pos = t0 + j;
        float gsum = 0.f;
#pragma unroll
        for (int r = 0; r < R32; ++r) gsum += xp3[j][r] * exT[r][c];
        float sig = sigmoid_exact(gsum);
        size_t off = ((size_t)bi * TLEN + pos) * KD + c;
        g_xin[off] = tf32r(xs[j][c] * sig + pos_emb[pos * KD + c]);
    }
}

// ---------------- weight prep (reorder + tf32 round, single kernel) ------------
__global__ __launch_bounds__(256) void prep_w_kernel(
    const float* __restrict__ wq, const float* __restrict__ wk,
    const float* __restrict__ wv, const float* __restrict__ wl,
    const float* __restrict__ uni_w)
{
    int idx = blockIdx.x * 256 + threadIdx.x;
    if (idx < 320 * 1024) {
        int n = idx & 1023, kcol = idx >> 10;
        int mm = kcol >> 6, c = kcol & 63;
        float w = (n < 512) ? wq[n * 320 + c * 5 + mm] : wk[(n - 512) * 320 + c * 5 + mm];
        g_WB[idx] = tf32r(w);
    } else if (idx < 320 * 1024 + 65536) {
        int j = idx - 320 * 1024;
        int n = j & 1023, c = j >> 10;
        g_WB2[j] = tf32r((n < 512) ? wv[n * 64 + c] : wl[(n - 512) * 64 + c]);
    } else if (idx < 320 * 1024 + 131072) {
        int j = idx - (320 * 1024 + 65536);
        g_WU[j] = tf32r(uni_w[j]);
    }
}

// ---------------- conv GEMMs (tf32 mma, cp.async dbl-buffered, mode=blockIdx.z) --
__global__ __launch_bounds__(256, 2) void convgemm_kernel(
    const float* __restrict__ bias0, const float* __restrict__ bias1)
{
    int mode = blockIdx.z;
    const int NSTAGE = (mode == 0) ? 10 : 2;
    extern __shared__ float sm[];
    float* As = sm;                   // [2][128][36]
    float* Bs = sm + 2 * 128 * 36;    // [2][32][68]
    const float* __restrict__ Bg = (mode == 0) ? g_WB : g_WB2;

    int tid = threadIdx.x, lane = tid & 31, wid = tid >> 5;
    int wm = wid & 3, wn = wid >> 2, gi = lane >> 2, ci = lane & 3;
    int m0 = blockIdx.x * 128, n0 = blockIdx.y * 64;
    int bi = m0 >> 10, tibase = m0 & 1023;
    uint32_t sb = (uint32_t)__cvta_generic_to_shared(sm);
    uint32_t a_sb = sb, b_sb = sb + 2 * 128 * 36 * 4;

    auto issue_stage = [&](int s_, int buf_) {
        int mm_ = (mode == 0) ? (s_ >> 1) : 0;
        int c0_ = (mode == 0) ? ((s_ & 1) << 5) : (s_ << 5);
        int sh_ = (mode == 0) ? (2 * mm_ - 8) : 0;
#pragma unroll
        for (int i_ = 0; i_ < 4; ++i_) {
            int f4 = tid + i_ * 256;
            int row = f4 >> 3, c4 = (f4 & 7) << 2;
            int tsrc = tibase + row + sh_;
            const float* srcp = g_xin + ((size_t)(bi << 10) + tsrc) * 64 + c0_ + c4;
            uint32_t dstp = a_sb + (uint32_t)((buf_ * 4608 + row * 36 + c4) * 4);
            cp16p(dstp, srcp, (tsrc >= 0) ? 16 : 0);
        }
#pragma unroll
        for (int i_ = 0; i_ < 2; ++i_) {
            int f4 = tid + i_ * 256;
            int row = f4 >> 4, c4 = (f4 & 15) << 2;
            const float* srcp = Bg + (size_t)(s_ * 32 + row) * 1024 + n0 + c4;
            uint32_t dstp = b_sb + (uint32_t)((buf_ * 2176 + row * 68 + c4) * 4);
            cp16(dstp, srcp);
        }
        CPCOMMIT();
    };

    float acc[2][4][4];
#pragma unroll
    for (int a = 0; a < 2; ++a)
#pragma unroll
        for (int b = 0; b < 4; ++b)
#pragma unroll
            for (int c = 0; c < 4; ++c) acc[a][b][c] = 0.f;

    issue_stage(0, 0);
    for (int s = 0; s < NSTAGE; ++s) {
        if (s + 1 < NSTAGE) { issue_stage(s + 1, (s + 1) & 1); CPWAIT1(); }
        else CPWAIT0();
        __syncthreads();
        const float* Ab = As + (s & 1) * 4608;
        const float* Bb = Bs + (s & 1) * 2176;
#pragma unroll
        for (int kk = 0; kk < 4; ++kk) {
            int k = kk * 8;
            uint32_t af[2][4];
#pragma unroll
            for (int mi = 0; mi < 2; ++mi) {
                int r = wm * 32 + mi * 16 + gi;
                af[mi][0] = __float_as_uint(Ab[r * 36 + k + ci]);
                af[mi][1] = __float_as_uint(Ab[(r + 8) * 36 + k + ci]);
                af[mi][2] = __float_as_uint(Ab[r * 36 + k + ci + 4]);
                af[mi][3] = __float_as_uint(Ab[(r + 8) * 36 + k + ci + 4]);
            }
            uint32_t bf[4][2];
#pragma unroll
            for (int ni = 0; ni < 4; ++ni) {
                int n = wn * 32 + ni * 8 + gi;
                bf[ni][0] = __float_as_uint(Bb[(k + ci) * 68 + n]);
                bf[ni][1] = __float_as_uint(Bb[(k + ci + 4) * 68 + n]);
            }
#pragma unroll
            for (int mi = 0; mi < 2; ++mi)
#pragma unroll
                for (int ni = 0; ni < 4; ++ni)
                    mma8(acc[mi][ni], af[mi][0], af[mi][1], af[mi][2], af[mi][3],
                         bf[ni][0], bf[ni][1]);
        }
        __syncthreads();
    }

#pragma unroll
    for (int mi = 0; mi < 2; ++mi)
#pragma unroll
        for (int ni = 0; ni < 4; ++ni)
#pragma unroll
            for (int j = 0; j < 4; ++j) {
                int m = m0 + wm * 32 + mi * 16 + gi + ((j >= 2) ? 8 : 0);
                int n = n0 + wn * 32 + ni * 8 + 2 * ci + (j & 1);
                float v = acc[mi][ni][j];
                int o = n & 511, ki = o >> 3, h = o & 7;
                int bb = m >> 10, ti = m & 1023;
                int gg = bb * 8 + (ti >> 7);
                int tj = ((ti & 127) << 3) | h;
                if (mode == 0) {
                    float bias = (n < 512) ? bias0[n] : bias1[n - 512];
                    float s = silu_fast(v + bias) * 0.35355339059327373f;  // / 64^0.25
                    float* dst = (n < 512) ? g_q : g_k;
                    dst[((size_t)gg * TLEN + tj) * KD + pqk(ki)] = tf32r(s);
                } else {
                    float s = silu_fast(v);
                    if (n < 512) {
                        g_v[((size_t)gg * KD + ki) * TLEN + (tj & ~63) + pqk(tj & 63)] = tf32r(s);
                    } else {
                        g_l[((size_t)gg * TLEN + tj) * KD + ki] = tf32r(s);
                    }
                }
            }
}

// ---------------- flash attention v4: 64-key tiles, decoupled balanced groups ---
// block (g, p): group B (warps 4-7) does q-tile qb=15-p, k-tiles 0..8 (9 tiles).
// group A (warps 0-3) does q-tile qa=p fully (p+1 tiles) + qb k-tiles 9..15-p
// (7-p tiles) = 8 tiles. Groups fully decoupled (named barriers, private smem:
// K double-buffered, V single-buffered). Split-KV merge for qb at the end.
__global__ __launch_bounds__(256, 2) void flash_mma_kernel()
{
    extern __shared__ float sm[];   // A: K[2][4096] V[4096] @0 | B: same @12288
    int g  = blockIdx.x;
    int p  = blockIdx.y;
    int qa = p, qb = 15 - p;
    int tid = threadIdx.x, lane = tid & 31, wid = tid >> 5;
    int gi = lane >> 2, ci = lane & 3;
    int wa = wid & 3;
    bool grpB = wid >= 4;
    int barid = grpB ? 2 : 1;
    int Na = p + 1;                      // group A's qa tile count
    int NIT = grpB ? 9 : 8;
    uint32_t sb = (uint32_t)__cvta_generic_to_shared(sm);
    int KO = grpB ? 12288 : 0;
    int VO = KO + 8192;
    int lt = wa * 32 + lane;             // 0..127 within group

    const float* Qg  = g_q + (size_t)g * (TLEN * KD);
    const float* Kg0 = g_k + (size_t)g * (TLEN * KD);
    const float* Vg0 = g_v + (size_t)g * (KD * TLEN);

    int qt = grpB ? qb : qa;
    int qbase = qt * 64 + wa * 16;
    int r0 = qbase + gi;

    uint32_t qf[8][4];
    auto load_qf = [&]() {
#pragma unroll
        for (int t4 = 0; t4 < 4; ++t4) {
            int woff = (2 * ci + (t4 & 1) + ((t4 >> 1) << 3)) << 2;
            float4 lo = *(const float4*)&Qg[(size_t)r0 * KD + woff];
            float4 hi = *(const float4*)&Qg[(size_t)(r0 + 8) * KD + woff];
            int kk0 = ((t4 >> 1) << 2) + ((t4 & 1) << 1);
            qf[kk0][0]     = __float_as_uint(lo.x); qf[kk0][2]     = __float_as_uint(lo.y);
            qf[kk0 + 1][0] = __float_as_uint(lo.z); qf[kk0 + 1][2] = __float_as_uint(lo.w);
            qf[kk0][1]     = __float_as_uint(hi.x); qf[kk0][3]     = __float_as_uint(hi.y);
            qf[kk0 + 1][1] = __float_as_uint(hi.z); qf[kk0 + 1][3] = __float_as_uint(hi.w);
        }
    };
    load_qf();

    float o[8][4];
#pragma unroll
    for (int a = 0; a < 8; ++a)
#pragma unroll
        for (int b = 0; b < 4; ++b) o[a][b] = 0.f;
    float m0v = -1e30f, m1v = -1e30f, l0 = 0.f, l1 = 0.f;

    int src_lo = (lane & ~3) | (ci >> 1);
    int src_hi = src_lo + 2;
    bool odd = ci & 1;

    // iteration i -> absolute 64-key tile
    auto kt_of = [&](int i) {
        if (grpB) return i;
        return (i < Na) ? i : (9 + i - Na);
    };

    auto issueK = [&](int i, int buf) {
        int k0 = kt_of(i) * 64;
#pragma unroll
        for (int j = 0; j < 8; ++j) {
            int f4 = lt + j * 128;
            int row = f4 >> 4, chunk = f4 & 15;
            int swc = chunk ^ (row & 7);
            cp16(sb + (uint32_t)((KO + buf * 4096 + row * 64 + swc * 4) * 4),
                 Kg0 + (size_t)(k0 + row) * 64 + chunk * 4);
        }
        CPCOMMIT();
    };
    auto issueV = [&](int i) {
        int k0 = kt_of(i) * 64;
#pragma unroll
        for (int j = 0; j < 8; ++j) {
            int f4 = lt + j * 128;
            int row = f4 >> 4, chunk = f4 & 15;
            int swc = chunk ^ (row & 7);
            cp16(sb + (uint32_t)((VO + row * 64 + swc * 4) * 4),
                 Vg0 + (size_t)row * TLEN + k0 + chunk * 4);
        }
        CPCOMMIT();
    };

    auto epilogue_store = [&]() {
        float inv0 = 1.f / l0, inv1 = 1.f / l1;
        float* Og = g_og + (size_t)g * (TLEN * KD);
#pragma unroll
        for (int nd = 0; nd < 8; ++nd) {
            int c = nd * 8 + 2 * ci;
            float2 t0; t0.x = o[nd][0] * inv0; t0.y = o[nd][1] * inv0;
            float2 t1; t1.x = o[nd][2] * inv1; t1.y = o[nd][3] * inv1;
            *(float2*)&Og[(size_t)r0 * KD + c] = t0;
            *(float2*)&Og[(size_t)(r0 + 8) * KD + c] = t1;
        }
    };
    auto reset_state = [&]() {
#pragma unroll
        for (int a = 0; a < 8; ++a)
#pragma unroll
            for (int b = 0; b < 4; ++b) o[a][b] = 0.f;
        m0v = -1e30f; m1v = -1e30f; l0 = 0.f; l1 = 0.f;
    };

    issueK(0, 0);
    for (int i = 0; i < NIT; ++i) {
        // group A: switch from qa to qb partial before processing tile i
        if (!grpB && i == Na) {
            epilogue_store();
            reset_state();
            qt = qb; qbase = qt * 64 + wa * 16; r0 = qbase + gi;
            load_qf();
        }
        bool more = (i + 1 < NIT);
        issueV(i);
        if (more) issueK(i + 1, (i + 1) & 1);
        if (more) CPWAIT2(); else CPWAIT1();    // K(i) ready
        barg(barid);

        int k0 = kt_of(i) * 64;
        const float* Ks = sm + KO + (i & 1) * 4096;
        const float* Vs = sm + VO;

        // S = Q K^T : per ni, 4 LDS128 + 8 MMA
        float s[8][4];
#pragma unroll
        for (int ni = 0; ni < 8; ++ni) {
            s[ni][0] = s[ni][1] = s[ni][2] = s[ni][3] = 0.f;
            int key = ni * 8 + gi;
            const uint32_t* Krow = (const uint32_t*)(Ks + key * 64);
            int sw = key & 7;
#pragma unroll
            for (int t4 = 0; t4 < 4; ++t4) {
                int chunk = 2 * ci + (t4 & 1) + ((t4 >> 1) << 3);
                uint4 F = *(const uint4*)(Krow + ((chunk ^ sw) << 2));
                int kk0 = ((t4 >> 1) << 2) + ((t4 & 1) << 1);
                mma8(s[ni], qf[kk0][0], qf[kk0][1], qf[kk0][2], qf[kk0][3], F.x, F.y);
                mma8(s[ni], qf[kk0 + 1][0], qf[kk0 + 1][1], qf[kk0 + 1][2], qf[kk0 + 1][3], F.z, F.w);
            }
        }
        if (k0 + 63 > qbase) {   // diagonal tile: causal mask
#pragma unroll
            for (int ni = 0; ni < 8; ++ni)
#pragma unroll
                for (int j = 0; j < 4; ++j) {
                    int col = k0 + ni * 8 + 2 * ci + (j & 1);
                    int row = r0 + ((j >= 2) ? 8 : 0);
                    if (col > row) s[ni][j] = -1e30f;
                }
        }
        // online softmax
        float mx0 = -1e30f, mx1 = -1e30f;
#pragma unroll
        for (int ni = 0; ni < 8; ++ni) {
            mx0 = fmaxf(mx0, fmaxf(s[ni][0], s[ni][1]));
            mx1 = fmaxf(mx1, fmaxf(s[ni][2], s[ni][3]));
        }
        mx0 = fmaxf(mx0, __shfl_xor_sync(0xffffffffu, mx0, 1));
        mx0 = fmaxf(mx0, __shfl_xor_sync(0xffffffffu, mx0, 2));
        mx1 = fmaxf(mx1, __shfl_xor_sync(0xffffffffu, mx1, 1));
        mx1 = fmaxf(mx1, __shfl_xor_sync(0xffffffffu, mx1, 2));
        float m0n = fmaxf(m0v, mx0), m1n = fmaxf(m1v, mx1);
        float corr0 = __expf(m0v - m0n), corr1 = __expf(m1v - m1n);

        float sum0 = 0.f, sum1 = 0.f;
#pragma unroll
        for (int ni = 0; ni < 8; ++ni) {
            s[ni][0] = tf32r(__expf(s[ni][0] - m0n));
            s[ni][1] = tf32r(__expf(s[ni][1] - m0n));
            s[ni][2] = tf32r(__expf(s[ni][2] - m1n));
            s[ni][3] = tf32r(__expf(s[ni][3] - m1n));
            sum0 += s[ni][0] + s[ni][1];
            sum1 += s[ni][2] + s[ni][3];
        }
        sum0 += __shfl_xor_sync(0xffffffffu, sum0, 1);
        sum0 += __shfl_xor_sync(0xffffffffu, sum0, 2);
        sum1 += __shfl_xor_sync(0xffffffffu, sum1, 1);
        sum1 += __shfl_xor_sync(0xffffffffu, sum1, 2);
        l0 = l0 * corr0 + sum0;
        l1 = l1 * corr1 + sum1;
        m0v = m0n; m1v = m1n;
#pragma unroll
        for (int nd = 0; nd < 8; ++nd) {
            o[nd][0] *= corr0; o[nd][1] *= corr0;
            o[nd][2] *= corr1; o[nd][3] *= corr1;
        }
        // P C-layout -> A-fragments in place
#pragma unroll
        for (int kg = 0; kg < 8; ++kg) {
            float v00 = __shfl_sync(0xffffffffu, s[kg][0], src_lo);
            float v01 = __shfl_sync(0xffffffffu, s[kg][1], src_lo);
            float v10 = __shfl_sync(0xffffffffu, s[kg][2], src_lo);
            float v11 = __shfl_sync(0xffffffffu, s[kg][3], src_lo);
            float w00 = __shfl_sync(0xffffffffu, s[kg][0], src_hi);
            float w01 = __shfl_sync(0xffffffffu, s[kg][1], src_hi);
            float w10 = __shfl_sync(0xffffffffu, s[kg][2], src_hi);
            float w11 = __shfl_sync(0xffffffffu, s[kg][3], src_hi);
            s[kg][0] = odd ? v01 : v00;
            s[kg][1] = odd ? v11 : v10;
            s[kg][2] = odd ? w01 : w00;
            s[kg][3] = odd ? w11 : w10;
        }
        // V(i) ready?
        if (more) CPWAIT1(); else CPWAIT0();
        barg(barid);
        // P @ V : per nd, 4 LDS128 + 8 MMA
#pragma unroll
        for (int nd = 0; nd < 8; ++nd) {
            int row = nd * 8 + gi;
            const uint32_t* Vrow = (const uint32_t*)(Vs + row * 64);
            int sw = row & 7;
#pragma unroll
            for (int t4 = 0; t4 < 4; ++t4) {
                int chunk = 2 * ci + (t4 & 1) + ((t4 >> 1) << 3);
                uint4 F = *(const uint4*)(Vrow + ((chunk ^ sw) << 2));
                int kg0 = ((t4 >> 1) << 2) + ((t4 & 1) << 1);
                mma8(o[nd], __float_as_uint(s[kg0][0]), __float_as_uint(s[kg0][1]),
                     __float_as_uint(s[kg0][2]), __float_as_uint(s[kg0][3]), F.x, F.y);
                mma8(o[nd], __float_as_uint(s[kg0 + 1][0]), __float_as_uint(s[kg0 + 1][1]),
                     __float_as_uint(s[kg0 + 1][2]), __float_as_uint(s[kg0 + 1][3]), F.z, F.w);
            }
        }
        barg(barid);   // protect V buffer (and K buf reuse) before next issues
    }

    // group A with p == 7: never switched inside loop -> finalize qa, empty qb partial
    if (!grpB && Na == NIT) {
        epilogue_store();
        reset_state();
        qt = qb; qbase = qt * 64 + wa * 16; r0 = qbase + gi;
    }

    // ---- split-KV merge for q-tile qb (A: tiles 9.., B: tiles 0..8)
    // merge buffers live in group B's K region (B done with it; A reads after sync)
    float* ob = sm + 12288;             // [64][68]
    float* mb = sm + 12288 + 4352;
    float* lb = mb + 64;
    if (grpB) {
        int rr = wa * 16 + gi;
#pragma unroll
        for (int nd = 0; nd < 8; ++nd) {
            int c = nd * 8 + 2 * ci;
            *(float2*)&ob[rr * 68 + c]       = make_float2(o[nd][0], o[nd][1]);
            *(float2*)&ob[(rr + 8) * 68 + c] = make_float2(o[nd][2], o[nd][3]);
        }
        if (ci == 0) {
            mb[rr] = m0v; lb[rr] = l0;
            mb[rr + 8] = m1v; lb[rr + 8] = l1;
        }
    }
    __syncthreads();
    if (!grpB) {
        int rr = wa * 16 + gi;
        float mB0 = mb[rr], lB0 = lb[rr], mB1 = mb[rr + 8], lB1 = lb[rr + 8];
        float mS0 = fmaxf(m0v, mB0), mS1 = fmaxf(m1v, mB1);
        float cA0 = __expf(m0v - mS0), cB0 = __expf(mB0 - mS0);
        float cA1 = __expf(m1v - mS1), cB1 = __expf(mB1 - mS1);
        l0 = l0 * cA0 + lB0 * cB0;
        l1 = l1 * cA1 + lB1 * cB1;
#pragma unroll
        for (int nd = 0; nd < 8; ++nd) {
            int c = nd * 8 + 2 * ci;
            float2 b0 = *(float2*)&ob[rr * 68 + c];
            float2 b1 = *(float2*)&ob[(rr + 8) * 68 + c];
            o[nd][0] = o[nd][0] * cA0 + b0.x * cB0;
            o[nd][1] = o[nd][1] * cA0 + b0.y * cB0;
            o[nd][2] = o[nd][2] * cA1 + b1.x * cB1;
            o[nd][3] = o[nd][3] * cA1 + b1.y * cB1;
        }
        epilogue_store();   // r0/qbase point at qb
    }
}

// ---------------- local windowed causal attention (smem, quad-per-query) -------
__global__ __launch_bounds__(256) void local_attn_kernel()
{
    __shared__ float Ls[69][68];
    int g = blockIdx.x, t0 = blockIdx.y * 64;
    int tid = threadIdx.x;
    const float* Lg = g_l + (size_t)g * (TLEN * KD);
    for (int i = tid; i < 69 * 16; i += 256) {
        int r = i >> 4, c4 = (i & 15) << 2;
        int tg = t0 - 5 + r;
        float4 v = make_float4(0.f, 0.f, 0.f, 0.f);
        if (tg >= 0) v = *(const float4*)&Lg[(size_t)tg * 64 + c4];
        *(float4*)&Ls[r][c4] = v;
    }
    __syncthreads();

    int q = tid >> 2, pi = tid & 3;
    int tj = t0 + q;
    float4 xq[4];
#pragma unroll
    for (int i = 0; i < 4; ++i)
        xq[i] = *(const float4*)&Ls[q + 5][pi * 4 + i * 16];

    float sc[6], mx = -1e30f;
#pragma unroll
    for (int w = 0; w < 6; ++w) {
        float d = 0.f;
#pragma unroll
        for (int i = 0; i < 4; ++i) {
            float4 rv = *(const float4*)&Ls[q + w][pi * 4 + i * 16];
            d += xq[i].x * rv.x + xq[i].y * rv.y + xq[i].z * rv.z + xq[i].w * rv.w;
        }
        d += __shfl_xor_sync(0xffffffffu, d, 1);
        d += __shfl_xor_sync(0xffffffffu, d, 2);
        sc[w] = (tj - 5 + w >= 0) ? d * 0.125f : -1e30f;   // / sqrt(64)
        mx = fmaxf(mx, sc[w]);
    }
    float e[6], den = 0.f;
#pragma unroll
    for (int w = 0; w < 6; ++w) { e[w] = __expf(sc[w] - mx); den += e[w]; }
    float inv = 1.f / den;

    float4 acc[4];
#pragma unroll
    for (int i = 0; i < 4; ++i) acc[i] = make_float4(0.f, 0.f, 0.f, 0.f);
#pragma unroll
    for (int w = 0; w < 6; ++w) {
        float ew = e[w];
#pragma unroll
        for (int i = 0; i < 4; ++i) {
            float4 rv = *(const float4*)&Ls[q + w][pi * 4 + i * 16];
            acc[i].x += ew * rv.x; acc[i].y += ew * rv.y;
            acc[i].z += ew * rv.z; acc[i].w += ew * rv.w;
        }
    }
    float* Og = g_ol + (size_t)g * (TLEN * KD) + (size_t)tj * 64;
#pragma unroll
    for (int i = 0; i < 4; ++i) {
        float4 t;
        t.x = acc[i].x * inv; t.y = acc[i].y * inv;
        t.z = acc[i].z * inv; t.w = acc[i].w * inv;
        *(float4*)&Og[pi * 4 + i * 16] = t;
    }
}

// ---------------- uni projection: fused gating + K-split tf32 GEMM -------------
__global__ __launch_bounds__(256, 2) void unigemm_kernel()
{
    __shared__ float As[128][36];
    __shared__ float Bs[32][68];
    int tid = threadIdx.x, lane = tid & 31, wid = tid >> 5;
    int wm = wid & 3, wn = wid >> 2, gi = lane >> 2, ci = lane & 3;
    int m0 = blockIdx.x * 128;
    int kz = blockIdx.y;
    int bi = m0 >> 10, tib = m0 & 1023;
    uint32_t b_sb = (uint32_t)__cvta_generic_to_shared(&Bs[0][0]);

    float acc[2][4][4];
#pragma unroll
    for (int a = 0; a < 2; ++a)
#pragma unroll
        for (int b = 0; b < 4; ++b)
#pragma unroll
            for (int c = 0; c < 4; ++c) acc[a][b][c] = 0.f;

    for (int s = 0; s < 8; ++s) {
        int k0 = kz * 256 + s * 32;
        int ch = k0 >> 6, ki0 = k0 & 63;
        int h2 = ch & 7;
        bool lohalf = ch < 8;
        const float* Og = g_og + (size_t)(bi * 8 + h2) * (TLEN * KD);
        const float* Lg = g_ol + (size_t)(bi * 8 + h2) * (TLEN * KD);
        __syncthreads();
#pragma unroll
        for (int i = 0; i < 2; ++i) {
            int f4 = tid + i * 256;
            int row = f4 >> 4, c4 = (f4 & 15) << 2;
            cp16(b_sb + (uint32_t)((row * 68 + c4) * 4), g_WU + (size_t)(k0 + row) * 64 + c4);
        }
        CPCOMMIT();
#pragma unroll
        for (int i = 0; i < 4; ++i) {
            int f4 = tid + i * 256;
            int row = f4 >> 3, c4 = (f4 & 7) << 2;
            int ti2 = tib + row;
            const float4 o4 = *(const float4*)(Og + (size_t)ti2 * 64 + ki0 + c4);
            const float4 l4 = *(const float4*)(Lg + (size_t)ti2 * 64 + ki0 + c4);
            float g0 = sigmoid_fast(o4.x), g1 = sigmoid_fast(o4.y);
            float g2 = sigmoid_fast(o4.z), g3 = sigmoid_fast(o4.w);
            float r0 = lohalf ? (1.f - g0) * l4.x : g0 * o4.x;
            float r1 = lohalf ? (1.f - g1) * l4.y : g1 * o4.y;
            float r2 = lohalf ? (1.f - g2) * l4.z : g2 * o4.z;
            float r3 = lohalf ? (1.f - g3) * l4.w : g3 * o4.w;
            As[row][c4 + 0] = tf32r(r0);
            As[row][c4 + 1] = tf32r(r1);
            As[row][c4 + 2] = tf32r(r2);
            As[row][c4 + 3] = tf32r(r3);
        }
        CPWAIT0();
        __syncthreads();
#pragma unroll
        for (int kk = 0; kk < 4; ++kk) {
            int k = kk * 8;
            uint32_t af[2][4];
#pragma unroll
            for (int mi = 0; mi < 2; ++mi) {
                int r = wm * 32 + mi * 16 + gi;
                af[mi][0] = __float_as_uint(As[r][k + ci]);
                af[mi][1] = __float_as_uint(As[r + 8][k + ci]);
                af[mi][2] = __float_as_uint(As[r][k + ci + 4]);
                af[mi][3] = __float_as_uint(As[r + 8][k + ci + 4]);
            }
            uint32_t bf[4][2];
#pragma unroll
            for (int ni = 0; ni < 4; ++ni) {
                int n = wn * 32 + ni * 8 + gi;
                bf[ni][0] = __float_as_uint(Bs[k + ci][n]);
                bf[ni][1] = __float_as_uint(Bs[k + ci + 4][n]);
            }
#pragma unroll
            for (int mi = 0; mi < 2; ++mi)
#pragma unroll
                for (int ni = 0; ni < 4; ++ni)
                    mma8(acc[mi][ni], af[mi][0], af[mi][1], af[mi][2], af[mi][3],
                         bf[ni][0], bf[ni][1]);
        }
    }

    float* P = g_part + ((size_t)kz * MROWS + m0) * 64;
#pragma unroll
    for (int mi = 0; mi < 2; ++mi)
#pragma unroll
        for (int ni = 0; ni < 4; ++ni)
#pragma unroll
            for (int j = 0; j < 4; j += 2) {
                int mrow = wm * 32 + mi * 16 + gi + ((j >= 2) ? 8 : 0);
                int n = wn * 32 + ni * 8 + 2 * ci;
                float2 t; t.x = acc[mi][ni][j]; t.y = acc[mi][ni][j + 1];
                *(float2*)&P[(size_t)mrow * 64 + n] = t;
            }
}

// ---------------- partial-reduce + silu + residual -> LN1 -> FF -> LN2 ---------
__global__ __launch_bounds__(256) void ffln_kernel(
    const float* __restrict__ uni_b,
    const float* __restrict__ ln1g, const float* __restrict__ ln1b,
    const float* __restrict__ ln2g, const float* __restrict__ ln2b,
    const float* __restrict__ w1, const float* __restrict__ b1,
    const float* __restrict__ w2, const float* __restrict__ b2,
    float* __restrict__ out)
{
    const int R = 16;
    __shared__ float yl[R][64];
    __shared__ float hs[R][256];
    __shared__ float fs[R][64];
    int r0 = blockIdx.x * R;
    int tid = threadIdx.x;
    int lane = tid & 31, w = tid >> 5;

    for (int rr = 0; rr < 2; ++rr) {
        int r = w * 2 + rr;
        size_t rg = (size_t)(r0 + r) * 64;
        float v0 = g_part[rg + lane] + g_part[(size_t)MROWS * 64 + rg + lane] +
                   g_part[(size_t)MROWS * 128 + rg + lane] + g_part[(size_t)MROWS * 192 + rg + lane];
        float v1 = g_part[rg + lane + 32] + g_part[(size_t)MROWS * 64 + rg + lane + 32] +
                   g_part[(size_t)MROWS * 128 + rg + lane + 32] + g_part[(size_t)MROWS * 192 + rg + lane + 32];
        v0 = silu_fast(v0 + uni_b[lane]) + g_xin[rg + lane];
        v1 = silu_fast(v1 + uni_b[lane + 32]) + g_xin[rg + lane + 32];
        float sm = v0 + v1;
#pragma unroll
        for (int o = 16; o; o >>= 1) sm += __shfl_xor_sync(0xffffffffu, sm, o);
        float mean = sm * (1.f / 64.f);
        float d0 = v0 - mean, d1 = v1 - mean;
        float vs = d0 * d0 + d1 * d1;
#pragma unroll
        for (int o = 16; o; o >>= 1) vs += __shfl_xor_sync(0xffffffffu, vs, o);
        float inv = rsqrtf(vs * (1.f / 64.f) + 1e-5f);
        yl[r][lane]      = d0 * inv * ln1g[lane] + ln1b[lane];
        yl[r][lane + 32] = d1 * inv * ln1g[lane + 32] + ln1b[lane + 32];
    }
    __syncthreads();

    {
        float acc[R];
#pragma unroll
        for (int r = 0; r < R; ++r) acc[r] = b1[tid];
        for (int c = 0; c < 64; ++c) {
            float wv = w1[c * 256 + tid];
#pragma unroll
            for (int r = 0; r < R; ++r) acc[r] += yl[r][c] * wv;
        }
#pragma unroll
        for (int r = 0; r < R; ++r) hs[r][tid] = fmaxf(acc[r], 0.f);
    }
    __syncthreads();

    {
        int j2 = tid & 63, rg = tid >> 6;
        float acc[4];
#pragma unroll
        for (int rr = 0; rr < 4; ++rr) acc[rr] = b2[j2];
        for (int c = 0; c < 256; ++c) {
            float wv = w2[c * 64 + j2];
#pragma unroll
            for (int rr = 0; rr < 4; ++rr) acc[rr] += hs[rg * 4 + rr][c] * wv;
        }
#pragma unroll
        for (int rr = 0; rr < 4; ++rr) fs[rg * 4 + rr][j2] = acc[rr] + yl[rg * 4 + rr][j2];
    }
    __syncthreads();

    for (int rr = 0; rr < 2; ++rr) {
        int r = w * 2 + rr;
        float v0 = fs[r][lane], v1 = fs[r][lane + 32];
        float sm = v0 + v1;
#pragma unroll
        for (int o = 16; o; o >>= 1) sm += __shfl_xor_sync(0xffffffffu, sm, o);
        float mean = sm * (1.f / 64.f);
        float d0 = v0 - mean, d1 = v1 - mean;
        float vs = d0 * d0 + d1 * d1;
#pragma unroll
        for (int o = 16; o; o >>= 1) vs += __shfl_xor_sync(0xffffffffu, vs, o);
        float inv = rsqrtf(vs * (1.f / 64.f) + 1e-5f);
        float* orow = out + (size_t)(r0 + r) * 64;
        orow[lane]      = d0 * inv * ln2g[lane] + ln2b[lane];
        orow[lane + 32] = d1 * inv * ln2g[lane + 32] + ln2b[lane + 32];
    }
}

// ---------------- launch ---------------------------------------------------------
extern "C" void kernel_launch(void* const* d_in, const int* in_sizes, int n_in,
                              void* d_out, int out_size)
{
    (void)in_sizes; (void)n_in; (void)out_size;
    const float* x       = (const float*)d_in[0];
    const float* sq_w    = (const float*)d_in[1];
    const float* bn_g    = (const float*)d_in[2];
    const float* bn_b    = (const float*)d_in[3];
    const float* dw_w    = (const float*)d_in[4];
    const float* ex_w    = (const float*)d_in[5];
    const float* pos_emb = (const float*)d_in[6];
    const float* wq      = (const float*)d_in[7];
    const float* bq      = (const float*)d_in[8];
    const float* wk      = (const float*)d_in[9];
    const float* bk      = (const float*)d_in[10];
    const float* wv      = (const float*)d_in[11];
    const float* wl      = (const float*)d_in[12];
    const float* uni_w   = (const float*)d_in[13];
    const float* uni_b   = (const float*)d_in[14];
    const float* ln1_g   = (const float*)d_in[15];
    const float* ln1_b   = (const float*)d_in[16];
    const float* ln2_g   = (const float*)d_in[17];
    const float* ln2_b   = (const float*)d_in[18];
    const float* ff_w1   = (const float*)d_in[19];
    const float* ff_b1   = (const float*)d_in[20];
    const float* ff_w2   = (const float*)d_in[21];
    const float* ff_b2   = (const float*)d_in[22];
    float* out = (float*)d_out;

    const int CONV_SMEM  = (2 * 128 * 36 + 2 * 32 * 68) * 4;   // 54272
    const int FLASH_SMEM = 24576 * 4;                          // 98304 (2 blocks/SM: 192KB)
    cudaFuncSetAttribute(convgemm_kernel, cudaFuncAttributeMaxDynamicSharedMemorySize, CONV_SMEM);
    cudaFuncSetAttribute(flash_mma_kernel, cudaFuncAttributeMaxDynamicSharedMemorySize, FLASH_SMEM);

    fused_xin_kernel<<<dim3(4, 32), 256>>>(x, sq_w, bn_g, bn_b, dw_w, ex_w, pos_emb);
    prep_w_kernel<<<1792, 256>>>(wq, wk, wv, wl, uni_w);

    convgemm_kernel<<<dim3(32, 16, 2), 256, CONV_SMEM>>>(bq, bk);

    flash_mma_kernel<<<dim3(32, 8), 256, FLASH_SMEM>>>();
    local_attn_kernel<<<dim3(32, 16), 256>>>();

    unigemm_kernel<<<dim3(32, 4), 256>>>();

    ffln_kernel<<<256, 256>>>(uni_b, ln1_g, ln1_b, ln2_g, ln2_b,
                              ff_w1, ff_b1, ff_w2, ff_b2, out);
}